// round 7
// baseline (speedup 1.0000x reference)
#include <cuda_runtime.h>

// ---------------------------------------------------------------------------
// VQ-VAE forward, sm_100a.
//   Encoder conv2/conv3: mma.sync tf32 3-term; inputs split ONCE at staging
//     into interleaved float2{hi,lo} -> mainloop = LDS.64 + HMMA only.
//   Decoder dconv1/dconv2: mma.sync tf32 1-term, zero-cvt mainloop.
//   conv1 / dconv3 / VQ: scalar-FFMA register-tiled.
// Output layout: [x_recon | z_e | z_q | idx(as float)], fp32.
// ---------------------------------------------------------------------------

#define NBATCH 16

// -------- scratch ------------------------------------------------------------
__device__ float g_h1[NBATCH * 128 * 128 * 128];
__device__ float g_h2[NBATCH * 256 * 64 * 64];
__device__ float g_g1[NBATCH * 256 * 64 * 64];
__device__ float g_g2[NBATCH * 128 * 128 * 128];
__device__ float g_ze[NBATCH * 64 * 32 * 32];
__device__ float g_zq[NBATCH * 64 * 32 * 32];
__device__ float g_if[16384];
__device__ float g_wt1[128 * 3 * 16];
__device__ float2 g_w2s[16 * 128 * 256];   // conv2  [t][ic][oc] (hi,lo)
__device__ float2 g_w3s[16 * 256 * 64];    // conv3  [t][ic][oc] (hi,lo)
__device__ float g_d2h[16 * 256 * 128];    // dconv2 [t][ic][oc] tf32-hi
__device__ float g_d1h[16 * 64 * 256];     // dconv1 [t][ic][oc] tf32-hi

// -------- mma helpers --------------------------------------------------------
__device__ __forceinline__ void tf32split(float v, unsigned& hi, unsigned& lo) {
    unsigned h;
    asm("cvt.rna.tf32.f32 %0,%1;" : "=r"(h) : "f"(v));
    float l = v - __uint_as_float(h);
    unsigned lw;
    asm("cvt.rna.tf32.f32 %0,%1;" : "=r"(lw) : "f"(l));
    hi = h; lo = lw;
}
__device__ __forceinline__ float tf32r(float v) {
    unsigned h;
    asm("cvt.rna.tf32.f32 %0,%1;" : "=r"(h) : "f"(v));
    return __uint_as_float(h);
}
__device__ __forceinline__ float2 splitpack(float v) {
    unsigned h, l;
    tf32split(v, h, l);
    return make_float2(__uint_as_float(h), __uint_as_float(l));
}
__device__ __forceinline__ void mma8(float* c, const unsigned* a,
                                     unsigned b0, unsigned b1) {
    asm("mma.sync.aligned.m16n8k8.row.col.f32.tf32.tf32.f32 "
        "{%0,%1,%2,%3},{%4,%5,%6,%7},{%8,%9},{%0,%1,%2,%3};"
        : "+f"(c[0]), "+f"(c[1]), "+f"(c[2]), "+f"(c[3])
        : "r"(a[0]), "r"(a[1]), "r"(a[2]), "r"(a[3]), "r"(b0), "r"(b1));
}
__device__ __forceinline__ void mma8f(float* c, const float* a,
                                      float b0, float b1) {
    mma8(c, (const unsigned*)a, __float_as_uint(b0), __float_as_uint(b1));
}

// -------- weight transforms --------------------------------------------------
__global__ void wtrans(const float* __restrict__ w, float* __restrict__ wo,
                       int Cout, int Cin) {   // OIHW -> [ic][oc][t]
    int idx = blockIdx.x * 256 + threadIdx.x;
    int total = Cout * Cin * 16;
    if (idx < total) {
        int t = idx & 15;
        int rest = idx >> 4;
        int ic = rest % Cin;
        int oc = rest / Cin;
        wo[(ic * Cout + oc) * 16 + t] = w[idx];
    }
}
__global__ void wsplit2t(const float* __restrict__ w, float2* __restrict__ wo) {
    int idx = blockIdx.x * 256 + threadIdx.x;   // 524288
    int t = idx & 15, ic = (idx >> 4) & 127, oc = idx >> 11;
    wo[(t * 128 + ic) * 256 + oc] = splitpack(w[idx]);
}
__global__ void wsplit3(const float* __restrict__ w, float2* __restrict__ wo) {
    int idx = blockIdx.x * 256 + threadIdx.x;   // 262144
    int t = idx & 15, ic = (idx >> 4) & 255, oc = idx >> 12;
    wo[(t * 256 + ic) * 64 + oc] = splitpack(w[idx]);
}
__global__ void whiD2(const float* __restrict__ w, float* __restrict__ wo) {
    int idx = blockIdx.x * 256 + threadIdx.x;   // 524288
    int t = idx & 15, oc = (idx >> 4) & 127, ic = idx >> 11;
    wo[(t * 256 + ic) * 128 + oc] = tf32r(w[idx]);
}
__global__ void whiD1(const float* __restrict__ w, float* __restrict__ wo) {
    int idx = blockIdx.x * 256 + threadIdx.x;   // 262144
    int t = idx & 15, oc = (idx >> 4) & 255, ic = idx >> 12;
    wo[(t * 64 + ic) * 256 + oc] = tf32r(w[idx]);
}

// ============================================================================
// conv2 MMA (3-term): h1 -> h2, k4 s2 p1, relu.
// Input staged as interleaved float2{hi,lo}; mainloop = LDS.64 + HMMA.
// ============================================================================
#define C2_WS2 (4 * 8 * 132)     // float2 weights (4-tap chunk)
#define C2_INS (8 * 6 * 132)     // float2 input pairs
#define C2_SMEM ((2 * C2_WS2 + 2 * C2_INS) * 4)
__global__ __launch_bounds__(256, 2)
void conv2_mma(const float* __restrict__ in, const float2* __restrict__ wt,
               const float* __restrict__ bias, float* __restrict__ out) {
    extern __shared__ float sm[];
    float2* ws  = (float2*)sm;
    float2* inp = (float2*)(sm + 2 * C2_WS2);

    const int oy0 = blockIdx.x * 2;
    const int ocb = blockIdx.y * 128;
    const int b   = blockIdx.z;

    const int tid  = threadIdx.x;
    const int wid  = tid >> 5;
    const int lane = tid & 31;
    const int wm   = wid >> 2;
    const int wn   = wid & 3;
    const int oyl  = wn >> 1;
    const int xb   = (wn & 1) * 32;
    const int lq   = lane >> 2;
    const int lr   = lane & 3;

    float acc[4][4][4];
#pragma unroll
    for (int mt = 0; mt < 4; mt++)
#pragma unroll
        for (int nt = 0; nt < 4; nt++)
#pragma unroll
            for (int i = 0; i < 4; i++) acc[mt][nt][i] = 0.f;

    const int iy0 = oy0 * 2 - 1;
    const float* inB = in + ((size_t)b * 128) * 128 * 128;

    for (int ch = 0; ch < 16; ch++) {
        for (int idx = tid; idx < 8 * 6 * 132; idx += 256) {
            int icl = idx / 792;
            int rem = idx - icl * 792;
            int r = rem / 132, c = rem - r * 132;
            int iy = iy0 + r, ix = c - 1;
            float v = 0.f;
            if ((unsigned)iy < 128u && (unsigned)ix < 128u)
                v = inB[((size_t)(ch * 8 + icl) * 128 + iy) * 128 + ix];
            inp[idx] = splitpack(v);
        }
        for (int tg = 0; tg < 4; tg++) {
            for (int idx = tid; idx < 4096; idx += 256) {
                int oc = idx & 127;
                int icl = (idx >> 7) & 7;
                int tl = idx >> 10;
                ws[(tl * 8 + icl) * 132 + oc] =
                    wt[((size_t)((tg * 4 + tl) * 128 + ch * 8 + icl)) * 256 + ocb + oc];
            }
            __syncthreads();

#pragma unroll
            for (int tapl = 0; tapl < 4; tapl++) {
                const int ky = tg, kx = tapl;
                unsigned ahi[4][4], alo[4][4];
#pragma unroll
                for (int mt = 0; mt < 4; mt++) {
                    const float2* ap = &ws[(tapl * 8 + lr) * 132 + wm * 64 + mt * 16 + lq];
                    float2 p0 = ap[0], p1 = ap[8], p2 = ap[4 * 132], p3 = ap[4 * 132 + 8];
                    ahi[mt][0] = __float_as_uint(p0.x); alo[mt][0] = __float_as_uint(p0.y);
                    ahi[mt][1] = __float_as_uint(p1.x); alo[mt][1] = __float_as_uint(p1.y);
                    ahi[mt][2] = __float_as_uint(p2.x); alo[mt][2] = __float_as_uint(p2.y);
                    ahi[mt][3] = __float_as_uint(p3.x); alo[mt][3] = __float_as_uint(p3.y);
                }
#pragma unroll
                for (int nt = 0; nt < 4; nt++) {
                    const int ox = xb + nt * 8 + lq;
                    const int off = lr * 792 + (2 * oyl + ky) * 132 + 2 * ox + kx;
                    float2 v0 = inp[off];
                    float2 v1 = inp[off + 4 * 792];
                    unsigned bh0 = __float_as_uint(v0.x), bl0 = __float_as_uint(v0.y);
                    unsigned bh1 = __float_as_uint(v1.x), bl1 = __float_as_uint(v1.y);
#pragma unroll
                    for (int mt = 0; mt < 4; mt++) {
                        mma8(acc[mt][nt], ahi[mt], bh0, bh1);
                        mma8(acc[mt][nt], ahi[mt], bl0, bl1);
                        mma8(acc[mt][nt], alo[mt], bh0, bh1);
                    }
                }
            }
            __syncthreads();
        }
    }

    const int oy = oy0 + oyl;
#pragma unroll
    for (int mt = 0; mt < 4; mt++) {
        const int oc = ocb + wm * 64 + mt * 16 + lq;
        const float b0v = bias[oc], b1v = bias[oc + 8];
#pragma unroll
        for (int nt = 0; nt < 4; nt++) {
            const int ox = xb + nt * 8 + 2 * lr;
            float* o0 = out + (((size_t)b * 256 + oc) * 64 + oy) * 64 + ox;
            float* o1 = o0 + (size_t)8 * 64 * 64;
            *(float2*)o0 = make_float2(fmaxf(acc[mt][nt][0] + b0v, 0.f),
                                       fmaxf(acc[mt][nt][1] + b0v, 0.f));
            *(float2*)o1 = make_float2(fmaxf(acc[mt][nt][2] + b1v, 0.f),
                                       fmaxf(acc[mt][nt][3] + b1v, 0.f));
        }
    }
}

// ============================================================================
// conv3 MMA (3-term): h2 -> 4 K-slab partials.  Interleaved float2 staging.
// ============================================================================
#define C3_WS2 (4 * 8 * 68)
#define C3_INS (8 * 18 * 68)
#define C3_SMEM ((2 * C3_WS2 + 2 * C3_INS) * 4)
__global__ __launch_bounds__(256, 2)
void conv3_mma(const float* __restrict__ in, const float2* __restrict__ wt,
               float* __restrict__ outp) {
    extern __shared__ float sm[];
    float2* ws  = (float2*)sm;
    float2* inp = (float2*)(sm + 2 * C3_WS2);

    const int r0   = blockIdx.x * 8;
    const int b    = blockIdx.z >> 2;
    const int slab = blockIdx.z & 3;

    const int tid  = threadIdx.x;
    const int w    = tid >> 5;
    const int lane = tid & 31;
    const int lq   = lane >> 2;
    const int lr   = lane & 3;

    float acc[4][4][4];
#pragma unroll
    for (int mt = 0; mt < 4; mt++)
#pragma unroll
        for (int nt = 0; nt < 4; nt++)
#pragma unroll
            for (int i = 0; i < 4; i++) acc[mt][nt][i] = 0.f;

    const int iy0 = r0 * 2 - 1;
    const float* inB = in + ((size_t)b * 256 + slab * 64) * 64 * 64;

    for (int ch = 0; ch < 8; ch++) {
        for (int idx = tid; idx < 8 * 18 * 66; idx += 256) {
            int icl = idx / 1188;
            int rem = idx - icl * 1188;
            int r = rem / 66, c = rem - r * 66;
            int iy = iy0 + r, ix = c - 1;
            float v = 0.f;
            if ((unsigned)iy < 64u && (unsigned)ix < 64u)
                v = inB[((size_t)(ch * 8 + icl) * 64 + iy) * 64 + ix];
            inp[icl * 1224 + r * 68 + c] = splitpack(v);
        }
        for (int tg = 0; tg < 4; tg++) {
            for (int idx = tid; idx < 2048; idx += 256) {
                int oc = idx & 63;
                int icl = (idx >> 6) & 7;
                int tl = idx >> 9;
                ws[(tl * 8 + icl) * 68 + oc] =
                    wt[((size_t)((tg * 4 + tl) * 256 + slab * 64 + ch * 8 + icl)) * 64 + oc];
            }
            __syncthreads();

#pragma unroll
            for (int tapl = 0; tapl < 4; tapl++) {
                const int ky = tg, kx = tapl;
                unsigned ahi[4][4], alo[4][4];
#pragma unroll
                for (int mt = 0; mt < 4; mt++) {
                    const float2* ap = &ws[(tapl * 8 + lr) * 68 + mt * 16 + lq];
                    float2 p0 = ap[0], p1 = ap[8], p2 = ap[4 * 68], p3 = ap[4 * 68 + 8];
                    ahi[mt][0] = __float_as_uint(p0.x); alo[mt][0] = __float_as_uint(p0.y);
                    ahi[mt][1] = __float_as_uint(p1.x); alo[mt][1] = __float_as_uint(p1.y);
                    ahi[mt][2] = __float_as_uint(p2.x); alo[mt][2] = __float_as_uint(p2.y);
                    ahi[mt][3] = __float_as_uint(p3.x); alo[mt][3] = __float_as_uint(p3.y);
                }
#pragma unroll
                for (int nt = 0; nt < 4; nt++) {
                    const int col = nt * 8 + lq;
                    const int off = lr * 1224 + (2 * w + ky) * 68 + 2 * col + kx;
                    float2 v0 = inp[off];
                    float2 v1 = inp[off + 4 * 1224];
                    unsigned bh0 = __float_as_uint(v0.x), bl0 = __float_as_uint(v0.y);
                    unsigned bh1 = __float_as_uint(v1.x), bl1 = __float_as_uint(v1.y);
#pragma unroll
                    for (int mt = 0; mt < 4; mt++) {
                        mma8(acc[mt][nt], ahi[mt], bh0, bh1);
                        mma8(acc[mt][nt], ahi[mt], bl0, bl1);
                        mma8(acc[mt][nt], alo[mt], bh0, bh1);
                    }
                }
            }
            __syncthreads();
        }
    }

    const int NZ = NBATCH * 64 * 32 * 32;
    float* part = outp + (size_t)slab * NZ;
    const int row = r0 + w;
#pragma unroll
    for (int mt = 0; mt < 4; mt++) {
        const int oc = mt * 16 + lq;
#pragma unroll
        for (int nt = 0; nt < 4; nt++) {
            float* o0 = part + (((size_t)b * 64 + oc) * 32 + row) * 32 + nt * 8 + 2 * lr;
            float* o1 = o0 + (size_t)8 * 32 * 32;
            *(float2*)o0 = make_float2(acc[mt][nt][0], acc[mt][nt][1]);
            *(float2*)o1 = make_float2(acc[mt][nt][2], acc[mt][nt][3]);
        }
    }
}

__global__ void addparts(const float* __restrict__ p, const float* __restrict__ bias,
                         float* __restrict__ ze) {
    const int S = NBATCH * 64 * 32 * 32;
    int i = blockIdx.x * 256 + threadIdx.x;
    float v = p[i] + p[i + S] + p[i + 2 * S] + p[i + 3 * S];
    ze[i] = v + bias[(i >> 10) & 63];
}

// ============================================================================
// dconv MMA, 1-term tf32: zero-cvt mainloop (weights pre-rounded in gmem,
// inputs rounded at staging).
// ============================================================================
template <int CIN, int HIN>
__global__ __launch_bounds__(256, 2)
void dconv_mma(const float* __restrict__ in, const float* __restrict__ wt,
               const float* __restrict__ bias, float* __restrict__ out,
               int Cout, int nOcb) {
    const int WROW = HIN + 2;
    __shared__ float ws[4 * 8 * 132];
    __shared__ float ins[8 * 3 * (HIN + 4)];

    const int y0 = blockIdx.x * 2;
    const int py = blockIdx.y >> 1, px = blockIdx.y & 1;
    const int b   = blockIdx.z / nOcb;
    const int ocb = (blockIdx.z % nOcb) * 128;

    const int tid  = threadIdx.x;
    const int wid  = tid >> 5;
    const int lane = tid & 31;
    const int wm   = wid >> 2;
    const int wn   = wid & 3;
    const int yl   = wn >> 1;
    const int xb   = (wn & 1) * (HIN / 2);
    const int lq   = lane >> 2;
    const int lr   = lane & 3;
    const int NT   = HIN / 16;
    const int ISTR = HIN + 4;

    float acc[4][4][4];
#pragma unroll
    for (int mt = 0; mt < 4; mt++)
#pragma unroll
        for (int nt = 0; nt < 4; nt++)
#pragma unroll
            for (int i = 0; i < 4; i++) acc[mt][nt][i] = 0.f;

    const float* inB = in + ((size_t)b * CIN) * HIN * HIN;

    for (int ch = 0; ch < CIN / 8; ch++) {
        for (int idx = tid; idx < 8 * 3 * WROW; idx += 256) {
            int icl = idx / (3 * WROW);
            int rem = idx - icl * 3 * WROW;
            int r = rem / WROW, s = rem - r * WROW;
            int iy = y0 + py - 1 + r;
            int ix = px - 1 + s;
            float v = 0.f;
            if ((unsigned)iy < (unsigned)HIN && (unsigned)ix < (unsigned)HIN)
                v = inB[((size_t)(ch * 8 + icl) * HIN + iy) * HIN + ix];
            ins[(icl * 3 + r) * ISTR + s] = tf32r(v);
        }
        for (int idx = tid; idx < 4096; idx += 256) {
            int oc = idx & 127;
            int icl = (idx >> 7) & 7;
            int tl = idx >> 10;
            int a = tl >> 1, c = tl & 1;
            int t = (1 - py + 2 * a) * 4 + (1 - px + 2 * c);
            ws[(tl * 8 + icl) * 132 + oc] =
                wt[((size_t)(t * CIN + ch * 8 + icl)) * Cout + ocb + oc];
        }
        __syncthreads();

#pragma unroll
        for (int tl = 0; tl < 4; tl++) {
            const int a = tl >> 1, c = tl & 1;
            float af[4][4];
#pragma unroll
            for (int mt = 0; mt < 4; mt++) {
                const float* ap = &ws[(tl * 8 + lr) * 132 + wm * 64 + mt * 16 + lq];
                af[mt][0] = ap[0];
                af[mt][1] = ap[8];
                af[mt][2] = ap[4 * 132];
                af[mt][3] = ap[4 * 132 + 8];
            }
#pragma unroll
            for (int nt = 0; nt < NT; nt++) {
                const int x = xb + nt * 8 + lq;
                const float* bp = &ins[(lr * 3 + (yl + 1 - a)) * ISTR + x + 1 - c];
                float b0 = bp[0], b1 = bp[4 * 3 * ISTR];
#pragma unroll
                for (int mt = 0; mt < 4; mt++)
                    mma8f(acc[mt][nt], af[mt], b0, b1);
            }
        }
        __syncthreads();
    }

    const int HOUT = 2 * HIN;
    const int oy = 2 * (y0 + yl) + py;
#pragma unroll
    for (int mt = 0; mt < 4; mt++) {
        const int oc = ocb + wm * 64 + mt * 16 + lq;
        const float b0v = bias[oc], b1v = bias[oc + 8];
#pragma unroll
        for (int nt = 0; nt < NT; nt++) {
            const int x = xb + nt * 8 + 2 * lr;
            const int ox = 2 * x + px;
            float* o0 = out + (((size_t)b * Cout + oc) * HOUT + oy) * HOUT + ox;
            float* o1 = o0 + (size_t)8 * HOUT * HOUT;
            o0[0] = fmaxf(acc[mt][nt][0] + b0v, 0.f);
            o0[2] = fmaxf(acc[mt][nt][1] + b0v, 0.f);
            o1[0] = fmaxf(acc[mt][nt][2] + b1v, 0.f);
            o1[2] = fmaxf(acc[mt][nt][3] + b1v, 0.f);
        }
    }
}

// ============================================================================
// Scalar kernels: conv1, dconv3out, vqk.
// ============================================================================
template <int CIN, bool RELU>
__global__ __launch_bounds__(256, 2)
void conv4s2(const float* __restrict__ in, const float* __restrict__ wt,
             const float* __restrict__ bias, float* __restrict__ out,
             int Cout, int Hin, int Win, int Hout, int Wout, int tilesX) {
    __shared__ float ish[34 * 36];
    __shared__ float wsh[64 * 16];

    const int tile = blockIdx.x;
    const int tx0 = (tile % tilesX) * 16;
    const int ty0 = (tile / tilesX) * 16;
    const int ocb = blockIdx.y * 64;
    const int b   = blockIdx.z;

    const int tid = threadIdx.x;
    const int og  = tid >> 5;
    const int sp  = tid & 31;
    const int r   = sp >> 1;
    const int cb  = (sp & 1) * 8;

    float acc[8][8];
#pragma unroll
    for (int o = 0; o < 8; o++) {
        float bv = bias[ocb + og * 8 + o];
#pragma unroll
        for (int j = 0; j < 8; j++) acc[o][j] = bv;
    }

    const int iy0 = ty0 * 2 - 1, ix0 = tx0 * 2 - 1;
    const float* inB = in + ((size_t)b * CIN) * Hin * Win;

    for (int ic = 0; ic < CIN; ic++) {
        const float* inC = inB + (size_t)ic * Hin * Win;
        for (int idx = tid; idx < 34 * 34; idx += 256) {
            int py = idx / 34, px = idx - py * 34;
            int iy = iy0 + py, ix = ix0 + px;
            float v = 0.f;
            if ((unsigned)iy < (unsigned)Hin && (unsigned)ix < (unsigned)Win)
                v = inC[iy * Win + ix];
            ish[py * 36 + px] = v;
        }
        const float* wC = wt + (ic * Cout + ocb) * 16;
        for (int idx = tid; idx < 1024; idx += 256) wsh[idx] = wC[idx];
        __syncthreads();

#pragma unroll
        for (int ky = 0; ky < 4; ky++) {
            const float* rp = &ish[(2 * r + ky) * 36 + 2 * cb];
            float4 v0 = *(const float4*)(rp);
            float4 v1 = *(const float4*)(rp + 4);
            float4 v2 = *(const float4*)(rp + 8);
            float4 v3 = *(const float4*)(rp + 12);
            float4 v4 = *(const float4*)(rp + 16);
            float riv[20] = {v0.x, v0.y, v0.z, v0.w, v1.x, v1.y, v1.z, v1.w,
                             v2.x, v2.y, v2.z, v2.w, v3.x, v3.y, v3.z, v3.w,
                             v4.x, v4.y, v4.z, v4.w};
#pragma unroll
            for (int kx = 0; kx < 4; kx++) {
                const int t = ky * 4 + kx;
                float wv[8];
#pragma unroll
                for (int o = 0; o < 8; o++) wv[o] = wsh[(og * 8 + o) * 16 + t];
#pragma unroll
                for (int o = 0; o < 8; o++)
#pragma unroll
                    for (int j = 0; j < 8; j++)
                        acc[o][j] = fmaf(wv[o], riv[kx + 2 * j], acc[o][j]);
            }
        }
        __syncthreads();
    }

    const int oy = ty0 + r;
    const int oxb = tx0 + cb;
#pragma unroll
    for (int o = 0; o < 8; o++) {
        float* op = out + (((size_t)b * Cout + ocb + og * 8 + o) * Hout + oy) * Wout + oxb;
        float tmp[8];
#pragma unroll
        for (int j = 0; j < 8; j++)
            tmp[j] = RELU ? fmaxf(acc[o][j], 0.f) : acc[o][j];
        *(float4*)op       = make_float4(tmp[0], tmp[1], tmp[2], tmp[3]);
        *(float4*)(op + 4) = make_float4(tmp[4], tmp[5], tmp[6], tmp[7]);
    }
}

__global__ __launch_bounds__(128, 4)
void dconv3out(const float* __restrict__ in, const float* __restrict__ wt,
               const float* __restrict__ bias, float* __restrict__ out,
               int tilesX) {
    const int Cin = 128, Hin = 128, Win = 128, Hout = 256, Wout = 256;
    __shared__ float ish[4][18 * 19];
    __shared__ float wsh[4][3 * 16];

    const int tile = blockIdx.x;
    const int ox0 = (tile % tilesX) * 32;
    const int oy0 = (tile / tilesX) * 32;
    const int b   = blockIdx.y;

    const int tid = threadIdx.x;
    const int q   = tid >> 5;
    const int py  = q >> 1, px = q & 1;
    const int sp  = tid & 31;
    const int ry  = sp >> 1;
    const int ch  = (sp & 1) * 8;

    float acc[3][8];
#pragma unroll
    for (int o = 0; o < 3; o++) {
        float bv = bias[o];
#pragma unroll
        for (int j = 0; j < 8; j++) acc[o][j] = bv;
    }

    const int iy0 = oy0 >> 1, ix0 = ox0 >> 1;
    const int kp = 1 - py, kq = 1 - px;

    for (int ic0 = 0; ic0 < Cin; ic0 += 4) {
        for (int idx = tid; idx < 4 * 324; idx += 128) {
            int icc = idx / 324, p = idx - icc * 324;
            int piy = p / 18, pix = p - piy * 18;
            int iy = iy0 - 1 + piy, ix = ix0 - 1 + pix;
            float v = 0.f;
            if ((unsigned)iy < (unsigned)Hin && (unsigned)ix < (unsigned)Win)
                v = in[(((size_t)b * Cin + ic0 + icc) * Hin + iy) * Win + ix];
            ish[icc][piy * 19 + pix] = v;
        }
        for (int idx = tid; idx < 4 * 48; idx += 128) {
            int icc = idx / 48, rmd = idx - icc * 48;
            wsh[icc][rmd] = wt[(ic0 + icc) * 48 + rmd];
        }
        __syncthreads();

#pragma unroll
        for (int icc = 0; icc < 4; icc++) {
#pragma unroll
            for (int a = 0; a < 2; a++) {
                const int ky  = kp + 2 * a;
                const int liy = ry + 1 + py - a;
                float iv[10];
                const int base = liy * 19 + ch + px;
#pragma unroll
                for (int j = 0; j < 10; j++) iv[j] = ish[icc][base + j];
#pragma unroll
                for (int c = 0; c < 2; c++) {
                    const int kx  = kq + 2 * c;
                    const int t   = ky * 4 + kx;
                    const int off = 1 - c;
                    float wv[3];
#pragma unroll
                    for (int o = 0; o < 3; o++) wv[o] = wsh[icc][o * 16 + t];
#pragma unroll
                    for (int o = 0; o < 3; o++)
#pragma unroll
                        for (int j = 0; j < 8; j++)
                            acc[o][j] = fmaf(wv[o], iv[j + off], acc[o][j]);
                }
            }
        }
        __syncthreads();
    }

    const int oy = oy0 + 2 * ry + py;
#pragma unroll
    for (int o = 0; o < 3; o++) {
        float* op = out + (((size_t)b * 3 + o) * Hout + oy) * Wout + ox0 + px + 2 * ch;
#pragma unroll
        for (int j = 0; j < 8; j++) op[2 * j] = acc[o][j];
    }
}

__global__ __launch_bounds__(128, 8)
void vqk(const float* __restrict__ ze, const float* __restrict__ emb,
         float* __restrict__ zq, float* __restrict__ idxf) {
    __shared__ __align__(16) float esh[64 * 64];
    __shared__ float en[64];

    const int row = blockIdx.x * 128 + threadIdx.x;
    float f[64];
    const float4* fp = (const float4*)(ze + (size_t)row * 64);
#pragma unroll
    for (int i = 0; i < 16; i++) {
        float4 v = fp[i];
        f[4 * i] = v.x; f[4 * i + 1] = v.y; f[4 * i + 2] = v.z; f[4 * i + 3] = v.w;
    }
    float fn = 0.f;
#pragma unroll
    for (int d = 0; d < 64; d++) fn = fmaf(f[d], f[d], fn);

    float best = 3.4e38f;
    int bidx = 0;
    for (int cb = 0; cb < 512; cb += 64) {
        __syncthreads();
        const float4* src = (const float4*)(emb + (size_t)cb * 64);
        for (int i = threadIdx.x; i < 1024; i += 128)
            ((float4*)esh)[i] = src[i];
        __syncthreads();
        if (threadIdx.x < 64) {
            float s = 0.f;
            const float* e = esh + threadIdx.x * 64;
#pragma unroll
            for (int d = 0; d < 64; d++) s = fmaf(e[d], e[d], s);
            en[threadIdx.x] = s;
        }
        __syncthreads();
        for (int c = 0; c < 64; c++) {
            const float4* ev = (const float4*)(esh + c * 64);
            float dot = 0.f;
#pragma unroll
            for (int i = 0; i < 16; i++) {
                float4 e = ev[i];
                dot = fmaf(f[4 * i], e.x, dot);
                dot = fmaf(f[4 * i + 1], e.y, dot);
                dot = fmaf(f[4 * i + 2], e.z, dot);
                dot = fmaf(f[4 * i + 3], e.w, dot);
            }
            float sc = fn - 2.f * dot + en[c];
            if (sc < best) { best = sc; bidx = cb + c; }
        }
    }

    idxf[row] = (float)bidx;
    const float4* ep = (const float4*)(emb + (size_t)bidx * 64);
    float4* qp = (float4*)(zq + (size_t)row * 64);
#pragma unroll
    for (int i = 0; i < 16; i++) qp[i] = ep[i];
}

// ---------------------------------------------------------------------------
extern "C" void kernel_launch(void* const* d_in, const int* in_sizes, int n_in,
                              void* d_out, int out_size) {
    (void)in_sizes; (void)n_in;
    const float* x   = (const float*)d_in[0];
    const float* w1  = (const float*)d_in[1];
    const float* b1  = (const float*)d_in[2];
    const float* w2  = (const float*)d_in[3];
    const float* b2  = (const float*)d_in[4];
    const float* w3  = (const float*)d_in[5];
    const float* b3  = (const float*)d_in[6];
    const float* d1w = (const float*)d_in[7];
    const float* d1b = (const float*)d_in[8];
    const float* d2w = (const float*)d_in[9];
    const float* d2b = (const float*)d_in[10];
    const float* d3w = (const float*)d_in[11];
    const float* d3b = (const float*)d_in[12];
    const float* emb = (const float*)d_in[13];

    float *h1, *h2, *g1, *g2, *ze, *zq, *idxf, *wt1, *d2h, *d1h;
    float2 *w2s, *w3s;
    cudaGetSymbolAddress((void**)&h1, g_h1);
    cudaGetSymbolAddress((void**)&h2, g_h2);
    cudaGetSymbolAddress((void**)&g1, g_g1);
    cudaGetSymbolAddress((void**)&g2, g_g2);
    cudaGetSymbolAddress((void**)&ze, g_ze);
    cudaGetSymbolAddress((void**)&zq, g_zq);
    cudaGetSymbolAddress((void**)&idxf, g_if);
    cudaGetSymbolAddress((void**)&wt1, g_wt1);
    cudaGetSymbolAddress((void**)&w2s, g_w2s);
    cudaGetSymbolAddress((void**)&w3s, g_w3s);
    cudaGetSymbolAddress((void**)&d2h, g_d2h);
    cudaGetSymbolAddress((void**)&d1h, g_d1h);

    float* outF = (float*)d_out;
    const int NX = NBATCH * 3 * 256 * 256;
    const int NZ = NBATCH * 64 * 32 * 32;
    const int NI = 16384;
    if (out_size >= NX + 2 * NZ + NI) {
        ze   = outF + NX;
        zq   = outF + NX + NZ;
        idxf = outF + NX + 2 * NZ;
    }

    static bool attr_done = false;
    if (!attr_done) {
        cudaFuncSetAttribute(conv2_mma, cudaFuncAttributeMaxDynamicSharedMemorySize,
                             C2_SMEM);
        cudaFuncSetAttribute(conv3_mma, cudaFuncAttributeMaxDynamicSharedMemorySize,
                             C3_SMEM);
        attr_done = true;
    }

    wsplit2t<<<2048, 256>>>(w2, w2s);
    wtrans<<<(128 * 3 * 16 + 255) / 256, 256>>>(w1, wt1, 128, 3);
    conv4s2<3, true><<<dim3(64, 2, NBATCH), 256>>>(x, wt1, b1, h1, 128, 256, 256, 128, 128, 8);
    conv2_mma<<<dim3(32, 2, NBATCH), 256, C2_SMEM>>>(h1, w2s, b2, h2);
    wsplit3<<<1024, 256>>>(w3, w3s);
    conv3_mma<<<dim3(4, 1, NBATCH * 4), 256, C3_SMEM>>>(h2, w3s, g2);
    addparts<<<NZ / 256, 256>>>(g2, b3, ze);
    vqk<<<128, 128>>>(ze, emb, zq, idxf);
    whiD1<<<1024, 256>>>(d1w, d1h);
    dconv_mma<64, 32><<<dim3(16, 4, NBATCH * 2), 256>>>(zq, d1h, d1b, g1, 256, 2);
    whiD2<<<2048, 256>>>(d2w, d2h);
    dconv_mma<256, 64><<<dim3(32, 4, NBATCH), 256>>>(g1, d2h, d2b, g2, 128, 1);
    dconv3out<<<dim3(64, NBATCH), 128>>>(g2, d3w, d3b, outF, 8);
}

// round 8
// speedup vs baseline: 1.0244x; 1.0244x over previous
#include <cuda_runtime.h>

// ---------------------------------------------------------------------------
// VQ-VAE forward, sm_100a.  (R5 baseline + mask-based B split in encoder.)
//   Encoder conv2/conv3: mma.sync tf32 3-term; B split via bit-mask
//     (LOP3+FADD) exploiting HMMA's ignore-low-13-bits tf32 semantics.
//   Decoder dconv1/dconv2: mma.sync tf32 1-term.
//   conv1 / dconv3 / VQ: scalar-FFMA register-tiled.
// Output layout: [x_recon | z_e | z_q | idx(as float)], fp32.
// ---------------------------------------------------------------------------

#define NBATCH 16

// -------- scratch ------------------------------------------------------------
__device__ float g_h1[NBATCH * 128 * 128 * 128];
__device__ float g_h2[NBATCH * 256 * 64 * 64];
__device__ float g_g1[NBATCH * 256 * 64 * 64];
__device__ float g_g2[NBATCH * 128 * 128 * 128];
__device__ float g_ze[NBATCH * 64 * 32 * 32];
__device__ float g_zq[NBATCH * 64 * 32 * 32];
__device__ float g_if[16384];
__device__ float g_wt1[128 * 3 * 16];
__device__ float2 g_w2s[16 * 128 * 256];   // conv2  [t][ic][oc] (hi,lo)
__device__ float2 g_w3s[16 * 256 * 64];    // conv3  [t][ic][oc] (hi,lo)
__device__ float2 g_d2s[16 * 256 * 128];   // dconv2 [t][ic][oc] (hi,lo)
__device__ float2 g_d1s[16 * 64 * 256];    // dconv1 [t][ic][oc] (hi,lo)

// -------- mma helpers --------------------------------------------------------
__device__ __forceinline__ void tf32split(float v, unsigned& hi, unsigned& lo) {
    unsigned h;
    asm("cvt.rna.tf32.f32 %0,%1;" : "=r"(h) : "f"(v));
    float l = v - __uint_as_float(h);
    unsigned lw;
    asm("cvt.rna.tf32.f32 %0,%1;" : "=r"(lw) : "f"(l));
    hi = h; lo = lw;
}
__device__ __forceinline__ unsigned tf32cvt(float v) {
    unsigned h;
    asm("cvt.rna.tf32.f32 %0,%1;" : "=r"(h) : "f"(v));
    return h;
}
__device__ __forceinline__ float2 splitpack(float v) {
    unsigned h, l;
    tf32split(v, h, l);
    return make_float2(__uint_as_float(h), __uint_as_float(l));
}
// mask-split: hi = v with low 13 bits zeroed (valid tf32 container, RZ);
// lo = exact residual passed raw (HMMA truncates its low bits).
__device__ __forceinline__ void masksplit(float v, unsigned& hi, unsigned& lo) {
    unsigned h = __float_as_uint(v) & 0xFFFFE000u;
    hi = h;
    lo = __float_as_uint(v - __uint_as_float(h));
}
__device__ __forceinline__ void mma8(float* c, const unsigned* a,
                                     unsigned b0, unsigned b1) {
    asm("mma.sync.aligned.m16n8k8.row.col.f32.tf32.tf32.f32 "
        "{%0,%1,%2,%3},{%4,%5,%6,%7},{%8,%9},{%0,%1,%2,%3};"
        : "+f"(c[0]), "+f"(c[1]), "+f"(c[2]), "+f"(c[3])
        : "r"(a[0]), "r"(a[1]), "r"(a[2]), "r"(a[3]), "r"(b0), "r"(b1));
}

// -------- weight transforms --------------------------------------------------
__global__ void wtrans(const float* __restrict__ w, float* __restrict__ wo,
                       int Cout, int Cin) {   // OIHW -> [ic][oc][t]
    int idx = blockIdx.x * 256 + threadIdx.x;
    int total = Cout * Cin * 16;
    if (idx < total) {
        int t = idx & 15;
        int rest = idx >> 4;
        int ic = rest % Cin;
        int oc = rest / Cin;
        wo[(ic * Cout + oc) * 16 + t] = w[idx];
    }
}
__global__ void wsplit2t(const float* __restrict__ w, float2* __restrict__ wo) {
    int idx = blockIdx.x * 256 + threadIdx.x;   // 524288
    int t = idx & 15, ic = (idx >> 4) & 127, oc = idx >> 11;
    wo[(t * 128 + ic) * 256 + oc] = splitpack(w[idx]);
}
__global__ void wsplit3(const float* __restrict__ w, float2* __restrict__ wo) {
    int idx = blockIdx.x * 256 + threadIdx.x;   // 262144
    int t = idx & 15, ic = (idx >> 4) & 255, oc = idx >> 12;
    wo[(t * 256 + ic) * 64 + oc] = splitpack(w[idx]);
}
__global__ void wsplitD2(const float* __restrict__ w, float2* __restrict__ wo) {
    int idx = blockIdx.x * 256 + threadIdx.x;   // 524288
    int t = idx & 15, oc = (idx >> 4) & 127, ic = idx >> 11;
    wo[(t * 256 + ic) * 128 + oc] = splitpack(w[idx]);
}
__global__ void wsplitD1(const float* __restrict__ w, float2* __restrict__ wo) {
    int idx = blockIdx.x * 256 + threadIdx.x;   // 262144
    int t = idx & 15, oc = (idx >> 4) & 255, ic = idx >> 12;
    wo[(t * 64 + ic) * 256 + oc] = splitpack(w[idx]);
}

// ============================================================================
// conv2 MMA (3-term): h1 -> h2, k4 s2 p1, relu.
// ============================================================================
#define C2_WS2 (4 * 8 * 132)
#define C2_INS (8 * 6 * 132)
#define C2_SMEM ((2 * C2_WS2 + C2_INS) * 4)
__global__ __launch_bounds__(256, 2)
void conv2_mma(const float* __restrict__ in, const float2* __restrict__ wt,
               const float* __restrict__ bias, float* __restrict__ out) {
    extern __shared__ float sm[];
    float2* ws = (float2*)sm;
    float* ins = sm + 2 * C2_WS2;

    const int oy0 = blockIdx.x * 2;
    const int ocb = blockIdx.y * 128;
    const int b   = blockIdx.z;

    const int tid  = threadIdx.x;
    const int wid  = tid >> 5;
    const int lane = tid & 31;
    const int wm   = wid >> 2;
    const int wn   = wid & 3;
    const int oyl  = wn >> 1;
    const int xb   = (wn & 1) * 32;
    const int lq   = lane >> 2;
    const int lr   = lane & 3;

    float acc[4][4][4];
#pragma unroll
    for (int mt = 0; mt < 4; mt++)
#pragma unroll
        for (int nt = 0; nt < 4; nt++)
#pragma unroll
            for (int i = 0; i < 4; i++) acc[mt][nt][i] = 0.f;

    const int iy0 = oy0 * 2 - 1;
    const float* inB = in + ((size_t)b * 128) * 128 * 128;

    for (int ch = 0; ch < 16; ch++) {
        for (int idx = tid; idx < 8 * 6 * 132; idx += 256) {
            int icl = idx / 792;
            int rem = idx - icl * 792;
            int r = rem / 132, c = rem - r * 132;
            int iy = iy0 + r, ix = c - 1;
            float v = 0.f;
            if ((unsigned)iy < 128u && (unsigned)ix < 128u)
                v = inB[((size_t)(ch * 8 + icl) * 128 + iy) * 128 + ix];
            ins[idx] = v;
        }
        for (int tg = 0; tg < 4; tg++) {
            for (int idx = tid; idx < 4096; idx += 256) {
                int oc = idx & 127;
                int icl = (idx >> 7) & 7;
                int tl = idx >> 10;
                ws[(tl * 8 + icl) * 132 + oc] =
                    wt[((size_t)((tg * 4 + tl) * 128 + ch * 8 + icl)) * 256 + ocb + oc];
            }
            __syncthreads();

#pragma unroll
            for (int tapl = 0; tapl < 4; tapl++) {
                const int ky = tg, kx = tapl;
                unsigned ahi[4][4], alo[4][4];
#pragma unroll
                for (int mt = 0; mt < 4; mt++) {
                    const float2* ap = &ws[(tapl * 8 + lr) * 132 + wm * 64 + mt * 16 + lq];
                    float2 p0 = ap[0], p1 = ap[8], p2 = ap[4 * 132], p3 = ap[4 * 132 + 8];
                    ahi[mt][0] = __float_as_uint(p0.x); alo[mt][0] = __float_as_uint(p0.y);
                    ahi[mt][1] = __float_as_uint(p1.x); alo[mt][1] = __float_as_uint(p1.y);
                    ahi[mt][2] = __float_as_uint(p2.x); alo[mt][2] = __float_as_uint(p2.y);
                    ahi[mt][3] = __float_as_uint(p3.x); alo[mt][3] = __float_as_uint(p3.y);
                }
#pragma unroll
                for (int nt = 0; nt < 4; nt++) {
                    const int ox = xb + nt * 8 + lq;
                    const float* bp = &ins[lr * 792 + (2 * oyl + ky) * 132 + 2 * ox + kx];
                    float rb0 = bp[0], rb1 = bp[4 * 792];
                    unsigned bh0, bl0, bh1, bl1;
                    masksplit(rb0, bh0, bl0);
                    masksplit(rb1, bh1, bl1);
#pragma unroll
                    for (int mt = 0; mt < 4; mt++) {
                        mma8(acc[mt][nt], ahi[mt], bh0, bh1);
                        mma8(acc[mt][nt], ahi[mt], bl0, bl1);
                        mma8(acc[mt][nt], alo[mt], bh0, bh1);
                    }
                }
            }
            __syncthreads();
        }
    }

    const int oy = oy0 + oyl;
#pragma unroll
    for (int mt = 0; mt < 4; mt++) {
        const int oc = ocb + wm * 64 + mt * 16 + lq;
        const float b0v = bias[oc], b1v = bias[oc + 8];
#pragma unroll
        for (int nt = 0; nt < 4; nt++) {
            const int ox = xb + nt * 8 + 2 * lr;
            float* o0 = out + (((size_t)b * 256 + oc) * 64 + oy) * 64 + ox;
            float* o1 = o0 + (size_t)8 * 64 * 64;
            *(float2*)o0 = make_float2(fmaxf(acc[mt][nt][0] + b0v, 0.f),
                                       fmaxf(acc[mt][nt][1] + b0v, 0.f));
            *(float2*)o1 = make_float2(fmaxf(acc[mt][nt][2] + b1v, 0.f),
                                       fmaxf(acc[mt][nt][3] + b1v, 0.f));
        }
    }
}

// ============================================================================
// conv3 MMA (3-term): h2 -> 4 K-slab partials.
// ============================================================================
#define C3_WS2 (4 * 8 * 68)
#define C3_INS (8 * 18 * 68)
#define C3_SMEM ((2 * C3_WS2 + C3_INS) * 4)
__global__ __launch_bounds__(256, 2)
void conv3_mma(const float* __restrict__ in, const float2* __restrict__ wt,
               float* __restrict__ outp) {
    extern __shared__ float sm[];
    float2* ws = (float2*)sm;
    float* ins = sm + 2 * C3_WS2;

    const int r0   = blockIdx.x * 8;
    const int b    = blockIdx.z >> 2;
    const int slab = blockIdx.z & 3;

    const int tid  = threadIdx.x;
    const int w    = tid >> 5;
    const int lane = tid & 31;
    const int lq   = lane >> 2;
    const int lr   = lane & 3;

    float acc[4][4][4];
#pragma unroll
    for (int mt = 0; mt < 4; mt++)
#pragma unroll
        for (int nt = 0; nt < 4; nt++)
#pragma unroll
            for (int i = 0; i < 4; i++) acc[mt][nt][i] = 0.f;

    const int iy0 = r0 * 2 - 1;
    const float* inB = in + ((size_t)b * 256 + slab * 64) * 64 * 64;

    for (int ch = 0; ch < 8; ch++) {
        for (int idx = tid; idx < 8 * 18 * 66; idx += 256) {
            int icl = idx / 1188;
            int rem = idx - icl * 1188;
            int r = rem / 66, c = rem - r * 66;
            int iy = iy0 + r, ix = c - 1;
            float v = 0.f;
            if ((unsigned)iy < 64u && (unsigned)ix < 64u)
                v = inB[((size_t)(ch * 8 + icl) * 64 + iy) * 64 + ix];
            ins[icl * 1224 + r * 68 + c] = v;
        }
        for (int tg = 0; tg < 4; tg++) {
            for (int idx = tid; idx < 2048; idx += 256) {
                int oc = idx & 63;
                int icl = (idx >> 6) & 7;
                int tl = idx >> 9;
                ws[(tl * 8 + icl) * 68 + oc] =
                    wt[((size_t)((tg * 4 + tl) * 256 + slab * 64 + ch * 8 + icl)) * 64 + oc];
            }
            __syncthreads();

#pragma unroll
            for (int tapl = 0; tapl < 4; tapl++) {
                const int ky = tg, kx = tapl;
                unsigned ahi[4][4], alo[4][4];
#pragma unroll
                for (int mt = 0; mt < 4; mt++) {
                    const float2* ap = &ws[(tapl * 8 + lr) * 68 + mt * 16 + lq];
                    float2 p0 = ap[0], p1 = ap[8], p2 = ap[4 * 68], p3 = ap[4 * 68 + 8];
                    ahi[mt][0] = __float_as_uint(p0.x); alo[mt][0] = __float_as_uint(p0.y);
                    ahi[mt][1] = __float_as_uint(p1.x); alo[mt][1] = __float_as_uint(p1.y);
                    ahi[mt][2] = __float_as_uint(p2.x); alo[mt][2] = __float_as_uint(p2.y);
                    ahi[mt][3] = __float_as_uint(p3.x); alo[mt][3] = __float_as_uint(p3.y);
                }
#pragma unroll
                for (int nt = 0; nt < 4; nt++) {
                    const int col = nt * 8 + lq;
                    const float* bp = &ins[lr * 1224 + (2 * w + ky) * 68 + 2 * col + kx];
                    float rb0 = bp[0], rb1 = bp[4 * 1224];
                    unsigned bh0, bl0, bh1, bl1;
                    masksplit(rb0, bh0, bl0);
                    masksplit(rb1, bh1, bl1);
#pragma unroll
                    for (int mt = 0; mt < 4; mt++) {
                        mma8(acc[mt][nt], ahi[mt], bh0, bh1);
                        mma8(acc[mt][nt], ahi[mt], bl0, bl1);
                        mma8(acc[mt][nt], alo[mt], bh0, bh1);
                    }
                }
            }
            __syncthreads();
        }
    }

    const int NZ = NBATCH * 64 * 32 * 32;
    float* part = outp + (size_t)slab * NZ;
    const int row = r0 + w;
#pragma unroll
    for (int mt = 0; mt < 4; mt++) {
        const int oc = mt * 16 + lq;
#pragma unroll
        for (int nt = 0; nt < 4; nt++) {
            float* o0 = part + (((size_t)b * 64 + oc) * 32 + row) * 32 + nt * 8 + 2 * lr;
            float* o1 = o0 + (size_t)8 * 32 * 32;
            *(float2*)o0 = make_float2(acc[mt][nt][0], acc[mt][nt][1]);
            *(float2*)o1 = make_float2(acc[mt][nt][2], acc[mt][nt][3]);
        }
    }
}

__global__ void addparts(const float* __restrict__ p, const float* __restrict__ bias,
                         float* __restrict__ ze) {
    const int S = NBATCH * 64 * 32 * 32;
    int i = blockIdx.x * 256 + threadIdx.x;
    float v = p[i] + p[i + S] + p[i + 2 * S] + p[i + 3 * S];
    ze[i] = v + bias[(i >> 10) & 63];
}

// ============================================================================
// dconv MMA (TERMS=1 path of R5): plain tf32, weights float2 pre-split (hi
// used), B rounded inline with cvt.rna.
// ============================================================================
template <int CIN, int HIN, int TERMS>
__global__ __launch_bounds__(256, 2)
void dconv_mma(const float* __restrict__ in, const float2* __restrict__ wt,
               const float* __restrict__ bias, float* __restrict__ out,
               int Cout, int nOcb) {
    const int WROW = HIN + 2;
    __shared__ float2 ws[4 * 8 * 132];
    __shared__ float ins[8 * 3 * (HIN + 4)];

    const int y0 = blockIdx.x * 2;
    const int py = blockIdx.y >> 1, px = blockIdx.y & 1;
    const int b   = blockIdx.z / nOcb;
    const int ocb = (blockIdx.z % nOcb) * 128;

    const int tid  = threadIdx.x;
    const int wid  = tid >> 5;
    const int lane = tid & 31;
    const int wm   = wid >> 2;
    const int wn   = wid & 3;
    const int yl   = wn >> 1;
    const int xb   = (wn & 1) * (HIN / 2);
    const int lq   = lane >> 2;
    const int lr   = lane & 3;
    const int NT   = HIN / 16;
    const int ISTR = HIN + 4;

    float acc[4][4][4];
#pragma unroll
    for (int mt = 0; mt < 4; mt++)
#pragma unroll
        for (int nt = 0; nt < 4; nt++)
#pragma unroll
            for (int i = 0; i < 4; i++) acc[mt][nt][i] = 0.f;

    const float* inB = in + ((size_t)b * CIN) * HIN * HIN;

    for (int ch = 0; ch < CIN / 8; ch++) {
        for (int idx = tid; idx < 8 * 3 * WROW; idx += 256) {
            int icl = idx / (3 * WROW);
            int rem = idx - icl * 3 * WROW;
            int r = rem / WROW, s = rem - r * WROW;
            int iy = y0 + py - 1 + r;
            int ix = px - 1 + s;
            float v = 0.f;
            if ((unsigned)iy < (unsigned)HIN && (unsigned)ix < (unsigned)HIN)
                v = inB[((size_t)(ch * 8 + icl) * HIN + iy) * HIN + ix];
            ins[(icl * 3 + r) * ISTR + s] = v;
        }
        for (int idx = tid; idx < 4096; idx += 256) {
            int oc = idx & 127;
            int icl = (idx >> 7) & 7;
            int tl = idx >> 10;
            int a = tl >> 1, c = tl & 1;
            int t = (1 - py + 2 * a) * 4 + (1 - px + 2 * c);
            ws[(tl * 8 + icl) * 132 + oc] =
                wt[((size_t)(t * CIN + ch * 8 + icl)) * Cout + ocb + oc];
        }
        __syncthreads();

#pragma unroll
        for (int tl = 0; tl < 4; tl++) {
            const int a = tl >> 1, c = tl & 1;
            unsigned ahi[4][4], alo[4][4];
#pragma unroll
            for (int mt = 0; mt < 4; mt++) {
                const float2* ap = &ws[(tl * 8 + lr) * 132 + wm * 64 + mt * 16 + lq];
                float2 p0 = ap[0], p1 = ap[8], p2 = ap[4 * 132], p3 = ap[4 * 132 + 8];
                ahi[mt][0] = __float_as_uint(p0.x);
                ahi[mt][1] = __float_as_uint(p1.x);
                ahi[mt][2] = __float_as_uint(p2.x);
                ahi[mt][3] = __float_as_uint(p3.x);
                if (TERMS == 3) {
                    alo[mt][0] = __float_as_uint(p0.y);
                    alo[mt][1] = __float_as_uint(p1.y);
                    alo[mt][2] = __float_as_uint(p2.y);
                    alo[mt][3] = __float_as_uint(p3.y);
                }
            }
#pragma unroll
            for (int nt = 0; nt < NT; nt++) {
                const int x = xb + nt * 8 + lq;
                const float* bp = &ins[(lr * 3 + (yl + 1 - a)) * ISTR + x + 1 - c];
                float rb0 = bp[0], rb1 = bp[4 * 3 * ISTR];
                if (TERMS == 3) {
                    unsigned bh0, bl0, bh1, bl1;
                    masksplit(rb0, bh0, bl0);
                    masksplit(rb1, bh1, bl1);
#pragma unroll
                    for (int mt = 0; mt < 4; mt++) {
                        mma8(acc[mt][nt], ahi[mt], bh0, bh1);
                        mma8(acc[mt][nt], ahi[mt], bl0, bl1);
                        mma8(acc[mt][nt], alo[mt], bh0, bh1);
                    }
                } else {
                    unsigned bh0 = tf32cvt(rb0), bh1 = tf32cvt(rb1);
#pragma unroll
                    for (int mt = 0; mt < 4; mt++)
                        mma8(acc[mt][nt], ahi[mt], bh0, bh1);
                }
            }
        }
        __syncthreads();
    }

    const int HOUT = 2 * HIN;
    const int oy = 2 * (y0 + yl) + py;
#pragma unroll
    for (int mt = 0; mt < 4; mt++) {
        const int oc = ocb + wm * 64 + mt * 16 + lq;
        const float b0v = bias[oc], b1v = bias[oc + 8];
#pragma unroll
        for (int nt = 0; nt < NT; nt++) {
            const int x = xb + nt * 8 + 2 * lr;
            const int ox = 2 * x + px;
            float* o0 = out + (((size_t)b * Cout + oc) * HOUT + oy) * HOUT + ox;
            float* o1 = o0 + (size_t)8 * HOUT * HOUT;
            o0[0] = fmaxf(acc[mt][nt][0] + b0v, 0.f);
            o0[2] = fmaxf(acc[mt][nt][1] + b0v, 0.f);
            o1[0] = fmaxf(acc[mt][nt][2] + b1v, 0.f);
            o1[2] = fmaxf(acc[mt][nt][3] + b1v, 0.f);
        }
    }
}

// ============================================================================
// Scalar kernels: conv1, dconv3out, vqk.
// ============================================================================
template <int CIN, bool RELU>
__global__ __launch_bounds__(256, 2)
void conv4s2(const float* __restrict__ in, const float* __restrict__ wt,
             const float* __restrict__ bias, float* __restrict__ out,
             int Cout, int Hin, int Win, int Hout, int Wout, int tilesX) {
    __shared__ float ish[34 * 36];
    __shared__ float wsh[64 * 16];

    const int tile = blockIdx.x;
    const int tx0 = (tile % tilesX) * 16;
    const int ty0 = (tile / tilesX) * 16;
    const int ocb = blockIdx.y * 64;
    const int b   = blockIdx.z;

    const int tid = threadIdx.x;
    const int og  = tid >> 5;
    const int sp  = tid & 31;
    const int r   = sp >> 1;
    const int cb  = (sp & 1) * 8;

    float acc[8][8];
#pragma unroll
    for (int o = 0; o < 8; o++) {
        float bv = bias[ocb + og * 8 + o];
#pragma unroll
        for (int j = 0; j < 8; j++) acc[o][j] = bv;
    }

    const int iy0 = ty0 * 2 - 1, ix0 = tx0 * 2 - 1;
    const float* inB = in + ((size_t)b * CIN) * Hin * Win;

    for (int ic = 0; ic < CIN; ic++) {
        const float* inC = inB + (size_t)ic * Hin * Win;
        for (int idx = tid; idx < 34 * 34; idx += 256) {
            int py = idx / 34, px = idx - py * 34;
            int iy = iy0 + py, ix = ix0 + px;
            float v = 0.f;
            if ((unsigned)iy < (unsigned)Hin && (unsigned)ix < (unsigned)Win)
                v = inC[iy * Win + ix];
            ish[py * 36 + px] = v;
        }
        const float* wC = wt + (ic * Cout + ocb) * 16;
        for (int idx = tid; idx < 1024; idx += 256) wsh[idx] = wC[idx];
        __syncthreads();

#pragma unroll
        for (int ky = 0; ky < 4; ky++) {
            const float* rp = &ish[(2 * r + ky) * 36 + 2 * cb];
            float4 v0 = *(const float4*)(rp);
            float4 v1 = *(const float4*)(rp + 4);
            float4 v2 = *(const float4*)(rp + 8);
            float4 v3 = *(const float4*)(rp + 12);
            float4 v4 = *(const float4*)(rp + 16);
            float riv[20] = {v0.x, v0.y, v0.z, v0.w, v1.x, v1.y, v1.z, v1.w,
                             v2.x, v2.y, v2.z, v2.w, v3.x, v3.y, v3.z, v3.w,
                             v4.x, v4.y, v4.z, v4.w};
#pragma unroll
            for (int kx = 0; kx < 4; kx++) {
                const int t = ky * 4 + kx;
                float wv[8];
#pragma unroll
                for (int o = 0; o < 8; o++) wv[o] = wsh[(og * 8 + o) * 16 + t];
#pragma unroll
                for (int o = 0; o < 8; o++)
#pragma unroll
                    for (int j = 0; j < 8; j++)
                        acc[o][j] = fmaf(wv[o], riv[kx + 2 * j], acc[o][j]);
            }
        }
        __syncthreads();
    }

    const int oy = ty0 + r;
    const int oxb = tx0 + cb;
#pragma unroll
    for (int o = 0; o < 8; o++) {
        float* op = out + (((size_t)b * Cout + ocb + og * 8 + o) * Hout + oy) * Wout + oxb;
        float tmp[8];
#pragma unroll
        for (int j = 0; j < 8; j++)
            tmp[j] = RELU ? fmaxf(acc[o][j], 0.f) : acc[o][j];
        *(float4*)op       = make_float4(tmp[0], tmp[1], tmp[2], tmp[3]);
        *(float4*)(op + 4) = make_float4(tmp[4], tmp[5], tmp[6], tmp[7]);
    }
}

__global__ __launch_bounds__(128, 4)
void dconv3out(const float* __restrict__ in, const float* __restrict__ wt,
               const float* __restrict__ bias, float* __restrict__ out,
               int tilesX) {
    const int Cin = 128, Hin = 128, Win = 128, Hout = 256, Wout = 256;
    __shared__ float ish[4][18 * 19];
    __shared__ float wsh[4][3 * 16];

    const int tile = blockIdx.x;
    const int ox0 = (tile % tilesX) * 32;
    const int oy0 = (tile / tilesX) * 32;
    const int b   = blockIdx.y;

    const int tid = threadIdx.x;
    const int q   = tid >> 5;
    const int py  = q >> 1, px = q & 1;
    const int sp  = tid & 31;
    const int ry  = sp >> 1;
    const int ch  = (sp & 1) * 8;

    float acc[3][8];
#pragma unroll
    for (int o = 0; o < 3; o++) {
        float bv = bias[o];
#pragma unroll
        for (int j = 0; j < 8; j++) acc[o][j] = bv;
    }

    const int iy0 = oy0 >> 1, ix0 = ox0 >> 1;
    const int kp = 1 - py, kq = 1 - px;

    for (int ic0 = 0; ic0 < Cin; ic0 += 4) {
        for (int idx = tid; idx < 4 * 324; idx += 128) {
            int icc = idx / 324, p = idx - icc * 324;
            int piy = p / 18, pix = p - piy * 18;
            int iy = iy0 - 1 + piy, ix = ix0 - 1 + pix;
            float v = 0.f;
            if ((unsigned)iy < (unsigned)Hin && (unsigned)ix < (unsigned)Win)
                v = in[(((size_t)b * Cin + ic0 + icc) * Hin + iy) * Win + ix];
            ish[icc][piy * 19 + pix] = v;
        }
        for (int idx = tid; idx < 4 * 48; idx += 128) {
            int icc = idx / 48, rmd = idx - icc * 48;
            wsh[icc][rmd] = wt[(ic0 + icc) * 48 + rmd];
        }
        __syncthreads();

#pragma unroll
        for (int icc = 0; icc < 4; icc++) {
#pragma unroll
            for (int a = 0; a < 2; a++) {
                const int ky  = kp + 2 * a;
                const int liy = ry + 1 + py - a;
                float iv[10];
                const int base = liy * 19 + ch + px;
#pragma unroll
                for (int j = 0; j < 10; j++) iv[j] = ish[icc][base + j];
#pragma unroll
                for (int c = 0; c < 2; c++) {
                    const int kx  = kq + 2 * c;
                    const int t   = ky * 4 + kx;
                    const int off = 1 - c;
                    float wv[3];
#pragma unroll
                    for (int o = 0; o < 3; o++) wv[o] = wsh[icc][o * 16 + t];
#pragma unroll
                    for (int o = 0; o < 3; o++)
#pragma unroll
                        for (int j = 0; j < 8; j++)
                            acc[o][j] = fmaf(wv[o], iv[j + off], acc[o][j]);
                }
            }
        }
        __syncthreads();
    }

    const int oy = oy0 + 2 * ry + py;
#pragma unroll
    for (int o = 0; o < 3; o++) {
        float* op = out + (((size_t)b * 3 + o) * Hout + oy) * Wout + ox0 + px + 2 * ch;
#pragma unroll
        for (int j = 0; j < 8; j++) op[2 * j] = acc[o][j];
    }
}

__global__ __launch_bounds__(128, 8)
void vqk(const float* __restrict__ ze, const float* __restrict__ emb,
         float* __restrict__ zq, float* __restrict__ idxf) {
    __shared__ __align__(16) float esh[64 * 64];
    __shared__ float en[64];

    const int row = blockIdx.x * 128 + threadIdx.x;
    float f[64];
    const float4* fp = (const float4*)(ze + (size_t)row * 64);
#pragma unroll
    for (int i = 0; i < 16; i++) {
        float4 v = fp[i];
        f[4 * i] = v.x; f[4 * i + 1] = v.y; f[4 * i + 2] = v.z; f[4 * i + 3] = v.w;
    }
    float fn = 0.f;
#pragma unroll
    for (int d = 0; d < 64; d++) fn = fmaf(f[d], f[d], fn);

    float best = 3.4e38f;
    int bidx = 0;
    for (int cb = 0; cb < 512; cb += 64) {
        __syncthreads();
        const float4* src = (const float4*)(emb + (size_t)cb * 64);
        for (int i = threadIdx.x; i < 1024; i += 128)
            ((float4*)esh)[i] = src[i];
        __syncthreads();
        if (threadIdx.x < 64) {
            float s = 0.f;
            const float* e = esh + threadIdx.x * 64;
#pragma unroll
            for (int d = 0; d < 64; d++) s = fmaf(e[d], e[d], s);
            en[threadIdx.x] = s;
        }
        __syncthreads();
        for (int c = 0; c < 64; c++) {
            const float4* ev = (const float4*)(esh + c * 64);
            float dot = 0.f;
#pragma unroll
            for (int i = 0; i < 16; i++) {
                float4 e = ev[i];
                dot = fmaf(f[4 * i], e.x, dot);
                dot = fmaf(f[4 * i + 1], e.y, dot);
                dot = fmaf(f[4 * i + 2], e.z, dot);
                dot = fmaf(f[4 * i + 3], e.w, dot);
            }
            float sc = fn - 2.f * dot + en[c];
            if (sc < best) { best = sc; bidx = cb + c; }
        }
    }

    idxf[row] = (float)bidx;
    const float4* ep = (const float4*)(emb + (size_t)bidx * 64);
    float4* qp = (float4*)(zq + (size_t)row * 64);
#pragma unroll
    for (int i = 0; i < 16; i++) qp[i] = ep[i];
}

// ---------------------------------------------------------------------------
extern "C" void kernel_launch(void* const* d_in, const int* in_sizes, int n_in,
                              void* d_out, int out_size) {
    (void)in_sizes; (void)n_in;
    const float* x   = (const float*)d_in[0];
    const float* w1  = (const float*)d_in[1];
    const float* b1  = (const float*)d_in[2];
    const float* w2  = (const float*)d_in[3];
    const float* b2  = (const float*)d_in[4];
    const float* w3  = (const float*)d_in[5];
    const float* b3  = (const float*)d_in[6];
    const float* d1w = (const float*)d_in[7];
    const float* d1b = (const float*)d_in[8];
    const float* d2w = (const float*)d_in[9];
    const float* d2b = (const float*)d_in[10];
    const float* d3w = (const float*)d_in[11];
    const float* d3b = (const float*)d_in[12];
    const float* emb = (const float*)d_in[13];

    float *h1, *h2, *g1, *g2, *ze, *zq, *idxf, *wt1;
    float2 *w2s, *w3s, *d2s, *d1s;
    cudaGetSymbolAddress((void**)&h1, g_h1);
    cudaGetSymbolAddress((void**)&h2, g_h2);
    cudaGetSymbolAddress((void**)&g1, g_g1);
    cudaGetSymbolAddress((void**)&g2, g_g2);
    cudaGetSymbolAddress((void**)&ze, g_ze);
    cudaGetSymbolAddress((void**)&zq, g_zq);
    cudaGetSymbolAddress((void**)&idxf, g_if);
    cudaGetSymbolAddress((void**)&wt1, g_wt1);
    cudaGetSymbolAddress((void**)&w2s, g_w2s);
    cudaGetSymbolAddress((void**)&w3s, g_w3s);
    cudaGetSymbolAddress((void**)&d2s, g_d2s);
    cudaGetSymbolAddress((void**)&d1s, g_d1s);

    float* outF = (float*)d_out;
    const int NX = NBATCH * 3 * 256 * 256;
    const int NZ = NBATCH * 64 * 32 * 32;
    const int NI = 16384;
    if (out_size >= NX + 2 * NZ + NI) {
        ze   = outF + NX;
        zq   = outF + NX + NZ;
        idxf = outF + NX + 2 * NZ;
    }

    static bool attr_done = false;
    if (!attr_done) {
        cudaFuncSetAttribute(conv2_mma, cudaFuncAttributeMaxDynamicSharedMemorySize,
                             C2_SMEM);
        cudaFuncSetAttribute(conv3_mma, cudaFuncAttributeMaxDynamicSharedMemorySize,
                             C3_SMEM);
        attr_done = true;
    }

    wsplit2t<<<2048, 256>>>(w2, w2s);
    wtrans<<<(128 * 3 * 16 + 255) / 256, 256>>>(w1, wt1, 128, 3);
    conv4s2<3, true><<<dim3(64, 2, NBATCH), 256>>>(x, wt1, b1, h1, 128, 256, 256, 128, 128, 8);
    conv2_mma<<<dim3(32, 2, NBATCH), 256, C2_SMEM>>>(h1, w2s, b2, h2);
    wsplit3<<<1024, 256>>>(w3, w3s);
    conv3_mma<<<dim3(4, 1, NBATCH * 4), 256, C3_SMEM>>>(h2, w3s, g2);
    addparts<<<NZ / 256, 256>>>(g2, b3, ze);
    vqk<<<128, 128>>>(ze, emb, zq, idxf);
    wsplitD1<<<1024, 256>>>(d1w, d1s);
    dconv_mma<64, 32, 1><<<dim3(16, 4, NBATCH * 2), 256>>>(zq, d1s, d1b, g1, 256, 2);
    wsplitD2<<<2048, 256>>>(d2w, d2s);
    dconv_mma<256, 64, 1><<<dim3(32, 4, NBATCH), 256>>>(g1, d2s, d2b, g2, 128, 1);
    dconv3out<<<dim3(64, NBATCH), 128>>>(g2, d3w, d3b, outF, 8);
}

// round 9
// speedup vs baseline: 1.1534x; 1.1259x over previous
#include <cuda_runtime.h>

// ---------------------------------------------------------------------------
// VQ-VAE forward, sm_100a.  (R5 math + cp.async double-buffered weights.)
//   Encoder conv2/conv3: mma.sync tf32 3-term hi/lo split (argmin-safe).
//   Decoder dconv1/dconv2: mma.sync tf32 1-term.
//   conv2/dconv1/dconv2: weight staging via cp.async ping-pong (latency hidden).
//   conv1 / dconv3 / VQ: scalar-FFMA register-tiled.
// Output layout: [x_recon | z_e | z_q | idx(as float)], fp32.
// ---------------------------------------------------------------------------

#define NBATCH 16

// -------- scratch ------------------------------------------------------------
__device__ float g_h1[NBATCH * 128 * 128 * 128];
__device__ float g_h2[NBATCH * 256 * 64 * 64];
__device__ float g_g1[NBATCH * 256 * 64 * 64];
__device__ float g_g2[NBATCH * 128 * 128 * 128];
__device__ float g_ze[NBATCH * 64 * 32 * 32];
__device__ float g_zq[NBATCH * 64 * 32 * 32];
__device__ float g_if[16384];
__device__ float g_wt1[128 * 3 * 16];
__device__ float2 g_w2s[16 * 128 * 256];   // conv2  [t][ic][oc] (hi,lo)
__device__ float2 g_w3s[16 * 256 * 64];    // conv3  [t][ic][oc] (hi,lo)
__device__ float2 g_d2s[16 * 256 * 128];   // dconv2 [t][ic][oc] (hi,lo)
__device__ float2 g_d1s[16 * 64 * 256];    // dconv1 [t][ic][oc] (hi,lo)

// -------- helpers ------------------------------------------------------------
__device__ __forceinline__ void tf32split(float v, unsigned& hi, unsigned& lo) {
    unsigned h;
    asm("cvt.rna.tf32.f32 %0,%1;" : "=r"(h) : "f"(v));
    float l = v - __uint_as_float(h);
    unsigned lw;
    asm("cvt.rna.tf32.f32 %0,%1;" : "=r"(lw) : "f"(l));
    hi = h; lo = lw;
}
__device__ __forceinline__ unsigned tf32cvt(float v) {
    unsigned h;
    asm("cvt.rna.tf32.f32 %0,%1;" : "=r"(h) : "f"(v));
    return h;
}
__device__ __forceinline__ float2 splitpack(float v) {
    unsigned h, l;
    tf32split(v, h, l);
    return make_float2(__uint_as_float(h), __uint_as_float(l));
}
__device__ __forceinline__ void mma8(float* c, const unsigned* a,
                                     unsigned b0, unsigned b1) {
    asm("mma.sync.aligned.m16n8k8.row.col.f32.tf32.tf32.f32 "
        "{%0,%1,%2,%3},{%4,%5,%6,%7},{%8,%9},{%0,%1,%2,%3};"
        : "+f"(c[0]), "+f"(c[1]), "+f"(c[2]), "+f"(c[3])
        : "r"(a[0]), "r"(a[1]), "r"(a[2]), "r"(a[3]), "r"(b0), "r"(b1));
}
__device__ __forceinline__ void cp_async8(unsigned dst, const void* src) {
    asm volatile("cp.async.ca.shared.global [%0], [%1], 8;\n"
                 :: "r"(dst), "l"(src));
}
__device__ __forceinline__ void cp_commit() {
    asm volatile("cp.async.commit_group;\n");
}
template <int N>
__device__ __forceinline__ void cp_wait() {
    asm volatile("cp.async.wait_group %0;\n" :: "n"(N));
}

// -------- weight transforms --------------------------------------------------
__global__ void wtrans(const float* __restrict__ w, float* __restrict__ wo,
                       int Cout, int Cin) {   // OIHW -> [ic][oc][t]
    int idx = blockIdx.x * 256 + threadIdx.x;
    int total = Cout * Cin * 16;
    if (idx < total) {
        int t = idx & 15;
        int rest = idx >> 4;
        int ic = rest % Cin;
        int oc = rest / Cin;
        wo[(ic * Cout + oc) * 16 + t] = w[idx];
    }
}
__global__ void wsplit2t(const float* __restrict__ w, float2* __restrict__ wo) {
    int idx = blockIdx.x * 256 + threadIdx.x;   // 524288
    int t = idx & 15, ic = (idx >> 4) & 127, oc = idx >> 11;
    wo[(t * 128 + ic) * 256 + oc] = splitpack(w[idx]);
}
__global__ void wsplit3(const float* __restrict__ w, float2* __restrict__ wo) {
    int idx = blockIdx.x * 256 + threadIdx.x;   // 262144
    int t = idx & 15, ic = (idx >> 4) & 255, oc = idx >> 12;
    wo[(t * 256 + ic) * 64 + oc] = splitpack(w[idx]);
}
__global__ void wsplitD2(const float* __restrict__ w, float2* __restrict__ wo) {
    int idx = blockIdx.x * 256 + threadIdx.x;   // 524288
    int t = idx & 15, oc = (idx >> 4) & 127, ic = idx >> 11;
    wo[(t * 256 + ic) * 128 + oc] = splitpack(w[idx]);
}
__global__ void wsplitD1(const float* __restrict__ w, float2* __restrict__ wo) {
    int idx = blockIdx.x * 256 + threadIdx.x;   // 262144
    int t = idx & 15, oc = (idx >> 4) & 255, ic = idx >> 12;
    wo[(t * 64 + ic) * 256 + oc] = splitpack(w[idx]);
}

// ============================================================================
// conv2 MMA (3-term): h1 -> h2, k4 s2 p1, relu.
// Weights double-buffered via cp.async; 64 chunks = 16 ch x 4 tap-groups.
// smem: 2 x 33.8KB weights + 25.3KB input ~ 90.8KB -> 2 CTAs/SM.
// ============================================================================
#define C2_WS2 (4 * 8 * 132)              // float2 per buffer
#define C2_INS (8 * 6 * 132)              // float
#define C2_SMEM ((4 * C2_WS2 + C2_INS) * 4)
__global__ __launch_bounds__(256, 2)
void conv2_mma(const float* __restrict__ in, const float2* __restrict__ wt,
               const float* __restrict__ bias, float* __restrict__ out) {
    extern __shared__ float sm[];
    float2* ws0 = (float2*)sm;            // [2][C2_WS2]
    float* ins = sm + 4 * C2_WS2;
    unsigned ws_base = (unsigned)__cvta_generic_to_shared(ws0);

    const int oy0 = blockIdx.x * 2;
    const int ocb = blockIdx.y * 128;
    const int b   = blockIdx.z;

    const int tid  = threadIdx.x;
    const int wid  = tid >> 5;
    const int lane = tid & 31;
    const int wm   = wid >> 2;
    const int wn   = wid & 3;
    const int oyl  = wn >> 1;
    const int xb   = (wn & 1) * 32;
    const int lq   = lane >> 2;
    const int lr   = lane & 3;

    float acc[4][4][4];
#pragma unroll
    for (int mt = 0; mt < 4; mt++)
#pragma unroll
        for (int nt = 0; nt < 4; nt++)
#pragma unroll
            for (int i = 0; i < 4; i++) acc[mt][nt][i] = 0.f;

    const int iy0 = oy0 * 2 - 1;
    const float* inB = in + ((size_t)b * 128) * 128 * 128;

    // async weight stage for chunk c into buffer buf
    auto stage_w = [&](int c, int buf) {
        const int tg = c & 3, ch = c >> 2;
#pragma unroll
        for (int i = 0; i < 16; i++) {
            int idx = tid + i * 256;
            int oc = idx & 127, icl = (idx >> 7) & 7, tl = idx >> 10;
            const float2* src =
                wt + ((size_t)((tg * 4 + tl) * 128 + ch * 8 + icl)) * 256 + ocb + oc;
            unsigned dst = ws_base + (unsigned)(buf * C2_WS2 + (tl * 8 + icl) * 132 + oc) * 8u;
            cp_async8(dst, src);
        }
        cp_commit();
    };

    stage_w(0, 0);
    for (int c = 0; c < 64; c++) {
        const int ch = c >> 2, tg = c & 3;
        if (tg == 0) {
            for (int idx = tid; idx < 8 * 6 * 132; idx += 256) {
                int icl = idx / 792;
                int rem = idx - icl * 792;
                int r = rem / 132, cc = rem - r * 132;
                int iy = iy0 + r, ix = cc - 1;
                float v = 0.f;
                if ((unsigned)iy < 128u && (unsigned)ix < 128u)
                    v = inB[((size_t)(ch * 8 + icl) * 128 + iy) * 128 + ix];
                ins[idx] = v;
            }
        }
        if (c < 63) { stage_w(c + 1, (c + 1) & 1); cp_wait<1>(); }
        else cp_wait<0>();
        __syncthreads();

        const float2* ws = ws0 + (c & 1) * C2_WS2;
#pragma unroll
        for (int tapl = 0; tapl < 4; tapl++) {
            const int ky = tg, kx = tapl;
            unsigned ahi[4][4], alo[4][4];
#pragma unroll
            for (int mt = 0; mt < 4; mt++) {
                const float2* ap = &ws[(tapl * 8 + lr) * 132 + wm * 64 + mt * 16 + lq];
                float2 p0 = ap[0], p1 = ap[8], p2 = ap[4 * 132], p3 = ap[4 * 132 + 8];
                ahi[mt][0] = __float_as_uint(p0.x); alo[mt][0] = __float_as_uint(p0.y);
                ahi[mt][1] = __float_as_uint(p1.x); alo[mt][1] = __float_as_uint(p1.y);
                ahi[mt][2] = __float_as_uint(p2.x); alo[mt][2] = __float_as_uint(p2.y);
                ahi[mt][3] = __float_as_uint(p3.x); alo[mt][3] = __float_as_uint(p3.y);
            }
#pragma unroll
            for (int nt = 0; nt < 4; nt++) {
                const int ox = xb + nt * 8 + lq;
                const float* bp = &ins[lr * 792 + (2 * oyl + ky) * 132 + 2 * ox + kx];
                float rb0 = bp[0], rb1 = bp[4 * 792];
                unsigned bh0, bl0, bh1, bl1;
                tf32split(rb0, bh0, bl0);
                tf32split(rb1, bh1, bl1);
#pragma unroll
                for (int mt = 0; mt < 4; mt++) {
                    mma8(acc[mt][nt], ahi[mt], bh0, bh1);
                    mma8(acc[mt][nt], ahi[mt], bl0, bl1);
                    mma8(acc[mt][nt], alo[mt], bh0, bh1);
                }
            }
        }
        __syncthreads();
    }

    const int oy = oy0 + oyl;
#pragma unroll
    for (int mt = 0; mt < 4; mt++) {
        const int oc = ocb + wm * 64 + mt * 16 + lq;
        const float b0v = bias[oc], b1v = bias[oc + 8];
#pragma unroll
        for (int nt = 0; nt < 4; nt++) {
            const int ox = xb + nt * 8 + 2 * lr;
            float* o0 = out + (((size_t)b * 256 + oc) * 64 + oy) * 64 + ox;
            float* o1 = o0 + (size_t)8 * 64 * 64;
            *(float2*)o0 = make_float2(fmaxf(acc[mt][nt][0] + b0v, 0.f),
                                       fmaxf(acc[mt][nt][1] + b0v, 0.f));
            *(float2*)o1 = make_float2(fmaxf(acc[mt][nt][2] + b1v, 0.f),
                                       fmaxf(acc[mt][nt][3] + b1v, 0.f));
        }
    }
}

// ============================================================================
// conv3 MMA (3-term): h2 -> 4 K-slab partials.  (R5, unchanged)
// ============================================================================
#define C3_WS2 (4 * 8 * 68)
#define C3_INS (8 * 18 * 68)
#define C3_SMEM ((2 * C3_WS2 + C3_INS) * 4)
__global__ __launch_bounds__(256, 2)
void conv3_mma(const float* __restrict__ in, const float2* __restrict__ wt,
               float* __restrict__ outp) {
    extern __shared__ float sm[];
    float2* ws = (float2*)sm;
    float* ins = sm + 2 * C3_WS2;

    const int r0   = blockIdx.x * 8;
    const int b    = blockIdx.z >> 2;
    const int slab = blockIdx.z & 3;

    const int tid  = threadIdx.x;
    const int w    = tid >> 5;
    const int lane = tid & 31;
    const int lq   = lane >> 2;
    const int lr   = lane & 3;

    float acc[4][4][4];
#pragma unroll
    for (int mt = 0; mt < 4; mt++)
#pragma unroll
        for (int nt = 0; nt < 4; nt++)
#pragma unroll
            for (int i = 0; i < 4; i++) acc[mt][nt][i] = 0.f;

    const int iy0 = r0 * 2 - 1;
    const float* inB = in + ((size_t)b * 256 + slab * 64) * 64 * 64;

    for (int ch = 0; ch < 8; ch++) {
        for (int idx = tid; idx < 8 * 18 * 66; idx += 256) {
            int icl = idx / 1188;
            int rem = idx - icl * 1188;
            int r = rem / 66, c = rem - r * 66;
            int iy = iy0 + r, ix = c - 1;
            float v = 0.f;
            if ((unsigned)iy < 64u && (unsigned)ix < 64u)
                v = inB[((size_t)(ch * 8 + icl) * 64 + iy) * 64 + ix];
            ins[icl * 1224 + r * 68 + c] = v;
        }
        for (int tg = 0; tg < 4; tg++) {
            for (int idx = tid; idx < 2048; idx += 256) {
                int oc = idx & 63;
                int icl = (idx >> 6) & 7;
                int tl = idx >> 9;
                ws[(tl * 8 + icl) * 68 + oc] =
                    wt[((size_t)((tg * 4 + tl) * 256 + slab * 64 + ch * 8 + icl)) * 64 + oc];
            }
            __syncthreads();

#pragma unroll
            for (int tapl = 0; tapl < 4; tapl++) {
                const int ky = tg, kx = tapl;
                unsigned ahi[4][4], alo[4][4];
#pragma unroll
                for (int mt = 0; mt < 4; mt++) {
                    const float2* ap = &ws[(tapl * 8 + lr) * 68 + mt * 16 + lq];
                    float2 p0 = ap[0], p1 = ap[8], p2 = ap[4 * 68], p3 = ap[4 * 68 + 8];
                    ahi[mt][0] = __float_as_uint(p0.x); alo[mt][0] = __float_as_uint(p0.y);
                    ahi[mt][1] = __float_as_uint(p1.x); alo[mt][1] = __float_as_uint(p1.y);
                    ahi[mt][2] = __float_as_uint(p2.x); alo[mt][2] = __float_as_uint(p2.y);
                    ahi[mt][3] = __float_as_uint(p3.x); alo[mt][3] = __float_as_uint(p3.y);
                }
#pragma unroll
                for (int nt = 0; nt < 4; nt++) {
                    const int col = nt * 8 + lq;
                    const float* bp = &ins[lr * 1224 + (2 * w + ky) * 68 + 2 * col + kx];
                    float rb0 = bp[0], rb1 = bp[4 * 1224];
                    unsigned bh0, bl0, bh1, bl1;
                    tf32split(rb0, bh0, bl0);
                    tf32split(rb1, bh1, bl1);
#pragma unroll
                    for (int mt = 0; mt < 4; mt++) {
                        mma8(acc[mt][nt], ahi[mt], bh0, bh1);
                        mma8(acc[mt][nt], ahi[mt], bl0, bl1);
                        mma8(acc[mt][nt], alo[mt], bh0, bh1);
                    }
                }
            }
            __syncthreads();
        }
    }

    const int NZ = NBATCH * 64 * 32 * 32;
    float* part = outp + (size_t)slab * NZ;
    const int row = r0 + w;
#pragma unroll
    for (int mt = 0; mt < 4; mt++) {
        const int oc = mt * 16 + lq;
#pragma unroll
        for (int nt = 0; nt < 4; nt++) {
            float* o0 = part + (((size_t)b * 64 + oc) * 32 + row) * 32 + nt * 8 + 2 * lr;
            float* o1 = o0 + (size_t)8 * 32 * 32;
            *(float2*)o0 = make_float2(acc[mt][nt][0], acc[mt][nt][1]);
            *(float2*)o1 = make_float2(acc[mt][nt][2], acc[mt][nt][3]);
        }
    }
}

__global__ void addparts(const float* __restrict__ p, const float* __restrict__ bias,
                         float* __restrict__ ze) {
    const int S = NBATCH * 64 * 32 * 32;
    int i = blockIdx.x * 256 + threadIdx.x;
    float v = p[i] + p[i + S] + p[i + 2 * S] + p[i + 3 * S];
    ze[i] = v + bias[(i >> 10) & 63];
}

// ============================================================================
// dconv MMA (1-term tf32), weights double-buffered via cp.async.
// smem: 2 x 33.8KB weights + input -> dynamic.
// ============================================================================
#define D_WS2 (4 * 8 * 132)
template <int CIN, int HIN>
__global__ __launch_bounds__(256, 2)
void dconv_mma(const float* __restrict__ in, const float2* __restrict__ wt,
               const float* __restrict__ bias, float* __restrict__ out,
               int Cout, int nOcb) {
    const int WROW = HIN + 2;
    const int ISTR = HIN + 4;
    extern __shared__ float sm[];
    float2* ws0 = (float2*)sm;            // [2][D_WS2]
    float* ins = sm + 4 * D_WS2;          // [8*3*ISTR]
    unsigned ws_base = (unsigned)__cvta_generic_to_shared(ws0);

    const int y0 = blockIdx.x * 2;
    const int py = blockIdx.y >> 1, px = blockIdx.y & 1;
    const int b   = blockIdx.z / nOcb;
    const int ocb = (blockIdx.z % nOcb) * 128;

    const int tid  = threadIdx.x;
    const int wid  = tid >> 5;
    const int lane = tid & 31;
    const int wm   = wid >> 2;
    const int wn   = wid & 3;
    const int yl   = wn >> 1;
    const int xb   = (wn & 1) * (HIN / 2);
    const int lq   = lane >> 2;
    const int lr   = lane & 3;
    const int NT   = HIN / 16;
    const int NCH  = CIN / 8;

    float acc[4][4][4];
#pragma unroll
    for (int mt = 0; mt < 4; mt++)
#pragma unroll
        for (int nt = 0; nt < 4; nt++)
#pragma unroll
            for (int i = 0; i < 4; i++) acc[mt][nt][i] = 0.f;

    const float* inB = in + ((size_t)b * CIN) * HIN * HIN;

    auto stage_w = [&](int ch, int buf) {
#pragma unroll
        for (int i = 0; i < 16; i++) {
            int idx = tid + i * 256;
            int oc = idx & 127, icl = (idx >> 7) & 7, tl = idx >> 10;
            int a = tl >> 1, c2 = tl & 1;
            int t = (1 - py + 2 * a) * 4 + (1 - px + 2 * c2);
            const float2* src =
                wt + ((size_t)(t * CIN + ch * 8 + icl)) * Cout + ocb + oc;
            unsigned dst = ws_base + (unsigned)(buf * D_WS2 + (tl * 8 + icl) * 132 + oc) * 8u;
            cp_async8(dst, src);
        }
        cp_commit();
    };

    stage_w(0, 0);
    for (int ch = 0; ch < NCH; ch++) {
        for (int idx = tid; idx < 8 * 3 * WROW; idx += 256) {
            int icl = idx / (3 * WROW);
            int rem = idx - icl * 3 * WROW;
            int r = rem / WROW, s = rem - r * WROW;
            int iy = y0 + py - 1 + r;
            int ix = px - 1 + s;
            float v = 0.f;
            if ((unsigned)iy < (unsigned)HIN && (unsigned)ix < (unsigned)HIN)
                v = inB[((size_t)(ch * 8 + icl) * HIN + iy) * HIN + ix];
            ins[(icl * 3 + r) * ISTR + s] = v;
        }
        if (ch + 1 < NCH) { stage_w(ch + 1, (ch + 1) & 1); cp_wait<1>(); }
        else cp_wait<0>();
        __syncthreads();

        const float2* ws = ws0 + (ch & 1) * D_WS2;
#pragma unroll
        for (int tl = 0; tl < 4; tl++) {
            const int a = tl >> 1, c = tl & 1;
            unsigned ahi[4][4];
#pragma unroll
            for (int mt = 0; mt < 4; mt++) {
                const float2* ap = &ws[(tl * 8 + lr) * 132 + wm * 64 + mt * 16 + lq];
                ahi[mt][0] = __float_as_uint(ap[0].x);
                ahi[mt][1] = __float_as_uint(ap[8].x);
                ahi[mt][2] = __float_as_uint(ap[4 * 132].x);
                ahi[mt][3] = __float_as_uint(ap[4 * 132 + 8].x);
            }
#pragma unroll
            for (int nt = 0; nt < NT; nt++) {
                const int x = xb + nt * 8 + lq;
                const float* bp = &ins[(lr * 3 + (yl + 1 - a)) * ISTR + x + 1 - c];
                unsigned bh0 = tf32cvt(bp[0]), bh1 = tf32cvt(bp[4 * 3 * ISTR]);
#pragma unroll
                for (int mt = 0; mt < 4; mt++)
                    mma8(acc[mt][nt], ahi[mt], bh0, bh1);
            }
        }
        __syncthreads();
    }

    const int HOUT = 2 * HIN;
    const int oy = 2 * (y0 + yl) + py;
#pragma unroll
    for (int mt = 0; mt < 4; mt++) {
        const int oc = ocb + wm * 64 + mt * 16 + lq;
        const float b0v = bias[oc], b1v = bias[oc + 8];
#pragma unroll
        for (int nt = 0; nt < NT; nt++) {
            const int x = xb + nt * 8 + 2 * lr;
            const int ox = 2 * x + px;
            float* o0 = out + (((size_t)b * Cout + oc) * HOUT + oy) * HOUT + ox;
            float* o1 = o0 + (size_t)8 * HOUT * HOUT;
            o0[0] = fmaxf(acc[mt][nt][0] + b0v, 0.f);
            o0[2] = fmaxf(acc[mt][nt][1] + b0v, 0.f);
            o1[0] = fmaxf(acc[mt][nt][2] + b1v, 0.f);
            o1[2] = fmaxf(acc[mt][nt][3] + b1v, 0.f);
        }
    }
}
#define DCONV_SMEM(HIN) ((4 * D_WS2 + 8 * 3 * ((HIN) + 4)) * 4)

// ============================================================================
// Scalar kernels: conv1, dconv3out, vqk.  (unchanged)
// ============================================================================
template <int CIN, bool RELU>
__global__ __launch_bounds__(256, 2)
void conv4s2(const float* __restrict__ in, const float* __restrict__ wt,
             const float* __restrict__ bias, float* __restrict__ out,
             int Cout, int Hin, int Win, int Hout, int Wout, int tilesX) {
    __shared__ float ish[34 * 36];
    __shared__ float wsh[64 * 16];

    const int tile = blockIdx.x;
    const int tx0 = (tile % tilesX) * 16;
    const int ty0 = (tile / tilesX) * 16;
    const int ocb = blockIdx.y * 64;
    const int b   = blockIdx.z;

    const int tid = threadIdx.x;
    const int og  = tid >> 5;
    const int sp  = tid & 31;
    const int r   = sp >> 1;
    const int cb  = (sp & 1) * 8;

    float acc[8][8];
#pragma unroll
    for (int o = 0; o < 8; o++) {
        float bv = bias[ocb + og * 8 + o];
#pragma unroll
        for (int j = 0; j < 8; j++) acc[o][j] = bv;
    }

    const int iy0 = ty0 * 2 - 1, ix0 = tx0 * 2 - 1;
    const float* inB = in + ((size_t)b * CIN) * Hin * Win;

    for (int ic = 0; ic < CIN; ic++) {
        const float* inC = inB + (size_t)ic * Hin * Win;
        for (int idx = tid; idx < 34 * 34; idx += 256) {
            int py = idx / 34, px = idx - py * 34;
            int iy = iy0 + py, ix = ix0 + px;
            float v = 0.f;
            if ((unsigned)iy < (unsigned)Hin && (unsigned)ix < (unsigned)Win)
                v = inC[iy * Win + ix];
            ish[py * 36 + px] = v;
        }
        const float* wC = wt + (ic * Cout + ocb) * 16;
        for (int idx = tid; idx < 1024; idx += 256) wsh[idx] = wC[idx];
        __syncthreads();

#pragma unroll
        for (int ky = 0; ky < 4; ky++) {
            const float* rp = &ish[(2 * r + ky) * 36 + 2 * cb];
            float4 v0 = *(const float4*)(rp);
            float4 v1 = *(const float4*)(rp + 4);
            float4 v2 = *(const float4*)(rp + 8);
            float4 v3 = *(const float4*)(rp + 12);
            float4 v4 = *(const float4*)(rp + 16);
            float riv[20] = {v0.x, v0.y, v0.z, v0.w, v1.x, v1.y, v1.z, v1.w,
                             v2.x, v2.y, v2.z, v2.w, v3.x, v3.y, v3.z, v3.w,
                             v4.x, v4.y, v4.z, v4.w};
#pragma unroll
            for (int kx = 0; kx < 4; kx++) {
                const int t = ky * 4 + kx;
                float wv[8];
#pragma unroll
                for (int o = 0; o < 8; o++) wv[o] = wsh[(og * 8 + o) * 16 + t];
#pragma unroll
                for (int o = 0; o < 8; o++)
#pragma unroll
                    for (int j = 0; j < 8; j++)
                        acc[o][j] = fmaf(wv[o], riv[kx + 2 * j], acc[o][j]);
            }
        }
        __syncthreads();
    }

    const int oy = ty0 + r;
    const int oxb = tx0 + cb;
#pragma unroll
    for (int o = 0; o < 8; o++) {
        float* op = out + (((size_t)b * Cout + ocb + og * 8 + o) * Hout + oy) * Wout + oxb;
        float tmp[8];
#pragma unroll
        for (int j = 0; j < 8; j++)
            tmp[j] = RELU ? fmaxf(acc[o][j], 0.f) : acc[o][j];
        *(float4*)op       = make_float4(tmp[0], tmp[1], tmp[2], tmp[3]);
        *(float4*)(op + 4) = make_float4(tmp[4], tmp[5], tmp[6], tmp[7]);
    }
}

__global__ __launch_bounds__(128, 4)
void dconv3out(const float* __restrict__ in, const float* __restrict__ wt,
               const float* __restrict__ bias, float* __restrict__ out,
               int tilesX) {
    const int Cin = 128, Hin = 128, Win = 128, Hout = 256, Wout = 256;
    __shared__ float ish[4][18 * 19];
    __shared__ float wsh[4][3 * 16];

    const int tile = blockIdx.x;
    const int ox0 = (tile % tilesX) * 32;
    const int oy0 = (tile / tilesX) * 32;
    const int b   = blockIdx.y;

    const int tid = threadIdx.x;
    const int q   = tid >> 5;
    const int py  = q >> 1, px = q & 1;
    const int sp  = tid & 31;
    const int ry  = sp >> 1;
    const int ch  = (sp & 1) * 8;

    float acc[3][8];
#pragma unroll
    for (int o = 0; o < 3; o++) {
        float bv = bias[o];
#pragma unroll
        for (int j = 0; j < 8; j++) acc[o][j] = bv;
    }

    const int iy0 = oy0 >> 1, ix0 = ox0 >> 1;
    const int kp = 1 - py, kq = 1 - px;

    for (int ic0 = 0; ic0 < Cin; ic0 += 4) {
        for (int idx = tid; idx < 4 * 324; idx += 128) {
            int icc = idx / 324, p = idx - icc * 324;
            int piy = p / 18, pix = p - piy * 18;
            int iy = iy0 - 1 + piy, ix = ix0 - 1 + pix;
            float v = 0.f;
            if ((unsigned)iy < (unsigned)Hin && (unsigned)ix < (unsigned)Win)
                v = in[(((size_t)b * Cin + ic0 + icc) * Hin + iy) * Win + ix];
            ish[icc][piy * 19 + pix] = v;
        }
        for (int idx = tid; idx < 4 * 48; idx += 128) {
            int icc = idx / 48, rmd = idx - icc * 48;
            wsh[icc][rmd] = wt[(ic0 + icc) * 48 + rmd];
        }
        __syncthreads();

#pragma unroll
        for (int icc = 0; icc < 4; icc++) {
#pragma unroll
            for (int a = 0; a < 2; a++) {
                const int ky  = kp + 2 * a;
                const int liy = ry + 1 + py - a;
                float iv[10];
                const int base = liy * 19 + ch + px;
#pragma unroll
                for (int j = 0; j < 10; j++) iv[j] = ish[icc][base + j];
#pragma unroll
                for (int c = 0; c < 2; c++) {
                    const int kx  = kq + 2 * c;
                    const int t   = ky * 4 + kx;
                    const int off = 1 - c;
                    float wv[3];
#pragma unroll
                    for (int o = 0; o < 3; o++) wv[o] = wsh[icc][o * 16 + t];
#pragma unroll
                    for (int o = 0; o < 3; o++)
#pragma unroll
                        for (int j = 0; j < 8; j++)
                            acc[o][j] = fmaf(wv[o], iv[j + off], acc[o][j]);
                }
            }
        }
        __syncthreads();
    }

    const int oy = oy0 + 2 * ry + py;
#pragma unroll
    for (int o = 0; o < 3; o++) {
        float* op = out + (((size_t)b * 3 + o) * Hout + oy) * Wout + ox0 + px + 2 * ch;
#pragma unroll
        for (int j = 0; j < 8; j++) op[2 * j] = acc[o][j];
    }
}

__global__ __launch_bounds__(128, 8)
void vqk(const float* __restrict__ ze, const float* __restrict__ emb,
         float* __restrict__ zq, float* __restrict__ idxf) {
    __shared__ __align__(16) float esh[64 * 64];
    __shared__ float en[64];

    const int row = blockIdx.x * 128 + threadIdx.x;
    float f[64];
    const float4* fp = (const float4*)(ze + (size_t)row * 64);
#pragma unroll
    for (int i = 0; i < 16; i++) {
        float4 v = fp[i];
        f[4 * i] = v.x; f[4 * i + 1] = v.y; f[4 * i + 2] = v.z; f[4 * i + 3] = v.w;
    }
    float fn = 0.f;
#pragma unroll
    for (int d = 0; d < 64; d++) fn = fmaf(f[d], f[d], fn);

    float best = 3.4e38f;
    int bidx = 0;
    for (int cb = 0; cb < 512; cb += 64) {
        __syncthreads();
        const float4* src = (const float4*)(emb + (size_t)cb * 64);
        for (int i = threadIdx.x; i < 1024; i += 128)
            ((float4*)esh)[i] = src[i];
        __syncthreads();
        if (threadIdx.x < 64) {
            float s = 0.f;
            const float* e = esh + threadIdx.x * 64;
#pragma unroll
            for (int d = 0; d < 64; d++) s = fmaf(e[d], e[d], s);
            en[threadIdx.x] = s;
        }
        __syncthreads();
        for (int c = 0; c < 64; c++) {
            const float4* ev = (const float4*)(esh + c * 64);
            float dot = 0.f;
#pragma unroll
            for (int i = 0; i < 16; i++) {
                float4 e = ev[i];
                dot = fmaf(f[4 * i], e.x, dot);
                dot = fmaf(f[4 * i + 1], e.y, dot);
                dot = fmaf(f[4 * i + 2], e.z, dot);
                dot = fmaf(f[4 * i + 3], e.w, dot);
            }
            float sc = fn - 2.f * dot + en[c];
            if (sc < best) { best = sc; bidx = cb + c; }
        }
    }

    idxf[row] = (float)bidx;
    const float4* ep = (const float4*)(emb + (size_t)bidx * 64);
    float4* qp = (float4*)(zq + (size_t)row * 64);
#pragma unroll
    for (int i = 0; i < 16; i++) qp[i] = ep[i];
}

// ---------------------------------------------------------------------------
extern "C" void kernel_launch(void* const* d_in, const int* in_sizes, int n_in,
                              void* d_out, int out_size) {
    (void)in_sizes; (void)n_in;
    const float* x   = (const float*)d_in[0];
    const float* w1  = (const float*)d_in[1];
    const float* b1  = (const float*)d_in[2];
    const float* w2  = (const float*)d_in[3];
    const float* b2  = (const float*)d_in[4];
    const float* w3  = (const float*)d_in[5];
    const float* b3  = (const float*)d_in[6];
    const float* d1w = (const float*)d_in[7];
    const float* d1b = (const float*)d_in[8];
    const float* d2w = (const float*)d_in[9];
    const float* d2b = (const float*)d_in[10];
    const float* d3w = (const float*)d_in[11];
    const float* d3b = (const float*)d_in[12];
    const float* emb = (const float*)d_in[13];

    float *h1, *h2, *g1, *g2, *ze, *zq, *idxf, *wt1;
    float2 *w2s, *w3s, *d2s, *d1s;
    cudaGetSymbolAddress((void**)&h1, g_h1);
    cudaGetSymbolAddress((void**)&h2, g_h2);
    cudaGetSymbolAddress((void**)&g1, g_g1);
    cudaGetSymbolAddress((void**)&g2, g_g2);
    cudaGetSymbolAddress((void**)&ze, g_ze);
    cudaGetSymbolAddress((void**)&zq, g_zq);
    cudaGetSymbolAddress((void**)&idxf, g_if);
    cudaGetSymbolAddress((void**)&wt1, g_wt1);
    cudaGetSymbolAddress((void**)&w2s, g_w2s);
    cudaGetSymbolAddress((void**)&w3s, g_w3s);
    cudaGetSymbolAddress((void**)&d2s, g_d2s);
    cudaGetSymbolAddress((void**)&d1s, g_d1s);

    float* outF = (float*)d_out;
    const int NX = NBATCH * 3 * 256 * 256;
    const int NZ = NBATCH * 64 * 32 * 32;
    const int NI = 16384;
    if (out_size >= NX + 2 * NZ + NI) {
        ze   = outF + NX;
        zq   = outF + NX + NZ;
        idxf = outF + NX + 2 * NZ;
    }

    static bool attr_done = false;
    if (!attr_done) {
        cudaFuncSetAttribute(conv2_mma, cudaFuncAttributeMaxDynamicSharedMemorySize,
                             C2_SMEM);
        cudaFuncSetAttribute(conv3_mma, cudaFuncAttributeMaxDynamicSharedMemorySize,
                             C3_SMEM);
        cudaFuncSetAttribute(dconv_mma<64, 32>, cudaFuncAttributeMaxDynamicSharedMemorySize,
                             DCONV_SMEM(32));
        cudaFuncSetAttribute(dconv_mma<256, 64>, cudaFuncAttributeMaxDynamicSharedMemorySize,
                             DCONV_SMEM(64));
        attr_done = true;
    }

    wsplit2t<<<2048, 256>>>(w2, w2s);
    wtrans<<<(128 * 3 * 16 + 255) / 256, 256>>>(w1, wt1, 128, 3);
    conv4s2<3, true><<<dim3(64, 2, NBATCH), 256>>>(x, wt1, b1, h1, 128, 256, 256, 128, 128, 8);
    conv2_mma<<<dim3(32, 2, NBATCH), 256, C2_SMEM>>>(h1, w2s, b2, h2);
    wsplit3<<<1024, 256>>>(w3, w3s);
    conv3_mma<<<dim3(4, 1, NBATCH * 4), 256, C3_SMEM>>>(h2, w3s, g2);
    addparts<<<NZ / 256, 256>>>(g2, b3, ze);
    vqk<<<128, 128>>>(ze, emb, zq, idxf);
    wsplitD1<<<1024, 256>>>(d1w, d1s);
    dconv_mma<64, 32><<<dim3(16, 4, NBATCH * 2), 256, DCONV_SMEM(32)>>>(zq, d1s, d1b, g1, 256, 2);
    wsplitD2<<<2048, 256>>>(d2w, d2s);
    dconv_mma<256, 64><<<dim3(32, 4, NBATCH), 256, DCONV_SMEM(64)>>>(g1, d2s, d2b, g2, 128, 1);
    dconv3out<<<dim3(64, NBATCH), 128>>>(g2, d3w, d3b, outF, 8);
}

// round 10
// speedup vs baseline: 1.2363x; 1.0719x over previous
#include <cuda_runtime.h>

// ---------------------------------------------------------------------------
// VQ-VAE forward, sm_100a.  (R9 + cp.async pipelining for conv3 weights and
// dconv input+weights.)
//   Encoder conv2/conv3: mma.sync tf32 3-term hi/lo split (argmin-safe).
//   Decoder dconv1/dconv2: mma.sync tf32 1-term.
//   conv1 / dconv3 / VQ: scalar-FFMA register-tiled.
// Output layout: [x_recon | z_e | z_q | idx(as float)], fp32.
// ---------------------------------------------------------------------------

#define NBATCH 16

// -------- scratch ------------------------------------------------------------
__device__ float g_h1[NBATCH * 128 * 128 * 128];
__device__ float g_h2[NBATCH * 256 * 64 * 64];
__device__ float g_g1[NBATCH * 256 * 64 * 64];
__device__ float g_g2[NBATCH * 128 * 128 * 128];
__device__ float g_ze[NBATCH * 64 * 32 * 32];
__device__ float g_zq[NBATCH * 64 * 32 * 32];
__device__ float g_if[16384];
__device__ float g_wt1[128 * 3 * 16];
__device__ float2 g_w2s[16 * 128 * 256];   // conv2  [t][ic][oc] (hi,lo)
__device__ float2 g_w3s[16 * 256 * 64];    // conv3  [t][ic][oc] (hi,lo)
__device__ float2 g_d2s[16 * 256 * 128];   // dconv2 [t][ic][oc] (hi,lo)
__device__ float2 g_d1s[16 * 64 * 256];    // dconv1 [t][ic][oc] (hi,lo)

// -------- helpers ------------------------------------------------------------
__device__ __forceinline__ void tf32split(float v, unsigned& hi, unsigned& lo) {
    unsigned h;
    asm("cvt.rna.tf32.f32 %0,%1;" : "=r"(h) : "f"(v));
    float l = v - __uint_as_float(h);
    unsigned lw;
    asm("cvt.rna.tf32.f32 %0,%1;" : "=r"(lw) : "f"(l));
    hi = h; lo = lw;
}
__device__ __forceinline__ unsigned tf32cvt(float v) {
    unsigned h;
    asm("cvt.rna.tf32.f32 %0,%1;" : "=r"(h) : "f"(v));
    return h;
}
__device__ __forceinline__ float2 splitpack(float v) {
    unsigned h, l;
    tf32split(v, h, l);
    return make_float2(__uint_as_float(h), __uint_as_float(l));
}
__device__ __forceinline__ void mma8(float* c, const unsigned* a,
                                     unsigned b0, unsigned b1) {
    asm("mma.sync.aligned.m16n8k8.row.col.f32.tf32.tf32.f32 "
        "{%0,%1,%2,%3},{%4,%5,%6,%7},{%8,%9},{%0,%1,%2,%3};"
        : "+f"(c[0]), "+f"(c[1]), "+f"(c[2]), "+f"(c[3])
        : "r"(a[0]), "r"(a[1]), "r"(a[2]), "r"(a[3]), "r"(b0), "r"(b1));
}
__device__ __forceinline__ void cp_async8(unsigned dst, const void* src) {
    asm volatile("cp.async.ca.shared.global [%0], [%1], 8;\n"
                 :: "r"(dst), "l"(src));
}
// 4-byte cp.async with zero-fill when pred==0 (CUTLASS ZFILL idiom)
__device__ __forceinline__ void cp_async4_z(unsigned dst, const void* src, bool pred) {
    int sz = pred ? 4 : 0;
    asm volatile("cp.async.ca.shared.global [%0], [%1], 4, %2;\n"
                 :: "r"(dst), "l"(src), "r"(sz));
}
__device__ __forceinline__ void cp_commit() {
    asm volatile("cp.async.commit_group;\n");
}
template <int N>
__device__ __forceinline__ void cp_wait() {
    asm volatile("cp.async.wait_group %0;\n" :: "n"(N));
}

// -------- weight transforms --------------------------------------------------
__global__ void wtrans(const float* __restrict__ w, float* __restrict__ wo,
                       int Cout, int Cin) {   // OIHW -> [ic][oc][t]
    int idx = blockIdx.x * 256 + threadIdx.x;
    int total = Cout * Cin * 16;
    if (idx < total) {
        int t = idx & 15;
        int rest = idx >> 4;
        int ic = rest % Cin;
        int oc = rest / Cin;
        wo[(ic * Cout + oc) * 16 + t] = w[idx];
    }
}
__global__ void wsplit2t(const float* __restrict__ w, float2* __restrict__ wo) {
    int idx = blockIdx.x * 256 + threadIdx.x;   // 524288
    int t = idx & 15, ic = (idx >> 4) & 127, oc = idx >> 11;
    wo[(t * 128 + ic) * 256 + oc] = splitpack(w[idx]);
}
__global__ void wsplit3(const float* __restrict__ w, float2* __restrict__ wo) {
    int idx = blockIdx.x * 256 + threadIdx.x;   // 262144
    int t = idx & 15, ic = (idx >> 4) & 255, oc = idx >> 12;
    wo[(t * 256 + ic) * 64 + oc] = splitpack(w[idx]);
}
__global__ void wsplitD2(const float* __restrict__ w, float2* __restrict__ wo) {
    int idx = blockIdx.x * 256 + threadIdx.x;   // 524288
    int t = idx & 15, oc = (idx >> 4) & 127, ic = idx >> 11;
    wo[(t * 256 + ic) * 128 + oc] = splitpack(w[idx]);
}
__global__ void wsplitD1(const float* __restrict__ w, float2* __restrict__ wo) {
    int idx = blockIdx.x * 256 + threadIdx.x;   // 262144
    int t = idx & 15, oc = (idx >> 4) & 255, ic = idx >> 12;
    wo[(t * 64 + ic) * 256 + oc] = splitpack(w[idx]);
}

// ============================================================================
// conv2 MMA (3-term): h1 -> h2, k4 s2 p1, relu.  (R9, unchanged)
// ============================================================================
#define C2_WS2 (4 * 8 * 132)
#define C2_INS (8 * 6 * 132)
#define C2_SMEM ((4 * C2_WS2 + C2_INS) * 4)
__global__ __launch_bounds__(256, 2)
void conv2_mma(const float* __restrict__ in, const float2* __restrict__ wt,
               const float* __restrict__ bias, float* __restrict__ out) {
    extern __shared__ float sm[];
    float2* ws0 = (float2*)sm;
    float* ins = sm + 4 * C2_WS2;
    unsigned ws_base = (unsigned)__cvta_generic_to_shared(ws0);

    const int oy0 = blockIdx.x * 2;
    const int ocb = blockIdx.y * 128;
    const int b   = blockIdx.z;

    const int tid  = threadIdx.x;
    const int wid  = tid >> 5;
    const int lane = tid & 31;
    const int wm   = wid >> 2;
    const int wn   = wid & 3;
    const int oyl  = wn >> 1;
    const int xb   = (wn & 1) * 32;
    const int lq   = lane >> 2;
    const int lr   = lane & 3;

    float acc[4][4][4];
#pragma unroll
    for (int mt = 0; mt < 4; mt++)
#pragma unroll
        for (int nt = 0; nt < 4; nt++)
#pragma unroll
            for (int i = 0; i < 4; i++) acc[mt][nt][i] = 0.f;

    const int iy0 = oy0 * 2 - 1;
    const float* inB = in + ((size_t)b * 128) * 128 * 128;

    auto stage_w = [&](int c, int buf) {
        const int tg = c & 3, ch = c >> 2;
#pragma unroll
        for (int i = 0; i < 16; i++) {
            int idx = tid + i * 256;
            int oc = idx & 127, icl = (idx >> 7) & 7, tl = idx >> 10;
            const float2* src =
                wt + ((size_t)((tg * 4 + tl) * 128 + ch * 8 + icl)) * 256 + ocb + oc;
            unsigned dst = ws_base + (unsigned)(buf * C2_WS2 + (tl * 8 + icl) * 132 + oc) * 8u;
            cp_async8(dst, src);
        }
        cp_commit();
    };

    stage_w(0, 0);
    for (int c = 0; c < 64; c++) {
        const int ch = c >> 2, tg = c & 3;
        if (tg == 0) {
            for (int idx = tid; idx < 8 * 6 * 132; idx += 256) {
                int icl = idx / 792;
                int rem = idx - icl * 792;
                int r = rem / 132, cc = rem - r * 132;
                int iy = iy0 + r, ix = cc - 1;
                float v = 0.f;
                if ((unsigned)iy < 128u && (unsigned)ix < 128u)
                    v = inB[((size_t)(ch * 8 + icl) * 128 + iy) * 128 + ix];
                ins[idx] = v;
            }
        }
        if (c < 63) { stage_w(c + 1, (c + 1) & 1); cp_wait<1>(); }
        else cp_wait<0>();
        __syncthreads();

        const float2* ws = ws0 + (c & 1) * C2_WS2;
#pragma unroll
        for (int tapl = 0; tapl < 4; tapl++) {
            const int ky = tg, kx = tapl;
            unsigned ahi[4][4], alo[4][4];
#pragma unroll
            for (int mt = 0; mt < 4; mt++) {
                const float2* ap = &ws[(tapl * 8 + lr) * 132 + wm * 64 + mt * 16 + lq];
                float2 p0 = ap[0], p1 = ap[8], p2 = ap[4 * 132], p3 = ap[4 * 132 + 8];
                ahi[mt][0] = __float_as_uint(p0.x); alo[mt][0] = __float_as_uint(p0.y);
                ahi[mt][1] = __float_as_uint(p1.x); alo[mt][1] = __float_as_uint(p1.y);
                ahi[mt][2] = __float_as_uint(p2.x); alo[mt][2] = __float_as_uint(p2.y);
                ahi[mt][3] = __float_as_uint(p3.x); alo[mt][3] = __float_as_uint(p3.y);
            }
#pragma unroll
            for (int nt = 0; nt < 4; nt++) {
                const int ox = xb + nt * 8 + lq;
                const float* bp = &ins[lr * 792 + (2 * oyl + ky) * 132 + 2 * ox + kx];
                float rb0 = bp[0], rb1 = bp[4 * 792];
                unsigned bh0, bl0, bh1, bl1;
                tf32split(rb0, bh0, bl0);
                tf32split(rb1, bh1, bl1);
#pragma unroll
                for (int mt = 0; mt < 4; mt++) {
                    mma8(acc[mt][nt], ahi[mt], bh0, bh1);
                    mma8(acc[mt][nt], ahi[mt], bl0, bl1);
                    mma8(acc[mt][nt], alo[mt], bh0, bh1);
                }
            }
        }
        __syncthreads();
    }

    const int oy = oy0 + oyl;
#pragma unroll
    for (int mt = 0; mt < 4; mt++) {
        const int oc = ocb + wm * 64 + mt * 16 + lq;
        const float b0v = bias[oc], b1v = bias[oc + 8];
#pragma unroll
        for (int nt = 0; nt < 4; nt++) {
            const int ox = xb + nt * 8 + 2 * lr;
            float* o0 = out + (((size_t)b * 256 + oc) * 64 + oy) * 64 + ox;
            float* o1 = o0 + (size_t)8 * 64 * 64;
            *(float2*)o0 = make_float2(fmaxf(acc[mt][nt][0] + b0v, 0.f),
                                       fmaxf(acc[mt][nt][1] + b0v, 0.f));
            *(float2*)o1 = make_float2(fmaxf(acc[mt][nt][2] + b1v, 0.f),
                                       fmaxf(acc[mt][nt][3] + b1v, 0.f));
        }
    }
}

// ============================================================================
// conv3 MMA (3-term): h2 -> 4 K-slab partials.  Weights cp.async ping-pong.
// ============================================================================
#define C3_WS2 (4 * 8 * 68)
#define C3_INS (8 * 18 * 68)
#define C3_SMEM ((4 * C3_WS2 + C3_INS) * 4)
__global__ __launch_bounds__(256, 2)
void conv3_mma(const float* __restrict__ in, const float2* __restrict__ wt,
               float* __restrict__ outp) {
    extern __shared__ float sm[];
    float2* ws0 = (float2*)sm;
    float* ins = sm + 4 * C3_WS2;
    unsigned ws_base = (unsigned)__cvta_generic_to_shared(ws0);

    const int r0   = blockIdx.x * 8;
    const int b    = blockIdx.z >> 2;
    const int slab = blockIdx.z & 3;

    const int tid  = threadIdx.x;
    const int w    = tid >> 5;
    const int lane = tid & 31;
    const int lq   = lane >> 2;
    const int lr   = lane & 3;

    float acc[4][4][4];
#pragma unroll
    for (int mt = 0; mt < 4; mt++)
#pragma unroll
        for (int nt = 0; nt < 4; nt++)
#pragma unroll
            for (int i = 0; i < 4; i++) acc[mt][nt][i] = 0.f;

    const int iy0 = r0 * 2 - 1;
    const float* inB = in + ((size_t)b * 256 + slab * 64) * 64 * 64;

    auto stage_w = [&](int c, int buf) {
        const int tg = c & 3, ch = c >> 2;
#pragma unroll
        for (int i = 0; i < 8; i++) {
            int idx = tid + i * 256;
            int oc = idx & 63, icl = (idx >> 6) & 7, tl = idx >> 9;
            const float2* src =
                wt + ((size_t)((tg * 4 + tl) * 256 + slab * 64 + ch * 8 + icl)) * 64 + oc;
            unsigned dst = ws_base + (unsigned)(buf * C3_WS2 + (tl * 8 + icl) * 68 + oc) * 8u;
            cp_async8(dst, src);
        }
        cp_commit();
    };

    stage_w(0, 0);
    for (int c = 0; c < 32; c++) {
        const int ch = c >> 2, tg = c & 3;
        if (tg == 0) {
            for (int idx = tid; idx < 8 * 18 * 66; idx += 256) {
                int icl = idx / 1188;
                int rem = idx - icl * 1188;
                int r = rem / 66, cc = rem - r * 66;
                int iy = iy0 + r, ix = cc - 1;
                float v = 0.f;
                if ((unsigned)iy < 64u && (unsigned)ix < 64u)
                    v = inB[((size_t)(ch * 8 + icl) * 64 + iy) * 64 + ix];
                ins[icl * 1224 + r * 68 + cc] = v;
            }
        }
        if (c < 31) { stage_w(c + 1, (c + 1) & 1); cp_wait<1>(); }
        else cp_wait<0>();
        __syncthreads();

        const float2* ws = ws0 + (c & 1) * C3_WS2;
#pragma unroll
        for (int tapl = 0; tapl < 4; tapl++) {
            const int ky = tg, kx = tapl;
            unsigned ahi[4][4], alo[4][4];
#pragma unroll
            for (int mt = 0; mt < 4; mt++) {
                const float2* ap = &ws[(tapl * 8 + lr) * 68 + mt * 16 + lq];
                float2 p0 = ap[0], p1 = ap[8], p2 = ap[4 * 68], p3 = ap[4 * 68 + 8];
                ahi[mt][0] = __float_as_uint(p0.x); alo[mt][0] = __float_as_uint(p0.y);
                ahi[mt][1] = __float_as_uint(p1.x); alo[mt][1] = __float_as_uint(p1.y);
                ahi[mt][2] = __float_as_uint(p2.x); alo[mt][2] = __float_as_uint(p2.y);
                ahi[mt][3] = __float_as_uint(p3.x); alo[mt][3] = __float_as_uint(p3.y);
            }
#pragma unroll
            for (int nt = 0; nt < 4; nt++) {
                const int col = nt * 8 + lq;
                const float* bp = &ins[lr * 1224 + (2 * w + ky) * 68 + 2 * col + kx];
                float rb0 = bp[0], rb1 = bp[4 * 1224];
                unsigned bh0, bl0, bh1, bl1;
                tf32split(rb0, bh0, bl0);
                tf32split(rb1, bh1, bl1);
#pragma unroll
                for (int mt = 0; mt < 4; mt++) {
                    mma8(acc[mt][nt], ahi[mt], bh0, bh1);
                    mma8(acc[mt][nt], ahi[mt], bl0, bl1);
                    mma8(acc[mt][nt], alo[mt], bh0, bh1);
                }
            }
        }
        __syncthreads();
    }

    const int NZ = NBATCH * 64 * 32 * 32;
    float* part = outp + (size_t)slab * NZ;
    const int row = r0 + w;
#pragma unroll
    for (int mt = 0; mt < 4; mt++) {
        const int oc = mt * 16 + lq;
#pragma unroll
        for (int nt = 0; nt < 4; nt++) {
            float* o0 = part + (((size_t)b * 64 + oc) * 32 + row) * 32 + nt * 8 + 2 * lr;
            float* o1 = o0 + (size_t)8 * 32 * 32;
            *(float2*)o0 = make_float2(acc[mt][nt][0], acc[mt][nt][1]);
            *(float2*)o1 = make_float2(acc[mt][nt][2], acc[mt][nt][3]);
        }
    }
}

__global__ void addparts(const float* __restrict__ p, const float* __restrict__ bias,
                         float* __restrict__ ze) {
    const int S = NBATCH * 64 * 32 * 32;
    int i = blockIdx.x * 256 + threadIdx.x;
    float v = p[i] + p[i + S] + p[i + 2 * S] + p[i + 3 * S];
    ze[i] = v + bias[(i >> 10) & 63];
}

// ============================================================================
// dconv MMA (1-term tf32): weights AND input double-buffered via cp.async
// (one commit group per chunk; wait_group 1 -> chunk ch's group complete).
// ============================================================================
#define D_WS2 (4 * 8 * 132)
template <int CIN, int HIN>
__global__ __launch_bounds__(256, 2)
void dconv_mma(const float* __restrict__ in, const float2* __restrict__ wt,
               const float* __restrict__ bias, float* __restrict__ out,
               int Cout, int nOcb) {
    const int WROW = HIN + 2;
    const int ISTR = HIN + 4;
    const int IBUF = 8 * 3 * ISTR;
    extern __shared__ float sm[];
    float2* ws0 = (float2*)sm;            // [2][D_WS2]
    float* ins0 = sm + 4 * D_WS2;         // [2][IBUF]
    unsigned ws_base = (unsigned)__cvta_generic_to_shared(ws0);
    unsigned in_base = (unsigned)__cvta_generic_to_shared(ins0);

    const int y0 = blockIdx.x * 2;
    const int py = blockIdx.y >> 1, px = blockIdx.y & 1;
    const int b   = blockIdx.z / nOcb;
    const int ocb = (blockIdx.z % nOcb) * 128;

    const int tid  = threadIdx.x;
    const int wid  = tid >> 5;
    const int lane = tid & 31;
    const int wm   = wid >> 2;
    const int wn   = wid & 3;
    const int yl   = wn >> 1;
    const int xb   = (wn & 1) * (HIN / 2);
    const int lq   = lane >> 2;
    const int lr   = lane & 3;
    const int NT   = HIN / 16;
    const int NCH  = CIN / 8;

    float acc[4][4][4];
#pragma unroll
    for (int mt = 0; mt < 4; mt++)
#pragma unroll
        for (int nt = 0; nt < 4; nt++)
#pragma unroll
            for (int i = 0; i < 4; i++) acc[mt][nt][i] = 0.f;

    const float* inB = in + ((size_t)b * CIN) * HIN * HIN;

    // stage chunk ch (input + weights) into buffer buf; ONE commit.
    auto stage = [&](int ch, int buf) {
        for (int idx = tid; idx < 8 * 3 * WROW; idx += 256) {
            int icl = idx / (3 * WROW);
            int rem = idx - icl * 3 * WROW;
            int r = rem / WROW, s = rem - r * WROW;
            int iy = y0 + py - 1 + r;
            int ix = px - 1 + s;
            bool ok = (unsigned)iy < (unsigned)HIN && (unsigned)ix < (unsigned)HIN;
            const float* src = inB + ((size_t)(ch * 8 + icl) * HIN + iy) * HIN + ix;
            unsigned dst = in_base + (unsigned)(buf * IBUF + (icl * 3 + r) * ISTR + s) * 4u;
            cp_async4_z(dst, src, ok);
        }
#pragma unroll
        for (int i = 0; i < 16; i++) {
            int idx = tid + i * 256;
            int oc = idx & 127, icl = (idx >> 7) & 7, tl = idx >> 10;
            int a = tl >> 1, c2 = tl & 1;
            int t = (1 - py + 2 * a) * 4 + (1 - px + 2 * c2);
            const float2* src =
                wt + ((size_t)(t * CIN + ch * 8 + icl)) * Cout + ocb + oc;
            unsigned dst = ws_base + (unsigned)(buf * D_WS2 + (tl * 8 + icl) * 132 + oc) * 8u;
            cp_async8(dst, src);
        }
        cp_commit();
    };

    stage(0, 0);
    for (int ch = 0; ch < NCH; ch++) {
        if (ch + 1 < NCH) { stage(ch + 1, (ch + 1) & 1); cp_wait<1>(); }
        else cp_wait<0>();
        __syncthreads();

        const float2* ws = ws0 + (ch & 1) * D_WS2;
        const float* ins = ins0 + (ch & 1) * IBUF;
#pragma unroll
        for (int tl = 0; tl < 4; tl++) {
            const int a = tl >> 1, c = tl & 1;
            unsigned ahi[4][4];
#pragma unroll
            for (int mt = 0; mt < 4; mt++) {
                const float2* ap = &ws[(tl * 8 + lr) * 132 + wm * 64 + mt * 16 + lq];
                ahi[mt][0] = __float_as_uint(ap[0].x);
                ahi[mt][1] = __float_as_uint(ap[8].x);
                ahi[mt][2] = __float_as_uint(ap[4 * 132].x);
                ahi[mt][3] = __float_as_uint(ap[4 * 132 + 8].x);
            }
#pragma unroll
            for (int nt = 0; nt < NT; nt++) {
                const int x = xb + nt * 8 + lq;
                const float* bp = &ins[(lr * 3 + (yl + 1 - a)) * ISTR + x + 1 - c];
                unsigned bh0 = tf32cvt(bp[0]), bh1 = tf32cvt(bp[4 * 3 * ISTR]);
#pragma unroll
                for (int mt = 0; mt < 4; mt++)
                    mma8(acc[mt][nt], ahi[mt], bh0, bh1);
            }
        }
        __syncthreads();
    }

    const int HOUT = 2 * HIN;
    const int oy = 2 * (y0 + yl) + py;
#pragma unroll
    for (int mt = 0; mt < 4; mt++) {
        const int oc = ocb + wm * 64 + mt * 16 + lq;
        const float b0v = bias[oc], b1v = bias[oc + 8];
#pragma unroll
        for (int nt = 0; nt < NT; nt++) {
            const int x = xb + nt * 8 + 2 * lr;
            const int ox = 2 * x + px;
            float* o0 = out + (((size_t)b * Cout + oc) * HOUT + oy) * HOUT + ox;
            float* o1 = o0 + (size_t)8 * HOUT * HOUT;
            o0[0] = fmaxf(acc[mt][nt][0] + b0v, 0.f);
            o0[2] = fmaxf(acc[mt][nt][1] + b0v, 0.f);
            o1[0] = fmaxf(acc[mt][nt][2] + b1v, 0.f);
            o1[2] = fmaxf(acc[mt][nt][3] + b1v, 0.f);
        }
    }
}
#define DCONV_SMEM(HIN) ((4 * D_WS2 + 2 * 8 * 3 * ((HIN) + 4)) * 4)

// ============================================================================
// Scalar kernels: conv1, dconv3out, vqk.  (unchanged)
// ============================================================================
template <int CIN, bool RELU>
__global__ __launch_bounds__(256, 2)
void conv4s2(const float* __restrict__ in, const float* __restrict__ wt,
             const float* __restrict__ bias, float* __restrict__ out,
             int Cout, int Hin, int Win, int Hout, int Wout, int tilesX) {
    __shared__ float ish[34 * 36];
    __shared__ float wsh[64 * 16];

    const int tile = blockIdx.x;
    const int tx0 = (tile % tilesX) * 16;
    const int ty0 = (tile / tilesX) * 16;
    const int ocb = blockIdx.y * 64;
    const int b   = blockIdx.z;

    const int tid = threadIdx.x;
    const int og  = tid >> 5;
    const int sp  = tid & 31;
    const int r   = sp >> 1;
    const int cb  = (sp & 1) * 8;

    float acc[8][8];
#pragma unroll
    for (int o = 0; o < 8; o++) {
        float bv = bias[ocb + og * 8 + o];
#pragma unroll
        for (int j = 0; j < 8; j++) acc[o][j] = bv;
    }

    const int iy0 = ty0 * 2 - 1, ix0 = tx0 * 2 - 1;
    const float* inB = in + ((size_t)b * CIN) * Hin * Win;

    for (int ic = 0; ic < CIN; ic++) {
        const float* inC = inB + (size_t)ic * Hin * Win;
        for (int idx = tid; idx < 34 * 34; idx += 256) {
            int py = idx / 34, px = idx - py * 34;
            int iy = iy0 + py, ix = ix0 + px;
            float v = 0.f;
            if ((unsigned)iy < (unsigned)Hin && (unsigned)ix < (unsigned)Win)
                v = inC[iy * Win + ix];
            ish[py * 36 + px] = v;
        }
        const float* wC = wt + (ic * Cout + ocb) * 16;
        for (int idx = tid; idx < 1024; idx += 256) wsh[idx] = wC[idx];
        __syncthreads();

#pragma unroll
        for (int ky = 0; ky < 4; ky++) {
            const float* rp = &ish[(2 * r + ky) * 36 + 2 * cb];
            float4 v0 = *(const float4*)(rp);
            float4 v1 = *(const float4*)(rp + 4);
            float4 v2 = *(const float4*)(rp + 8);
            float4 v3 = *(const float4*)(rp + 12);
            float4 v4 = *(const float4*)(rp + 16);
            float riv[20] = {v0.x, v0.y, v0.z, v0.w, v1.x, v1.y, v1.z, v1.w,
                             v2.x, v2.y, v2.z, v2.w, v3.x, v3.y, v3.z, v3.w,
                             v4.x, v4.y, v4.z, v4.w};
#pragma unroll
            for (int kx = 0; kx < 4; kx++) {
                const int t = ky * 4 + kx;
                float wv[8];
#pragma unroll
                for (int o = 0; o < 8; o++) wv[o] = wsh[(og * 8 + o) * 16 + t];
#pragma unroll
                for (int o = 0; o < 8; o++)
#pragma unroll
                    for (int j = 0; j < 8; j++)
                        acc[o][j] = fmaf(wv[o], riv[kx + 2 * j], acc[o][j]);
            }
        }
        __syncthreads();
    }

    const int oy = ty0 + r;
    const int oxb = tx0 + cb;
#pragma unroll
    for (int o = 0; o < 8; o++) {
        float* op = out + (((size_t)b * Cout + ocb + og * 8 + o) * Hout + oy) * Wout + oxb;
        float tmp[8];
#pragma unroll
        for (int j = 0; j < 8; j++)
            tmp[j] = RELU ? fmaxf(acc[o][j], 0.f) : acc[o][j];
        *(float4*)op       = make_float4(tmp[0], tmp[1], tmp[2], tmp[3]);
        *(float4*)(op + 4) = make_float4(tmp[4], tmp[5], tmp[6], tmp[7]);
    }
}

__global__ __launch_bounds__(128, 4)
void dconv3out(const float* __restrict__ in, const float* __restrict__ wt,
               const float* __restrict__ bias, float* __restrict__ out,
               int tilesX) {
    const int Cin = 128, Hin = 128, Win = 128, Hout = 256, Wout = 256;
    __shared__ float ish[4][18 * 19];
    __shared__ float wsh[4][3 * 16];

    const int tile = blockIdx.x;
    const int ox0 = (tile % tilesX) * 32;
    const int oy0 = (tile / tilesX) * 32;
    const int b   = blockIdx.y;

    const int tid = threadIdx.x;
    const int q   = tid >> 5;
    const int py  = q >> 1, px = q & 1;
    const int sp  = tid & 31;
    const int ry  = sp >> 1;
    const int ch  = (sp & 1) * 8;

    float acc[3][8];
#pragma unroll
    for (int o = 0; o < 3; o++) {
        float bv = bias[o];
#pragma unroll
        for (int j = 0; j < 8; j++) acc[o][j] = bv;
    }

    const int iy0 = oy0 >> 1, ix0 = ox0 >> 1;
    const int kp = 1 - py, kq = 1 - px;

    for (int ic0 = 0; ic0 < Cin; ic0 += 4) {
        for (int idx = tid; idx < 4 * 324; idx += 128) {
            int icc = idx / 324, p = idx - icc * 324;
            int piy = p / 18, pix = p - piy * 18;
            int iy = iy0 - 1 + piy, ix = ix0 - 1 + pix;
            float v = 0.f;
            if ((unsigned)iy < (unsigned)Hin && (unsigned)ix < (unsigned)Win)
                v = in[(((size_t)b * Cin + ic0 + icc) * Hin + iy) * Win + ix];
            ish[icc][piy * 19 + pix] = v;
        }
        for (int idx = tid; idx < 4 * 48; idx += 128) {
            int icc = idx / 48, rmd = idx - icc * 48;
            wsh[icc][rmd] = wt[(ic0 + icc) * 48 + rmd];
        }
        __syncthreads();

#pragma unroll
        for (int icc = 0; icc < 4; icc++) {
#pragma unroll
            for (int a = 0; a < 2; a++) {
                const int ky  = kp + 2 * a;
                const int liy = ry + 1 + py - a;
                float iv[10];
                const int base = liy * 19 + ch + px;
#pragma unroll
                for (int j = 0; j < 10; j++) iv[j] = ish[icc][base + j];
#pragma unroll
                for (int c = 0; c < 2; c++) {
                    const int kx  = kq + 2 * c;
                    const int t   = ky * 4 + kx;
                    const int off = 1 - c;
                    float wv[3];
#pragma unroll
                    for (int o = 0; o < 3; o++) wv[o] = wsh[icc][o * 16 + t];
#pragma unroll
                    for (int o = 0; o < 3; o++)
#pragma unroll
                        for (int j = 0; j < 8; j++)
                            acc[o][j] = fmaf(wv[o], iv[j + off], acc[o][j]);
                }
            }
        }
        __syncthreads();
    }

    const int oy = oy0 + 2 * ry + py;
#pragma unroll
    for (int o = 0; o < 3; o++) {
        float* op = out + (((size_t)b * 3 + o) * Hout + oy) * Wout + ox0 + px + 2 * ch;
#pragma unroll
        for (int j = 0; j < 8; j++) op[2 * j] = acc[o][j];
    }
}

__global__ __launch_bounds__(128, 8)
void vqk(const float* __restrict__ ze, const float* __restrict__ emb,
         float* __restrict__ zq, float* __restrict__ idxf) {
    __shared__ __align__(16) float esh[64 * 64];
    __shared__ float en[64];

    const int row = blockIdx.x * 128 + threadIdx.x;
    float f[64];
    const float4* fp = (const float4*)(ze + (size_t)row * 64);
#pragma unroll
    for (int i = 0; i < 16; i++) {
        float4 v = fp[i];
        f[4 * i] = v.x; f[4 * i + 1] = v.y; f[4 * i + 2] = v.z; f[4 * i + 3] = v.w;
    }
    float fn = 0.f;
#pragma unroll
    for (int d = 0; d < 64; d++) fn = fmaf(f[d], f[d], fn);

    float best = 3.4e38f;
    int bidx = 0;
    for (int cb = 0; cb < 512; cb += 64) {
        __syncthreads();
        const float4* src = (const float4*)(emb + (size_t)cb * 64);
        for (int i = threadIdx.x; i < 1024; i += 128)
            ((float4*)esh)[i] = src[i];
        __syncthreads();
        if (threadIdx.x < 64) {
            float s = 0.f;
            const float* e = esh + threadIdx.x * 64;
#pragma unroll
            for (int d = 0; d < 64; d++) s = fmaf(e[d], e[d], s);
            en[threadIdx.x] = s;
        }
        __syncthreads();
        for (int c = 0; c < 64; c++) {
            const float4* ev = (const float4*)(esh + c * 64);
            float dot = 0.f;
#pragma unroll
            for (int i = 0; i < 16; i++) {
                float4 e = ev[i];
                dot = fmaf(f[4 * i], e.x, dot);
                dot = fmaf(f[4 * i + 1], e.y, dot);
                dot = fmaf(f[4 * i + 2], e.z, dot);
                dot = fmaf(f[4 * i + 3], e.w, dot);
            }
            float sc = fn - 2.f * dot + en[c];
            if (sc < best) { best = sc; bidx = cb + c; }
        }
    }

    idxf[row] = (float)bidx;
    const float4* ep = (const float4*)(emb + (size_t)bidx * 64);
    float4* qp = (float4*)(zq + (size_t)row * 64);
#pragma unroll
    for (int i = 0; i < 16; i++) qp[i] = ep[i];
}

// ---------------------------------------------------------------------------
extern "C" void kernel_launch(void* const* d_in, const int* in_sizes, int n_in,
                              void* d_out, int out_size) {
    (void)in_sizes; (void)n_in;
    const float* x   = (const float*)d_in[0];
    const float* w1  = (const float*)d_in[1];
    const float* b1  = (const float*)d_in[2];
    const float* w2  = (const float*)d_in[3];
    const float* b2  = (const float*)d_in[4];
    const float* w3  = (const float*)d_in[5];
    const float* b3  = (const float*)d_in[6];
    const float* d1w = (const float*)d_in[7];
    const float* d1b = (const float*)d_in[8];
    const float* d2w = (const float*)d_in[9];
    const float* d2b = (const float*)d_in[10];
    const float* d3w = (const float*)d_in[11];
    const float* d3b = (const float*)d_in[12];
    const float* emb = (const float*)d_in[13];

    float *h1, *h2, *g1, *g2, *ze, *zq, *idxf, *wt1;
    float2 *w2s, *w3s, *d2s, *d1s;
    cudaGetSymbolAddress((void**)&h1, g_h1);
    cudaGetSymbolAddress((void**)&h2, g_h2);
    cudaGetSymbolAddress((void**)&g1, g_g1);
    cudaGetSymbolAddress((void**)&g2, g_g2);
    cudaGetSymbolAddress((void**)&ze, g_ze);
    cudaGetSymbolAddress((void**)&zq, g_zq);
    cudaGetSymbolAddress((void**)&idxf, g_if);
    cudaGetSymbolAddress((void**)&wt1, g_wt1);
    cudaGetSymbolAddress((void**)&w2s, g_w2s);
    cudaGetSymbolAddress((void**)&w3s, g_w3s);
    cudaGetSymbolAddress((void**)&d2s, g_d2s);
    cudaGetSymbolAddress((void**)&d1s, g_d1s);

    float* outF = (float*)d_out;
    const int NX = NBATCH * 3 * 256 * 256;
    const int NZ = NBATCH * 64 * 32 * 32;
    const int NI = 16384;
    if (out_size >= NX + 2 * NZ + NI) {
        ze   = outF + NX;
        zq   = outF + NX + NZ;
        idxf = outF + NX + 2 * NZ;
    }

    static bool attr_done = false;
    if (!attr_done) {
        cudaFuncSetAttribute(conv2_mma, cudaFuncAttributeMaxDynamicSharedMemorySize,
                             C2_SMEM);
        cudaFuncSetAttribute(conv3_mma, cudaFuncAttributeMaxDynamicSharedMemorySize,
                             C3_SMEM);
        cudaFuncSetAttribute(dconv_mma<64, 32>, cudaFuncAttributeMaxDynamicSharedMemorySize,
                             DCONV_SMEM(32));
        cudaFuncSetAttribute(dconv_mma<256, 64>, cudaFuncAttributeMaxDynamicSharedMemorySize,
                             DCONV_SMEM(64));
        attr_done = true;
    }

    wsplit2t<<<2048, 256>>>(w2, w2s);
    wtrans<<<(128 * 3 * 16 + 255) / 256, 256>>>(w1, wt1, 128, 3);
    conv4s2<3, true><<<dim3(64, 2, NBATCH), 256>>>(x, wt1, b1, h1, 128, 256, 256, 128, 128, 8);
    conv2_mma<<<dim3(32, 2, NBATCH), 256, C2_SMEM>>>(h1, w2s, b2, h2);
    wsplit3<<<1024, 256>>>(w3, w3s);
    conv3_mma<<<dim3(4, 1, NBATCH * 4), 256, C3_SMEM>>>(h2, w3s, g2);
    addparts<<<NZ / 256, 256>>>(g2, b3, ze);
    vqk<<<128, 128>>>(ze, emb, zq, idxf);
    wsplitD1<<<1024, 256>>>(d1w, d1s);
    dconv_mma<64, 32><<<dim3(16, 4, NBATCH * 2), 256, DCONV_SMEM(32)>>>(zq, d1s, d1b, g1, 256, 2);
    wsplitD2<<<2048, 256>>>(d2w, d2s);
    dconv_mma<256, 64><<<dim3(32, 4, NBATCH), 256, DCONV_SMEM(64)>>>(g1, d2s, d2b, g2, 128, 1);
    dconv3out<<<dim3(64, NBATCH), 128>>>(g2, d3w, d3b, outF, 8);
}

// round 11
// speedup vs baseline: 1.2761x; 1.0322x over previous
#include <cuda_runtime.h>

// ---------------------------------------------------------------------------
// VQ-VAE forward, sm_100a.  (R10 + conv3 input double-buffer + conv2 async
// input staging.)
//   Encoder conv2/conv3: mma.sync tf32 3-term hi/lo split (argmin-safe).
//   Decoder dconv1/dconv2: mma.sync tf32 1-term.
//   All MMA layers: cp.async pipelined staging.
//   conv1 / dconv3 / VQ: scalar-FFMA register-tiled.
// Output layout: [x_recon | z_e | z_q | idx(as float)], fp32.
// ---------------------------------------------------------------------------

#define NBATCH 16

// -------- scratch ------------------------------------------------------------
__device__ float g_h1[NBATCH * 128 * 128 * 128];
__device__ float g_h2[NBATCH * 256 * 64 * 64];
__device__ float g_g1[NBATCH * 256 * 64 * 64];
__device__ float g_g2[NBATCH * 128 * 128 * 128];
__device__ float g_ze[NBATCH * 64 * 32 * 32];
__device__ float g_zq[NBATCH * 64 * 32 * 32];
__device__ float g_if[16384];
__device__ float g_wt1[128 * 3 * 16];
__device__ float2 g_w2s[16 * 128 * 256];   // conv2  [t][ic][oc] (hi,lo)
__device__ float2 g_w3s[16 * 256 * 64];    // conv3  [t][ic][oc] (hi,lo)
__device__ float2 g_d2s[16 * 256 * 128];   // dconv2 [t][ic][oc] (hi,lo)
__device__ float2 g_d1s[16 * 64 * 256];    // dconv1 [t][ic][oc] (hi,lo)

// -------- helpers ------------------------------------------------------------
__device__ __forceinline__ void tf32split(float v, unsigned& hi, unsigned& lo) {
    unsigned h;
    asm("cvt.rna.tf32.f32 %0,%1;" : "=r"(h) : "f"(v));
    float l = v - __uint_as_float(h);
    unsigned lw;
    asm("cvt.rna.tf32.f32 %0,%1;" : "=r"(lw) : "f"(l));
    hi = h; lo = lw;
}
__device__ __forceinline__ unsigned tf32cvt(float v) {
    unsigned h;
    asm("cvt.rna.tf32.f32 %0,%1;" : "=r"(h) : "f"(v));
    return h;
}
__device__ __forceinline__ float2 splitpack(float v) {
    unsigned h, l;
    tf32split(v, h, l);
    return make_float2(__uint_as_float(h), __uint_as_float(l));
}
__device__ __forceinline__ void mma8(float* c, const unsigned* a,
                                     unsigned b0, unsigned b1) {
    asm("mma.sync.aligned.m16n8k8.row.col.f32.tf32.tf32.f32 "
        "{%0,%1,%2,%3},{%4,%5,%6,%7},{%8,%9},{%0,%1,%2,%3};"
        : "+f"(c[0]), "+f"(c[1]), "+f"(c[2]), "+f"(c[3])
        : "r"(a[0]), "r"(a[1]), "r"(a[2]), "r"(a[3]), "r"(b0), "r"(b1));
}
__device__ __forceinline__ void cp_async8(unsigned dst, const void* src) {
    asm volatile("cp.async.ca.shared.global [%0], [%1], 8;\n"
                 :: "r"(dst), "l"(src));
}
__device__ __forceinline__ void cp_async4_z(unsigned dst, const void* src, bool pred) {
    int sz = pred ? 4 : 0;
    asm volatile("cp.async.ca.shared.global [%0], [%1], 4, %2;\n"
                 :: "r"(dst), "l"(src), "r"(sz));
}
__device__ __forceinline__ void cp_commit() {
    asm volatile("cp.async.commit_group;\n");
}
template <int N>
__device__ __forceinline__ void cp_wait() {
    asm volatile("cp.async.wait_group %0;\n" :: "n"(N));
}

// -------- weight transforms --------------------------------------------------
__global__ void wtrans(const float* __restrict__ w, float* __restrict__ wo,
                       int Cout, int Cin) {   // OIHW -> [ic][oc][t]
    int idx = blockIdx.x * 256 + threadIdx.x;
    int total = Cout * Cin * 16;
    if (idx < total) {
        int t = idx & 15;
        int rest = idx >> 4;
        int ic = rest % Cin;
        int oc = rest / Cin;
        wo[(ic * Cout + oc) * 16 + t] = w[idx];
    }
}
__global__ void wsplit2t(const float* __restrict__ w, float2* __restrict__ wo) {
    int idx = blockIdx.x * 256 + threadIdx.x;   // 524288
    int t = idx & 15, ic = (idx >> 4) & 127, oc = idx >> 11;
    wo[(t * 128 + ic) * 256 + oc] = splitpack(w[idx]);
}
__global__ void wsplit3(const float* __restrict__ w, float2* __restrict__ wo) {
    int idx = blockIdx.x * 256 + threadIdx.x;   // 262144
    int t = idx & 15, ic = (idx >> 4) & 255, oc = idx >> 12;
    wo[(t * 256 + ic) * 64 + oc] = splitpack(w[idx]);
}
__global__ void wsplitD2(const float* __restrict__ w, float2* __restrict__ wo) {
    int idx = blockIdx.x * 256 + threadIdx.x;   // 524288
    int t = idx & 15, oc = (idx >> 4) & 127, ic = idx >> 11;
    wo[(t * 256 + ic) * 128 + oc] = splitpack(w[idx]);
}
__global__ void wsplitD1(const float* __restrict__ w, float2* __restrict__ wo) {
    int idx = blockIdx.x * 256 + threadIdx.x;   // 262144
    int t = idx & 15, oc = (idx >> 4) & 255, ic = idx >> 12;
    wo[(t * 64 + ic) * 256 + oc] = splitpack(w[idx]);
}

// ============================================================================
// conv2 MMA (3-term): h1 -> h2, k4 s2 p1, relu.
// Weights ping-pong cp.async; input staged via cp.async (own group, in-chunk).
// ============================================================================
#define C2_WS2 (4 * 8 * 132)
#define C2_INS (8 * 6 * 132)
#define C2_SMEM ((4 * C2_WS2 + C2_INS) * 4)
__global__ __launch_bounds__(256, 2)
void conv2_mma(const float* __restrict__ in, const float2* __restrict__ wt,
               const float* __restrict__ bias, float* __restrict__ out) {
    extern __shared__ float sm[];
    float2* ws0 = (float2*)sm;
    float* ins = sm + 4 * C2_WS2;
    unsigned ws_base = (unsigned)__cvta_generic_to_shared(ws0);
    unsigned in_base = (unsigned)__cvta_generic_to_shared(ins);

    const int oy0 = blockIdx.x * 2;
    const int ocb = blockIdx.y * 128;
    const int b   = blockIdx.z;

    const int tid  = threadIdx.x;
    const int wid  = tid >> 5;
    const int lane = tid & 31;
    const int wm   = wid >> 2;
    const int wn   = wid & 3;
    const int oyl  = wn >> 1;
    const int xb   = (wn & 1) * 32;
    const int lq   = lane >> 2;
    const int lr   = lane & 3;

    float acc[4][4][4];
#pragma unroll
    for (int mt = 0; mt < 4; mt++)
#pragma unroll
        for (int nt = 0; nt < 4; nt++)
#pragma unroll
            for (int i = 0; i < 4; i++) acc[mt][nt][i] = 0.f;

    const int iy0 = oy0 * 2 - 1;
    const float* inB = in + ((size_t)b * 128) * 128 * 128;

    auto stage_in = [&](int ch) {
        for (int idx = tid; idx < 8 * 6 * 132; idx += 256) {
            int icl = idx / 792;
            int rem = idx - icl * 792;
            int r = rem / 132, cc = rem - r * 132;
            int iy = iy0 + r, ix = cc - 1;
            bool ok = (unsigned)iy < 128u && (unsigned)ix < 128u;
            const float* src = inB + ((size_t)(ch * 8 + icl) * 128 + iy) * 128 + ix;
            cp_async4_z(in_base + (unsigned)idx * 4u, src, ok);
        }
        cp_commit();
    };
    auto stage_w = [&](int c, int buf) {
        const int tg = c & 3, ch = c >> 2;
#pragma unroll
        for (int i = 0; i < 16; i++) {
            int idx = tid + i * 256;
            int oc = idx & 127, icl = (idx >> 7) & 7, tl = idx >> 10;
            const float2* src =
                wt + ((size_t)((tg * 4 + tl) * 128 + ch * 8 + icl)) * 256 + ocb + oc;
            unsigned dst = ws_base + (unsigned)(buf * C2_WS2 + (tl * 8 + icl) * 132 + oc) * 8u;
            cp_async8(dst, src);
        }
        cp_commit();
    };

    stage_in(0);
    stage_w(0, 0);
    for (int c = 0; c < 64; c++) {
        const int ch = c >> 2, tg = c & 3;
        if (tg == 0 && c > 0) stage_in(ch);
        if (c < 63) { stage_w(c + 1, (c + 1) & 1); cp_wait<1>(); }
        else cp_wait<0>();
        __syncthreads();

        const float2* ws = ws0 + (c & 1) * C2_WS2;
#pragma unroll
        for (int tapl = 0; tapl < 4; tapl++) {
            const int ky = tg, kx = tapl;
            unsigned ahi[4][4], alo[4][4];
#pragma unroll
            for (int mt = 0; mt < 4; mt++) {
                const float2* ap = &ws[(tapl * 8 + lr) * 132 + wm * 64 + mt * 16 + lq];
                float2 p0 = ap[0], p1 = ap[8], p2 = ap[4 * 132], p3 = ap[4 * 132 + 8];
                ahi[mt][0] = __float_as_uint(p0.x); alo[mt][0] = __float_as_uint(p0.y);
                ahi[mt][1] = __float_as_uint(p1.x); alo[mt][1] = __float_as_uint(p1.y);
                ahi[mt][2] = __float_as_uint(p2.x); alo[mt][2] = __float_as_uint(p2.y);
                ahi[mt][3] = __float_as_uint(p3.x); alo[mt][3] = __float_as_uint(p3.y);
            }
#pragma unroll
            for (int nt = 0; nt < 4; nt++) {
                const int ox = xb + nt * 8 + lq;
                const float* bp = &ins[lr * 792 + (2 * oyl + ky) * 132 + 2 * ox + kx];
                float rb0 = bp[0], rb1 = bp[4 * 792];
                unsigned bh0, bl0, bh1, bl1;
                tf32split(rb0, bh0, bl0);
                tf32split(rb1, bh1, bl1);
#pragma unroll
                for (int mt = 0; mt < 4; mt++) {
                    mma8(acc[mt][nt], ahi[mt], bh0, bh1);
                    mma8(acc[mt][nt], ahi[mt], bl0, bl1);
                    mma8(acc[mt][nt], alo[mt], bh0, bh1);
                }
            }
        }
        __syncthreads();
    }

    const int oy = oy0 + oyl;
#pragma unroll
    for (int mt = 0; mt < 4; mt++) {
        const int oc = ocb + wm * 64 + mt * 16 + lq;
        const float b0v = bias[oc], b1v = bias[oc + 8];
#pragma unroll
        for (int nt = 0; nt < 4; nt++) {
            const int ox = xb + nt * 8 + 2 * lr;
            float* o0 = out + (((size_t)b * 256 + oc) * 64 + oy) * 64 + ox;
            float* o1 = o0 + (size_t)8 * 64 * 64;
            *(float2*)o0 = make_float2(fmaxf(acc[mt][nt][0] + b0v, 0.f),
                                       fmaxf(acc[mt][nt][1] + b0v, 0.f));
            *(float2*)o1 = make_float2(fmaxf(acc[mt][nt][2] + b1v, 0.f),
                                       fmaxf(acc[mt][nt][3] + b1v, 0.f));
        }
    }
}

// ============================================================================
// conv3 MMA (3-term): h2 -> 4 K-slab partials.
// Weights ping-pong + input ping-pong, single commit group per chunk.
// ============================================================================
#define C3_WS2 (4 * 8 * 68)
#define C3_INS (8 * 18 * 68)
#define C3_SMEM ((4 * C3_WS2 + 2 * C3_INS) * 4)
__global__ __launch_bounds__(256, 2)
void conv3_mma(const float* __restrict__ in, const float2* __restrict__ wt,
               float* __restrict__ outp) {
    extern __shared__ float sm[];
    float2* ws0 = (float2*)sm;
    float* ins0 = sm + 4 * C3_WS2;
    unsigned ws_base = (unsigned)__cvta_generic_to_shared(ws0);
    unsigned in_base = (unsigned)__cvta_generic_to_shared(ins0);

    const int r0   = blockIdx.x * 8;
    const int b    = blockIdx.z >> 2;
    const int slab = blockIdx.z & 3;

    const int tid  = threadIdx.x;
    const int w    = tid >> 5;
    const int lane = tid & 31;
    const int lq   = lane >> 2;
    const int lr   = lane & 3;

    float acc[4][4][4];
#pragma unroll
    for (int mt = 0; mt < 4; mt++)
#pragma unroll
        for (int nt = 0; nt < 4; nt++)
#pragma unroll
            for (int i = 0; i < 4; i++) acc[mt][nt][i] = 0.f;

    const int iy0 = r0 * 2 - 1;
    const float* inB = in + ((size_t)b * 256 + slab * 64) * 64 * 64;

    auto stage_in3 = [&](int ch) {
        const int ib = ch & 1;
        for (int idx = tid; idx < 8 * 18 * 66; idx += 256) {
            int icl = idx / 1188;
            int rem = idx - icl * 1188;
            int r = rem / 66, cc = rem - r * 66;
            int iy = iy0 + r, ix = cc - 1;
            bool ok = (unsigned)iy < 64u && (unsigned)ix < 64u;
            const float* src = inB + ((size_t)(ch * 8 + icl) * 64 + iy) * 64 + ix;
            unsigned dst = in_base + (unsigned)(ib * C3_INS + icl * 1224 + r * 68 + cc) * 4u;
            cp_async4_z(dst, src, ok);
        }
    };
    auto stage_w3 = [&](int c, int buf) {
        const int tg = c & 3, ch = c >> 2;
#pragma unroll
        for (int i = 0; i < 8; i++) {
            int idx = tid + i * 256;
            int oc = idx & 63, icl = (idx >> 6) & 7, tl = idx >> 9;
            const float2* src =
                wt + ((size_t)((tg * 4 + tl) * 256 + slab * 64 + ch * 8 + icl)) * 64 + oc;
            unsigned dst = ws_base + (unsigned)(buf * C3_WS2 + (tl * 8 + icl) * 68 + oc) * 8u;
            cp_async8(dst, src);
        }
    };

    stage_in3(0);
    stage_w3(0, 0);
    cp_commit();
    for (int c = 0; c < 32; c++) {
        if (c < 31) {
            if (((c + 1) & 3) == 0) stage_in3((c + 1) >> 2);
            stage_w3(c + 1, (c + 1) & 1);
            cp_commit();
            cp_wait<1>();
        } else cp_wait<0>();
        __syncthreads();

        const int tg = c & 3;
        const float2* ws = ws0 + (c & 1) * C3_WS2;
        const float* ins = ins0 + ((c >> 2) & 1) * C3_INS;
#pragma unroll
        for (int tapl = 0; tapl < 4; tapl++) {
            const int ky = tg, kx = tapl;
            unsigned ahi[4][4], alo[4][4];
#pragma unroll
            for (int mt = 0; mt < 4; mt++) {
                const float2* ap = &ws[(tapl * 8 + lr) * 68 + mt * 16 + lq];
                float2 p0 = ap[0], p1 = ap[8], p2 = ap[4 * 68], p3 = ap[4 * 68 + 8];
                ahi[mt][0] = __float_as_uint(p0.x); alo[mt][0] = __float_as_uint(p0.y);
                ahi[mt][1] = __float_as_uint(p1.x); alo[mt][1] = __float_as_uint(p1.y);
                ahi[mt][2] = __float_as_uint(p2.x); alo[mt][2] = __float_as_uint(p2.y);
                ahi[mt][3] = __float_as_uint(p3.x); alo[mt][3] = __float_as_uint(p3.y);
            }
#pragma unroll
            for (int nt = 0; nt < 4; nt++) {
                const int col = nt * 8 + lq;
                const float* bp = &ins[lr * 1224 + (2 * w + ky) * 68 + 2 * col + kx];
                float rb0 = bp[0], rb1 = bp[4 * 1224];
                unsigned bh0, bl0, bh1, bl1;
                tf32split(rb0, bh0, bl0);
                tf32split(rb1, bh1, bl1);
#pragma unroll
                for (int mt = 0; mt < 4; mt++) {
                    mma8(acc[mt][nt], ahi[mt], bh0, bh1);
                    mma8(acc[mt][nt], ahi[mt], bl0, bl1);
                    mma8(acc[mt][nt], alo[mt], bh0, bh1);
                }
            }
        }
        __syncthreads();
    }

    const int NZ = NBATCH * 64 * 32 * 32;
    float* part = outp + (size_t)slab * NZ;
    const int row = r0 + w;
#pragma unroll
    for (int mt = 0; mt < 4; mt++) {
        const int oc = mt * 16 + lq;
#pragma unroll
        for (int nt = 0; nt < 4; nt++) {
            float* o0 = part + (((size_t)b * 64 + oc) * 32 + row) * 32 + nt * 8 + 2 * lr;
            float* o1 = o0 + (size_t)8 * 32 * 32;
            *(float2*)o0 = make_float2(acc[mt][nt][0], acc[mt][nt][1]);
            *(float2*)o1 = make_float2(acc[mt][nt][2], acc[mt][nt][3]);
        }
    }
}

__global__ void addparts(const float* __restrict__ p, const float* __restrict__ bias,
                         float* __restrict__ ze) {
    const int S = NBATCH * 64 * 32 * 32;
    int i = blockIdx.x * 256 + threadIdx.x;
    float v = p[i] + p[i + S] + p[i + 2 * S] + p[i + 3 * S];
    ze[i] = v + bias[(i >> 10) & 63];
}

// ============================================================================
// dconv MMA (1-term tf32): weights AND input double-buffered via cp.async.
// (R10, unchanged)
// ============================================================================
#define D_WS2 (4 * 8 * 132)
template <int CIN, int HIN>
__global__ __launch_bounds__(256, 2)
void dconv_mma(const float* __restrict__ in, const float2* __restrict__ wt,
               const float* __restrict__ bias, float* __restrict__ out,
               int Cout, int nOcb) {
    const int WROW = HIN + 2;
    const int ISTR = HIN + 4;
    const int IBUF = 8 * 3 * ISTR;
    extern __shared__ float sm[];
    float2* ws0 = (float2*)sm;
    float* ins0 = sm + 4 * D_WS2;
    unsigned ws_base = (unsigned)__cvta_generic_to_shared(ws0);
    unsigned in_base = (unsigned)__cvta_generic_to_shared(ins0);

    const int y0 = blockIdx.x * 2;
    const int py = blockIdx.y >> 1, px = blockIdx.y & 1;
    const int b   = blockIdx.z / nOcb;
    const int ocb = (blockIdx.z % nOcb) * 128;

    const int tid  = threadIdx.x;
    const int wid  = tid >> 5;
    const int lane = tid & 31;
    const int wm   = wid >> 2;
    const int wn   = wid & 3;
    const int yl   = wn >> 1;
    const int xb   = (wn & 1) * (HIN / 2);
    const int lq   = lane >> 2;
    const int lr   = lane & 3;
    const int NT   = HIN / 16;
    const int NCH  = CIN / 8;

    float acc[4][4][4];
#pragma unroll
    for (int mt = 0; mt < 4; mt++)
#pragma unroll
        for (int nt = 0; nt < 4; nt++)
#pragma unroll
            for (int i = 0; i < 4; i++) acc[mt][nt][i] = 0.f;

    const float* inB = in + ((size_t)b * CIN) * HIN * HIN;

    auto stage = [&](int ch, int buf) {
        for (int idx = tid; idx < 8 * 3 * WROW; idx += 256) {
            int icl = idx / (3 * WROW);
            int rem = idx - icl * 3 * WROW;
            int r = rem / WROW, s = rem - r * WROW;
            int iy = y0 + py - 1 + r;
            int ix = px - 1 + s;
            bool ok = (unsigned)iy < (unsigned)HIN && (unsigned)ix < (unsigned)HIN;
            const float* src = inB + ((size_t)(ch * 8 + icl) * HIN + iy) * HIN + ix;
            unsigned dst = in_base + (unsigned)(buf * IBUF + (icl * 3 + r) * ISTR + s) * 4u;
            cp_async4_z(dst, src, ok);
        }
#pragma unroll
        for (int i = 0; i < 16; i++) {
            int idx = tid + i * 256;
            int oc = idx & 127, icl = (idx >> 7) & 7, tl = idx >> 10;
            int a = tl >> 1, c2 = tl & 1;
            int t = (1 - py + 2 * a) * 4 + (1 - px + 2 * c2);
            const float2* src =
                wt + ((size_t)(t * CIN + ch * 8 + icl)) * Cout + ocb + oc;
            unsigned dst = ws_base + (unsigned)(buf * D_WS2 + (tl * 8 + icl) * 132 + oc) * 8u;
            cp_async8(dst, src);
        }
        cp_commit();
    };

    stage(0, 0);
    for (int ch = 0; ch < NCH; ch++) {
        if (ch + 1 < NCH) { stage(ch + 1, (ch + 1) & 1); cp_wait<1>(); }
        else cp_wait<0>();
        __syncthreads();

        const float2* ws = ws0 + (ch & 1) * D_WS2;
        const float* ins = ins0 + (ch & 1) * IBUF;
#pragma unroll
        for (int tl = 0; tl < 4; tl++) {
            const int a = tl >> 1, c = tl & 1;
            unsigned ahi[4][4];
#pragma unroll
            for (int mt = 0; mt < 4; mt++) {
                const float2* ap = &ws[(tl * 8 + lr) * 132 + wm * 64 + mt * 16 + lq];
                ahi[mt][0] = __float_as_uint(ap[0].x);
                ahi[mt][1] = __float_as_uint(ap[8].x);
                ahi[mt][2] = __float_as_uint(ap[4 * 132].x);
                ahi[mt][3] = __float_as_uint(ap[4 * 132 + 8].x);
            }
#pragma unroll
            for (int nt = 0; nt < NT; nt++) {
                const int x = xb + nt * 8 + lq;
                const float* bp = &ins[(lr * 3 + (yl + 1 - a)) * ISTR + x + 1 - c];
                unsigned bh0 = tf32cvt(bp[0]), bh1 = tf32cvt(bp[4 * 3 * ISTR]);
#pragma unroll
                for (int mt = 0; mt < 4; mt++)
                    mma8(acc[mt][nt], ahi[mt], bh0, bh1);
            }
        }
        __syncthreads();
    }

    const int HOUT = 2 * HIN;
    const int oy = 2 * (y0 + yl) + py;
#pragma unroll
    for (int mt = 0; mt < 4; mt++) {
        const int oc = ocb + wm * 64 + mt * 16 + lq;
        const float b0v = bias[oc], b1v = bias[oc + 8];
#pragma unroll
        for (int nt = 0; nt < NT; nt++) {
            const int x = xb + nt * 8 + 2 * lr;
            const int ox = 2 * x + px;
            float* o0 = out + (((size_t)b * Cout + oc) * HOUT + oy) * HOUT + ox;
            float* o1 = o0 + (size_t)8 * HOUT * HOUT;
            o0[0] = fmaxf(acc[mt][nt][0] + b0v, 0.f);
            o0[2] = fmaxf(acc[mt][nt][1] + b0v, 0.f);
            o1[0] = fmaxf(acc[mt][nt][2] + b1v, 0.f);
            o1[2] = fmaxf(acc[mt][nt][3] + b1v, 0.f);
        }
    }
}
#define DCONV_SMEM(HIN) ((4 * D_WS2 + 2 * 8 * 3 * ((HIN) + 4)) * 4)

// ============================================================================
// Scalar kernels: conv1, dconv3out, vqk.  (unchanged)
// ============================================================================
template <int CIN, bool RELU>
__global__ __launch_bounds__(256, 2)
void conv4s2(const float* __restrict__ in, const float* __restrict__ wt,
             const float* __restrict__ bias, float* __restrict__ out,
             int Cout, int Hin, int Win, int Hout, int Wout, int tilesX) {
    __shared__ float ish[34 * 36];
    __shared__ float wsh[64 * 16];

    const int tile = blockIdx.x;
    const int tx0 = (tile % tilesX) * 16;
    const int ty0 = (tile / tilesX) * 16;
    const int ocb = blockIdx.y * 64;
    const int b   = blockIdx.z;

    const int tid = threadIdx.x;
    const int og  = tid >> 5;
    const int sp  = tid & 31;
    const int r   = sp >> 1;
    const int cb  = (sp & 1) * 8;

    float acc[8][8];
#pragma unroll
    for (int o = 0; o < 8; o++) {
        float bv = bias[ocb + og * 8 + o];
#pragma unroll
        for (int j = 0; j < 8; j++) acc[o][j] = bv;
    }

    const int iy0 = ty0 * 2 - 1, ix0 = tx0 * 2 - 1;
    const float* inB = in + ((size_t)b * CIN) * Hin * Win;

    for (int ic = 0; ic < CIN; ic++) {
        const float* inC = inB + (size_t)ic * Hin * Win;
        for (int idx = tid; idx < 34 * 34; idx += 256) {
            int py = idx / 34, px = idx - py * 34;
            int iy = iy0 + py, ix = ix0 + px;
            float v = 0.f;
            if ((unsigned)iy < (unsigned)Hin && (unsigned)ix < (unsigned)Win)
                v = inC[iy * Win + ix];
            ish[py * 36 + px] = v;
        }
        const float* wC = wt + (ic * Cout + ocb) * 16;
        for (int idx = tid; idx < 1024; idx += 256) wsh[idx] = wC[idx];
        __syncthreads();

#pragma unroll
        for (int ky = 0; ky < 4; ky++) {
            const float* rp = &ish[(2 * r + ky) * 36 + 2 * cb];
            float4 v0 = *(const float4*)(rp);
            float4 v1 = *(const float4*)(rp + 4);
            float4 v2 = *(const float4*)(rp + 8);
            float4 v3 = *(const float4*)(rp + 12);
            float4 v4 = *(const float4*)(rp + 16);
            float riv[20] = {v0.x, v0.y, v0.z, v0.w, v1.x, v1.y, v1.z, v1.w,
                             v2.x, v2.y, v2.z, v2.w, v3.x, v3.y, v3.z, v3.w,
                             v4.x, v4.y, v4.z, v4.w};
#pragma unroll
            for (int kx = 0; kx < 4; kx++) {
                const int t = ky * 4 + kx;
                float wv[8];
#pragma unroll
                for (int o = 0; o < 8; o++) wv[o] = wsh[(og * 8 + o) * 16 + t];
#pragma unroll
                for (int o = 0; o < 8; o++)
#pragma unroll
                    for (int j = 0; j < 8; j++)
                        acc[o][j] = fmaf(wv[o], riv[kx + 2 * j], acc[o][j]);
            }
        }
        __syncthreads();
    }

    const int oy = ty0 + r;
    const int oxb = tx0 + cb;
#pragma unroll
    for (int o = 0; o < 8; o++) {
        float* op = out + (((size_t)b * Cout + ocb + og * 8 + o) * Hout + oy) * Wout + oxb;
        float tmp[8];
#pragma unroll
        for (int j = 0; j < 8; j++)
            tmp[j] = RELU ? fmaxf(acc[o][j], 0.f) : acc[o][j];
        *(float4*)op       = make_float4(tmp[0], tmp[1], tmp[2], tmp[3]);
        *(float4*)(op + 4) = make_float4(tmp[4], tmp[5], tmp[6], tmp[7]);
    }
}

__global__ __launch_bounds__(128, 4)
void dconv3out(const float* __restrict__ in, const float* __restrict__ wt,
               const float* __restrict__ bias, float* __restrict__ out,
               int tilesX) {
    const int Cin = 128, Hin = 128, Win = 128, Hout = 256, Wout = 256;
    __shared__ float ish[4][18 * 19];
    __shared__ float wsh[4][3 * 16];

    const int tile = blockIdx.x;
    const int ox0 = (tile % tilesX) * 32;
    const int oy0 = (tile / tilesX) * 32;
    const int b   = blockIdx.y;

    const int tid = threadIdx.x;
    const int q   = tid >> 5;
    const int py  = q >> 1, px = q & 1;
    const int sp  = tid & 31;
    const int ry  = sp >> 1;
    const int ch  = (sp & 1) * 8;

    float acc[3][8];
#pragma unroll
    for (int o = 0; o < 3; o++) {
        float bv = bias[o];
#pragma unroll
        for (int j = 0; j < 8; j++) acc[o][j] = bv;
    }

    const int iy0 = oy0 >> 1, ix0 = ox0 >> 1;
    const int kp = 1 - py, kq = 1 - px;

    for (int ic0 = 0; ic0 < Cin; ic0 += 4) {
        for (int idx = tid; idx < 4 * 324; idx += 128) {
            int icc = idx / 324, p = idx - icc * 324;
            int piy = p / 18, pix = p - piy * 18;
            int iy = iy0 - 1 + piy, ix = ix0 - 1 + pix;
            float v = 0.f;
            if ((unsigned)iy < (unsigned)Hin && (unsigned)ix < (unsigned)Win)
                v = in[(((size_t)b * Cin + ic0 + icc) * Hin + iy) * Win + ix];
            ish[icc][piy * 19 + pix] = v;
        }
        for (int idx = tid; idx < 4 * 48; idx += 128) {
            int icc = idx / 48, rmd = idx - icc * 48;
            wsh[icc][rmd] = wt[(ic0 + icc) * 48 + rmd];
        }
        __syncthreads();

#pragma unroll
        for (int icc = 0; icc < 4; icc++) {
#pragma unroll
            for (int a = 0; a < 2; a++) {
                const int ky  = kp + 2 * a;
                const int liy = ry + 1 + py - a;
                float iv[10];
                const int base = liy * 19 + ch + px;
#pragma unroll
                for (int j = 0; j < 10; j++) iv[j] = ish[icc][base + j];
#pragma unroll
                for (int c = 0; c < 2; c++) {
                    const int kx  = kq + 2 * c;
                    const int t   = ky * 4 + kx;
                    const int off = 1 - c;
                    float wv[3];
#pragma unroll
                    for (int o = 0; o < 3; o++) wv[o] = wsh[icc][o * 16 + t];
#pragma unroll
                    for (int o = 0; o < 3; o++)
#pragma unroll
                        for (int j = 0; j < 8; j++)
                            acc[o][j] = fmaf(wv[o], iv[j + off], acc[o][j]);
                }
            }
        }
        __syncthreads();
    }

    const int oy = oy0 + 2 * ry + py;
#pragma unroll
    for (int o = 0; o < 3; o++) {
        float* op = out + (((size_t)b * 3 + o) * Hout + oy) * Wout + ox0 + px + 2 * ch;
#pragma unroll
        for (int j = 0; j < 8; j++) op[2 * j] = acc[o][j];
    }
}

__global__ __launch_bounds__(128, 8)
void vqk(const float* __restrict__ ze, const float* __restrict__ emb,
         float* __restrict__ zq, float* __restrict__ idxf) {
    __shared__ __align__(16) float esh[64 * 64];
    __shared__ float en[64];

    const int row = blockIdx.x * 128 + threadIdx.x;
    float f[64];
    const float4* fp = (const float4*)(ze + (size_t)row * 64);
#pragma unroll
    for (int i = 0; i < 16; i++) {
        float4 v = fp[i];
        f[4 * i] = v.x; f[4 * i + 1] = v.y; f[4 * i + 2] = v.z; f[4 * i + 3] = v.w;
    }
    float fn = 0.f;
#pragma unroll
    for (int d = 0; d < 64; d++) fn = fmaf(f[d], f[d], fn);

    float best = 3.4e38f;
    int bidx = 0;
    for (int cb = 0; cb < 512; cb += 64) {
        __syncthreads();
        const float4* src = (const float4*)(emb + (size_t)cb * 64);
        for (int i = threadIdx.x; i < 1024; i += 128)
            ((float4*)esh)[i] = src[i];
        __syncthreads();
        if (threadIdx.x < 64) {
            float s = 0.f;
            const float* e = esh + threadIdx.x * 64;
#pragma unroll
            for (int d = 0; d < 64; d++) s = fmaf(e[d], e[d], s);
            en[threadIdx.x] = s;
        }
        __syncthreads();
        for (int c = 0; c < 64; c++) {
            const float4* ev = (const float4*)(esh + c * 64);
            float dot = 0.f;
#pragma unroll
            for (int i = 0; i < 16; i++) {
                float4 e = ev[i];
                dot = fmaf(f[4 * i], e.x, dot);
                dot = fmaf(f[4 * i + 1], e.y, dot);
                dot = fmaf(f[4 * i + 2], e.z, dot);
                dot = fmaf(f[4 * i + 3], e.w, dot);
            }
            float sc = fn - 2.f * dot + en[c];
            if (sc < best) { best = sc; bidx = cb + c; }
        }
    }

    idxf[row] = (float)bidx;
    const float4* ep = (const float4*)(emb + (size_t)bidx * 64);
    float4* qp = (float4*)(zq + (size_t)row * 64);
#pragma unroll
    for (int i = 0; i < 16; i++) qp[i] = ep[i];
}

// ---------------------------------------------------------------------------
extern "C" void kernel_launch(void* const* d_in, const int* in_sizes, int n_in,
                              void* d_out, int out_size) {
    (void)in_sizes; (void)n_in;
    const float* x   = (const float*)d_in[0];
    const float* w1  = (const float*)d_in[1];
    const float* b1  = (const float*)d_in[2];
    const float* w2  = (const float*)d_in[3];
    const float* b2  = (const float*)d_in[4];
    const float* w3  = (const float*)d_in[5];
    const float* b3  = (const float*)d_in[6];
    const float* d1w = (const float*)d_in[7];
    const float* d1b = (const float*)d_in[8];
    const float* d2w = (const float*)d_in[9];
    const float* d2b = (const float*)d_in[10];
    const float* d3w = (const float*)d_in[11];
    const float* d3b = (const float*)d_in[12];
    const float* emb = (const float*)d_in[13];

    float *h1, *h2, *g1, *g2, *ze, *zq, *idxf, *wt1;
    float2 *w2s, *w3s, *d2s, *d1s;
    cudaGetSymbolAddress((void**)&h1, g_h1);
    cudaGetSymbolAddress((void**)&h2, g_h2);
    cudaGetSymbolAddress((void**)&g1, g_g1);
    cudaGetSymbolAddress((void**)&g2, g_g2);
    cudaGetSymbolAddress((void**)&ze, g_ze);
    cudaGetSymbolAddress((void**)&zq, g_zq);
    cudaGetSymbolAddress((void**)&idxf, g_if);
    cudaGetSymbolAddress((void**)&wt1, g_wt1);
    cudaGetSymbolAddress((void**)&w2s, g_w2s);
    cudaGetSymbolAddress((void**)&w3s, g_w3s);
    cudaGetSymbolAddress((void**)&d2s, g_d2s);
    cudaGetSymbolAddress((void**)&d1s, g_d1s);

    float* outF = (float*)d_out;
    const int NX = NBATCH * 3 * 256 * 256;
    const int NZ = NBATCH * 64 * 32 * 32;
    const int NI = 16384;
    if (out_size >= NX + 2 * NZ + NI) {
        ze   = outF + NX;
        zq   = outF + NX + NZ;
        idxf = outF + NX + 2 * NZ;
    }

    static bool attr_done = false;
    if (!attr_done) {
        cudaFuncSetAttribute(conv2_mma, cudaFuncAttributeMaxDynamicSharedMemorySize,
                             C2_SMEM);
        cudaFuncSetAttribute(conv3_mma, cudaFuncAttributeMaxDynamicSharedMemorySize,
                             C3_SMEM);
        cudaFuncSetAttribute(dconv_mma<64, 32>, cudaFuncAttributeMaxDynamicSharedMemorySize,
                             DCONV_SMEM(32));
        cudaFuncSetAttribute(dconv_mma<256, 64>, cudaFuncAttributeMaxDynamicSharedMemorySize,
                             DCONV_SMEM(64));
        attr_done = true;
    }

    wsplit2t<<<2048, 256>>>(w2, w2s);
    wtrans<<<(128 * 3 * 16 + 255) / 256, 256>>>(w1, wt1, 128, 3);
    conv4s2<3, true><<<dim3(64, 2, NBATCH), 256>>>(x, wt1, b1, h1, 128, 256, 256, 128, 128, 8);
    conv2_mma<<<dim3(32, 2, NBATCH), 256, C2_SMEM>>>(h1, w2s, b2, h2);
    wsplit3<<<1024, 256>>>(w3, w3s);
    conv3_mma<<<dim3(4, 1, NBATCH * 4), 256, C3_SMEM>>>(h2, w3s, g2);
    addparts<<<NZ / 256, 256>>>(g2, b3, ze);
    vqk<<<128, 128>>>(ze, emb, zq, idxf);
    wsplitD1<<<1024, 256>>>(d1w, d1s);
    dconv_mma<64, 32><<<dim3(16, 4, NBATCH * 2), 256, DCONV_SMEM(32)>>>(zq, d1s, d1b, g1, 256, 2);
    wsplitD2<<<2048, 256>>>(d2w, d2s);
    dconv_mma<256, 64><<<dim3(32, 4, NBATCH), 256, DCONV_SMEM(64)>>>(g1, d2s, d2b, g2, 128, 1);
    dconv3out<<<dim3(64, NBATCH), 128>>>(g2, d3w, d3b, outF, 8);
}

// round 12
// speedup vs baseline: 1.2766x; 1.0004x over previous
#include <cuda_runtime.h>

// ---------------------------------------------------------------------------
// VQ-VAE forward, sm_100a.  (R10 + conv3 input double-buffer + conv2 async
// input staging.)
//   Encoder conv2/conv3: mma.sync tf32 3-term hi/lo split (argmin-safe).
//   Decoder dconv1/dconv2: mma.sync tf32 1-term.
//   All MMA layers: cp.async pipelined staging.
//   conv1 / dconv3 / VQ: scalar-FFMA register-tiled.
// Output layout: [x_recon | z_e | z_q | idx(as float)], fp32.
// ---------------------------------------------------------------------------

#define NBATCH 16

// -------- scratch ------------------------------------------------------------
__device__ float g_h1[NBATCH * 128 * 128 * 128];
__device__ float g_h2[NBATCH * 256 * 64 * 64];
__device__ float g_g1[NBATCH * 256 * 64 * 64];
__device__ float g_g2[NBATCH * 128 * 128 * 128];
__device__ float g_ze[NBATCH * 64 * 32 * 32];
__device__ float g_zq[NBATCH * 64 * 32 * 32];
__device__ float g_if[16384];
__device__ float g_wt1[128 * 3 * 16];
__device__ float2 g_w2s[16 * 128 * 256];   // conv2  [t][ic][oc] (hi,lo)
__device__ float2 g_w3s[16 * 256 * 64];    // conv3  [t][ic][oc] (hi,lo)
__device__ float2 g_d2s[16 * 256 * 128];   // dconv2 [t][ic][oc] (hi,lo)
__device__ float2 g_d1s[16 * 64 * 256];    // dconv1 [t][ic][oc] (hi,lo)

// -------- helpers ------------------------------------------------------------
__device__ __forceinline__ void tf32split(float v, unsigned& hi, unsigned& lo) {
    unsigned h;
    asm("cvt.rna.tf32.f32 %0,%1;" : "=r"(h) : "f"(v));
    float l = v - __uint_as_float(h);
    unsigned lw;
    asm("cvt.rna.tf32.f32 %0,%1;" : "=r"(lw) : "f"(l));
    hi = h; lo = lw;
}
__device__ __forceinline__ unsigned tf32cvt(float v) {
    unsigned h;
    asm("cvt.rna.tf32.f32 %0,%1;" : "=r"(h) : "f"(v));
    return h;
}
__device__ __forceinline__ float2 splitpack(float v) {
    unsigned h, l;
    tf32split(v, h, l);
    return make_float2(__uint_as_float(h), __uint_as_float(l));
}
__device__ __forceinline__ void mma8(float* c, const unsigned* a,
                                     unsigned b0, unsigned b1) {
    asm("mma.sync.aligned.m16n8k8.row.col.f32.tf32.tf32.f32 "
        "{%0,%1,%2,%3},{%4,%5,%6,%7},{%8,%9},{%0,%1,%2,%3};"
        : "+f"(c[0]), "+f"(c[1]), "+f"(c[2]), "+f"(c[3])
        : "r"(a[0]), "r"(a[1]), "r"(a[2]), "r"(a[3]), "r"(b0), "r"(b1));
}
__device__ __forceinline__ void cp_async8(unsigned dst, const void* src) {
    asm volatile("cp.async.ca.shared.global [%0], [%1], 8;\n"
                 :: "r"(dst), "l"(src));
}
__device__ __forceinline__ void cp_async4_z(unsigned dst, const void* src, bool pred) {
    int sz = pred ? 4 : 0;
    asm volatile("cp.async.ca.shared.global [%0], [%1], 4, %2;\n"
                 :: "r"(dst), "l"(src), "r"(sz));
}
__device__ __forceinline__ void cp_commit() {
    asm volatile("cp.async.commit_group;\n");
}
template <int N>
__device__ __forceinline__ void cp_wait() {
    asm volatile("cp.async.wait_group %0;\n" :: "n"(N));
}

// -------- weight transforms --------------------------------------------------
__global__ void wtrans(const float* __restrict__ w, float* __restrict__ wo,
                       int Cout, int Cin) {   // OIHW -> [ic][oc][t]
    int idx = blockIdx.x * 256 + threadIdx.x;
    int total = Cout * Cin * 16;
    if (idx < total) {
        int t = idx & 15;
        int rest = idx >> 4;
        int ic = rest % Cin;
        int oc = rest / Cin;
        wo[(ic * Cout + oc) * 16 + t] = w[idx];
    }
}
__global__ void wsplit2t(const float* __restrict__ w, float2* __restrict__ wo) {
    int idx = blockIdx.x * 256 + threadIdx.x;   // 524288
    int t = idx & 15, ic = (idx >> 4) & 127, oc = idx >> 11;
    wo[(t * 128 + ic) * 256 + oc] = splitpack(w[idx]);
}
__global__ void wsplit3(const float* __restrict__ w, float2* __restrict__ wo) {
    int idx = blockIdx.x * 256 + threadIdx.x;   // 262144
    int t = idx & 15, ic = (idx >> 4) & 255, oc = idx >> 12;
    wo[(t * 256 + ic) * 64 + oc] = splitpack(w[idx]);
}
__global__ void wsplitD2(const float* __restrict__ w, float2* __restrict__ wo) {
    int idx = blockIdx.x * 256 + threadIdx.x;   // 524288
    int t = idx & 15, oc = (idx >> 4) & 127, ic = idx >> 11;
    wo[(t * 256 + ic) * 128 + oc] = splitpack(w[idx]);
}
__global__ void wsplitD1(const float* __restrict__ w, float2* __restrict__ wo) {
    int idx = blockIdx.x * 256 + threadIdx.x;   // 262144
    int t = idx & 15, oc = (idx >> 4) & 255, ic = idx >> 12;
    wo[(t * 64 + ic) * 256 + oc] = splitpack(w[idx]);
}

// ============================================================================
// conv2 MMA (3-term): h1 -> h2, k4 s2 p1, relu.
// Weights ping-pong cp.async; input staged via cp.async (own group, in-chunk).
// ============================================================================
#define C2_WS2 (4 * 8 * 132)
#define C2_INS (8 * 6 * 132)
#define C2_SMEM ((4 * C2_WS2 + C2_INS) * 4)
__global__ __launch_bounds__(256, 2)
void conv2_mma(const float* __restrict__ in, const float2* __restrict__ wt,
               const float* __restrict__ bias, float* __restrict__ out) {
    extern __shared__ float sm[];
    float2* ws0 = (float2*)sm;
    float* ins = sm + 4 * C2_WS2;
    unsigned ws_base = (unsigned)__cvta_generic_to_shared(ws0);
    unsigned in_base = (unsigned)__cvta_generic_to_shared(ins);

    const int oy0 = blockIdx.x * 2;
    const int ocb = blockIdx.y * 128;
    const int b   = blockIdx.z;

    const int tid  = threadIdx.x;
    const int wid  = tid >> 5;
    const int lane = tid & 31;
    const int wm   = wid >> 2;
    const int wn   = wid & 3;
    const int oyl  = wn >> 1;
    const int xb   = (wn & 1) * 32;
    const int lq   = lane >> 2;
    const int lr   = lane & 3;

    float acc[4][4][4];
#pragma unroll
    for (int mt = 0; mt < 4; mt++)
#pragma unroll
        for (int nt = 0; nt < 4; nt++)
#pragma unroll
            for (int i = 0; i < 4; i++) acc[mt][nt][i] = 0.f;

    const int iy0 = oy0 * 2 - 1;
    const float* inB = in + ((size_t)b * 128) * 128 * 128;

    auto stage_in = [&](int ch) {
        for (int idx = tid; idx < 8 * 6 * 132; idx += 256) {
            int icl = idx / 792;
            int rem = idx - icl * 792;
            int r = rem / 132, cc = rem - r * 132;
            int iy = iy0 + r, ix = cc - 1;
            bool ok = (unsigned)iy < 128u && (unsigned)ix < 128u;
            const float* src = inB + ((size_t)(ch * 8 + icl) * 128 + iy) * 128 + ix;
            cp_async4_z(in_base + (unsigned)idx * 4u, src, ok);
        }
        cp_commit();
    };
    auto stage_w = [&](int c, int buf) {
        const int tg = c & 3, ch = c >> 2;
#pragma unroll
        for (int i = 0; i < 16; i++) {
            int idx = tid + i * 256;
            int oc = idx & 127, icl = (idx >> 7) & 7, tl = idx >> 10;
            const float2* src =
                wt + ((size_t)((tg * 4 + tl) * 128 + ch * 8 + icl)) * 256 + ocb + oc;
            unsigned dst = ws_base + (unsigned)(buf * C2_WS2 + (tl * 8 + icl) * 132 + oc) * 8u;
            cp_async8(dst, src);
        }
        cp_commit();
    };

    stage_in(0);
    stage_w(0, 0);
    for (int c = 0; c < 64; c++) {
        const int ch = c >> 2, tg = c & 3;
        if (tg == 0 && c > 0) stage_in(ch);
        if (c < 63) { stage_w(c + 1, (c + 1) & 1); cp_wait<1>(); }
        else cp_wait<0>();
        __syncthreads();

        const float2* ws = ws0 + (c & 1) * C2_WS2;
#pragma unroll
        for (int tapl = 0; tapl < 4; tapl++) {
            const int ky = tg, kx = tapl;
            unsigned ahi[4][4], alo[4][4];
#pragma unroll
            for (int mt = 0; mt < 4; mt++) {
                const float2* ap = &ws[(tapl * 8 + lr) * 132 + wm * 64 + mt * 16 + lq];
                float2 p0 = ap[0], p1 = ap[8], p2 = ap[4 * 132], p3 = ap[4 * 132 + 8];
                ahi[mt][0] = __float_as_uint(p0.x); alo[mt][0] = __float_as_uint(p0.y);
                ahi[mt][1] = __float_as_uint(p1.x); alo[mt][1] = __float_as_uint(p1.y);
                ahi[mt][2] = __float_as_uint(p2.x); alo[mt][2] = __float_as_uint(p2.y);
                ahi[mt][3] = __float_as_uint(p3.x); alo[mt][3] = __float_as_uint(p3.y);
            }
#pragma unroll
            for (int nt = 0; nt < 4; nt++) {
                const int ox = xb + nt * 8 + lq;
                const float* bp = &ins[lr * 792 + (2 * oyl + ky) * 132 + 2 * ox + kx];
                float rb0 = bp[0], rb1 = bp[4 * 792];
                unsigned bh0, bl0, bh1, bl1;
                tf32split(rb0, bh0, bl0);
                tf32split(rb1, bh1, bl1);
#pragma unroll
                for (int mt = 0; mt < 4; mt++) {
                    mma8(acc[mt][nt], ahi[mt], bh0, bh1);
                    mma8(acc[mt][nt], ahi[mt], bl0, bl1);
                    mma8(acc[mt][nt], alo[mt], bh0, bh1);
                }
            }
        }
        __syncthreads();
    }

    const int oy = oy0 + oyl;
#pragma unroll
    for (int mt = 0; mt < 4; mt++) {
        const int oc = ocb + wm * 64 + mt * 16 + lq;
        const float b0v = bias[oc], b1v = bias[oc + 8];
#pragma unroll
        for (int nt = 0; nt < 4; nt++) {
            const int ox = xb + nt * 8 + 2 * lr;
            float* o0 = out + (((size_t)b * 256 + oc) * 64 + oy) * 64 + ox;
            float* o1 = o0 + (size_t)8 * 64 * 64;
            *(float2*)o0 = make_float2(fmaxf(acc[mt][nt][0] + b0v, 0.f),
                                       fmaxf(acc[mt][nt][1] + b0v, 0.f));
            *(float2*)o1 = make_float2(fmaxf(acc[mt][nt][2] + b1v, 0.f),
                                       fmaxf(acc[mt][nt][3] + b1v, 0.f));
        }
    }
}

// ============================================================================
// conv3 MMA (3-term): h2 -> 4 K-slab partials.
// Weights ping-pong + input ping-pong, single commit group per chunk.
// ============================================================================
#define C3_WS2 (4 * 8 * 68)
#define C3_INS (8 * 18 * 68)
#define C3_SMEM ((4 * C3_WS2 + 2 * C3_INS) * 4)
__global__ __launch_bounds__(256, 2)
void conv3_mma(const float* __restrict__ in, const float2* __restrict__ wt,
               float* __restrict__ outp) {
    extern __shared__ float sm[];
    float2* ws0 = (float2*)sm;
    float* ins0 = sm + 4 * C3_WS2;
    unsigned ws_base = (unsigned)__cvta_generic_to_shared(ws0);
    unsigned in_base = (unsigned)__cvta_generic_to_shared(ins0);

    const int r0   = blockIdx.x * 8;
    const int b    = blockIdx.z >> 2;
    const int slab = blockIdx.z & 3;

    const int tid  = threadIdx.x;
    const int w    = tid >> 5;
    const int lane = tid & 31;
    const int lq   = lane >> 2;
    const int lr   = lane & 3;

    float acc[4][4][4];
#pragma unroll
    for (int mt = 0; mt < 4; mt++)
#pragma unroll
        for (int nt = 0; nt < 4; nt++)
#pragma unroll
            for (int i = 0; i < 4; i++) acc[mt][nt][i] = 0.f;

    const int iy0 = r0 * 2 - 1;
    const float* inB = in + ((size_t)b * 256 + slab * 64) * 64 * 64;

    auto stage_in3 = [&](int ch) {
        const int ib = ch & 1;
        for (int idx = tid; idx < 8 * 18 * 66; idx += 256) {
            int icl = idx / 1188;
            int rem = idx - icl * 1188;
            int r = rem / 66, cc = rem - r * 66;
            int iy = iy0 + r, ix = cc - 1;
            bool ok = (unsigned)iy < 64u && (unsigned)ix < 64u;
            const float* src = inB + ((size_t)(ch * 8 + icl) * 64 + iy) * 64 + ix;
            unsigned dst = in_base + (unsigned)(ib * C3_INS + icl * 1224 + r * 68 + cc) * 4u;
            cp_async4_z(dst, src, ok);
        }
    };
    auto stage_w3 = [&](int c, int buf) {
        const int tg = c & 3, ch = c >> 2;
#pragma unroll
        for (int i = 0; i < 8; i++) {
            int idx = tid + i * 256;
            int oc = idx & 63, icl = (idx >> 6) & 7, tl = idx >> 9;
            const float2* src =
                wt + ((size_t)((tg * 4 + tl) * 256 + slab * 64 + ch * 8 + icl)) * 64 + oc;
            unsigned dst = ws_base + (unsigned)(buf * C3_WS2 + (tl * 8 + icl) * 68 + oc) * 8u;
            cp_async8(dst, src);
        }
    };

    stage_in3(0);
    stage_w3(0, 0);
    cp_commit();
    for (int c = 0; c < 32; c++) {
        if (c < 31) {
            if (((c + 1) & 3) == 0) stage_in3((c + 1) >> 2);
            stage_w3(c + 1, (c + 1) & 1);
            cp_commit();
            cp_wait<1>();
        } else cp_wait<0>();
        __syncthreads();

        const int tg = c & 3;
        const float2* ws = ws0 + (c & 1) * C3_WS2;
        const float* ins = ins0 + ((c >> 2) & 1) * C3_INS;
#pragma unroll
        for (int tapl = 0; tapl < 4; tapl++) {
            const int ky = tg, kx = tapl;
            unsigned ahi[4][4], alo[4][4];
#pragma unroll
            for (int mt = 0; mt < 4; mt++) {
                const float2* ap = &ws[(tapl * 8 + lr) * 68 + mt * 16 + lq];
                float2 p0 = ap[0], p1 = ap[8], p2 = ap[4 * 68], p3 = ap[4 * 68 + 8];
                ahi[mt][0] = __float_as_uint(p0.x); alo[mt][0] = __float_as_uint(p0.y);
                ahi[mt][1] = __float_as_uint(p1.x); alo[mt][1] = __float_as_uint(p1.y);
                ahi[mt][2] = __float_as_uint(p2.x); alo[mt][2] = __float_as_uint(p2.y);
                ahi[mt][3] = __float_as_uint(p3.x); alo[mt][3] = __float_as_uint(p3.y);
            }
#pragma unroll
            for (int nt = 0; nt < 4; nt++) {
                const int col = nt * 8 + lq;
                const float* bp = &ins[lr * 1224 + (2 * w + ky) * 68 + 2 * col + kx];
                float rb0 = bp[0], rb1 = bp[4 * 1224];
                unsigned bh0, bl0, bh1, bl1;
                tf32split(rb0, bh0, bl0);
                tf32split(rb1, bh1, bl1);
#pragma unroll
                for (int mt = 0; mt < 4; mt++) {
                    mma8(acc[mt][nt], ahi[mt], bh0, bh1);
                    mma8(acc[mt][nt], ahi[mt], bl0, bl1);
                    mma8(acc[mt][nt], alo[mt], bh0, bh1);
                }
            }
        }
        __syncthreads();
    }

    const int NZ = NBATCH * 64 * 32 * 32;
    float* part = outp + (size_t)slab * NZ;
    const int row = r0 + w;
#pragma unroll
    for (int mt = 0; mt < 4; mt++) {
        const int oc = mt * 16 + lq;
#pragma unroll
        for (int nt = 0; nt < 4; nt++) {
            float* o0 = part + (((size_t)b * 64 + oc) * 32 + row) * 32 + nt * 8 + 2 * lr;
            float* o1 = o0 + (size_t)8 * 32 * 32;
            *(float2*)o0 = make_float2(acc[mt][nt][0], acc[mt][nt][1]);
            *(float2*)o1 = make_float2(acc[mt][nt][2], acc[mt][nt][3]);
        }
    }
}

__global__ void addparts(const float* __restrict__ p, const float* __restrict__ bias,
                         float* __restrict__ ze) {
    const int S = NBATCH * 64 * 32 * 32;
    int i = blockIdx.x * 256 + threadIdx.x;
    float v = p[i] + p[i + S] + p[i + 2 * S] + p[i + 3 * S];
    ze[i] = v + bias[(i >> 10) & 63];
}

// ============================================================================
// dconv MMA (1-term tf32): weights AND input double-buffered via cp.async.
// (R10, unchanged)
// ============================================================================
#define D_WS2 (4 * 8 * 132)
template <int CIN, int HIN>
__global__ __launch_bounds__(256, 2)
void dconv_mma(const float* __restrict__ in, const float2* __restrict__ wt,
               const float* __restrict__ bias, float* __restrict__ out,
               int Cout, int nOcb) {
    const int WROW = HIN + 2;
    const int ISTR = HIN + 4;
    const int IBUF = 8 * 3 * ISTR;
    extern __shared__ float sm[];
    float2* ws0 = (float2*)sm;
    float* ins0 = sm + 4 * D_WS2;
    unsigned ws_base = (unsigned)__cvta_generic_to_shared(ws0);
    unsigned in_base = (unsigned)__cvta_generic_to_shared(ins0);

    const int y0 = blockIdx.x * 2;
    const int py = blockIdx.y >> 1, px = blockIdx.y & 1;
    const int b   = blockIdx.z / nOcb;
    const int ocb = (blockIdx.z % nOcb) * 128;

    const int tid  = threadIdx.x;
    const int wid  = tid >> 5;
    const int lane = tid & 31;
    const int wm   = wid >> 2;
    const int wn   = wid & 3;
    const int yl   = wn >> 1;
    const int xb   = (wn & 1) * (HIN / 2);
    const int lq   = lane >> 2;
    const int lr   = lane & 3;
    const int NT   = HIN / 16;
    const int NCH  = CIN / 8;

    float acc[4][4][4];
#pragma unroll
    for (int mt = 0; mt < 4; mt++)
#pragma unroll
        for (int nt = 0; nt < 4; nt++)
#pragma unroll
            for (int i = 0; i < 4; i++) acc[mt][nt][i] = 0.f;

    const float* inB = in + ((size_t)b * CIN) * HIN * HIN;

    auto stage = [&](int ch, int buf) {
        for (int idx = tid; idx < 8 * 3 * WROW; idx += 256) {
            int icl = idx / (3 * WROW);
            int rem = idx - icl * 3 * WROW;
            int r = rem / WROW, s = rem - r * WROW;
            int iy = y0 + py - 1 + r;
            int ix = px - 1 + s;
            bool ok = (unsigned)iy < (unsigned)HIN && (unsigned)ix < (unsigned)HIN;
            const float* src = inB + ((size_t)(ch * 8 + icl) * HIN + iy) * HIN + ix;
            unsigned dst = in_base + (unsigned)(buf * IBUF + (icl * 3 + r) * ISTR + s) * 4u;
            cp_async4_z(dst, src, ok);
        }
#pragma unroll
        for (int i = 0; i < 16; i++) {
            int idx = tid + i * 256;
            int oc = idx & 127, icl = (idx >> 7) & 7, tl = idx >> 10;
            int a = tl >> 1, c2 = tl & 1;
            int t = (1 - py + 2 * a) * 4 + (1 - px + 2 * c2);
            const float2* src =
                wt + ((size_t)(t * CIN + ch * 8 + icl)) * Cout + ocb + oc;
            unsigned dst = ws_base + (unsigned)(buf * D_WS2 + (tl * 8 + icl) * 132 + oc) * 8u;
            cp_async8(dst, src);
        }
        cp_commit();
    };

    stage(0, 0);
    for (int ch = 0; ch < NCH; ch++) {
        if (ch + 1 < NCH) { stage(ch + 1, (ch + 1) & 1); cp_wait<1>(); }
        else cp_wait<0>();
        __syncthreads();

        const float2* ws = ws0 + (ch & 1) * D_WS2;
        const float* ins = ins0 + (ch & 1) * IBUF;
#pragma unroll
        for (int tl = 0; tl < 4; tl++) {
            const int a = tl >> 1, c = tl & 1;
            unsigned ahi[4][4];
#pragma unroll
            for (int mt = 0; mt < 4; mt++) {
                const float2* ap = &ws[(tl * 8 + lr) * 132 + wm * 64 + mt * 16 + lq];
                ahi[mt][0] = __float_as_uint(ap[0].x);
                ahi[mt][1] = __float_as_uint(ap[8].x);
                ahi[mt][2] = __float_as_uint(ap[4 * 132].x);
                ahi[mt][3] = __float_as_uint(ap[4 * 132 + 8].x);
            }
#pragma unroll
            for (int nt = 0; nt < NT; nt++) {
                const int x = xb + nt * 8 + lq;
                const float* bp = &ins[(lr * 3 + (yl + 1 - a)) * ISTR + x + 1 - c];
                unsigned bh0 = tf32cvt(bp[0]), bh1 = tf32cvt(bp[4 * 3 * ISTR]);
#pragma unroll
                for (int mt = 0; mt < 4; mt++)
                    mma8(acc[mt][nt], ahi[mt], bh0, bh1);
            }
        }
        __syncthreads();
    }

    const int HOUT = 2 * HIN;
    const int oy = 2 * (y0 + yl) + py;
#pragma unroll
    for (int mt = 0; mt < 4; mt++) {
        const int oc = ocb + wm * 64 + mt * 16 + lq;
        const float b0v = bias[oc], b1v = bias[oc + 8];
#pragma unroll
        for (int nt = 0; nt < NT; nt++) {
            const int x = xb + nt * 8 + 2 * lr;
            const int ox = 2 * x + px;
            float* o0 = out + (((size_t)b * Cout + oc) * HOUT + oy) * HOUT + ox;
            float* o1 = o0 + (size_t)8 * HOUT * HOUT;
            o0[0] = fmaxf(acc[mt][nt][0] + b0v, 0.f);
            o0[2] = fmaxf(acc[mt][nt][1] + b0v, 0.f);
            o1[0] = fmaxf(acc[mt][nt][2] + b1v, 0.f);
            o1[2] = fmaxf(acc[mt][nt][3] + b1v, 0.f);
        }
    }
}
#define DCONV_SMEM(HIN) ((4 * D_WS2 + 2 * 8 * 3 * ((HIN) + 4)) * 4)

// ============================================================================
// Scalar kernels: conv1, dconv3out, vqk.  (unchanged)
// ============================================================================
template <int CIN, bool RELU>
__global__ __launch_bounds__(256, 2)
void conv4s2(const float* __restrict__ in, const float* __restrict__ wt,
             const float* __restrict__ bias, float* __restrict__ out,
             int Cout, int Hin, int Win, int Hout, int Wout, int tilesX) {
    __shared__ float ish[34 * 36];
    __shared__ float wsh[64 * 16];

    const int tile = blockIdx.x;
    const int tx0 = (tile % tilesX) * 16;
    const int ty0 = (tile / tilesX) * 16;
    const int ocb = blockIdx.y * 64;
    const int b   = blockIdx.z;

    const int tid = threadIdx.x;
    const int og  = tid >> 5;
    const int sp  = tid & 31;
    const int r   = sp >> 1;
    const int cb  = (sp & 1) * 8;

    float acc[8][8];
#pragma unroll
    for (int o = 0; o < 8; o++) {
        float bv = bias[ocb + og * 8 + o];
#pragma unroll
        for (int j = 0; j < 8; j++) acc[o][j] = bv;
    }

    const int iy0 = ty0 * 2 - 1, ix0 = tx0 * 2 - 1;
    const float* inB = in + ((size_t)b * CIN) * Hin * Win;

    for (int ic = 0; ic < CIN; ic++) {
        const float* inC = inB + (size_t)ic * Hin * Win;
        for (int idx = tid; idx < 34 * 34; idx += 256) {
            int py = idx / 34, px = idx - py * 34;
            int iy = iy0 + py, ix = ix0 + px;
            float v = 0.f;
            if ((unsigned)iy < (unsigned)Hin && (unsigned)ix < (unsigned)Win)
                v = inC[iy * Win + ix];
            ish[py * 36 + px] = v;
        }
        const float* wC = wt + (ic * Cout + ocb) * 16;
        for (int idx = tid; idx < 1024; idx += 256) wsh[idx] = wC[idx];
        __syncthreads();

#pragma unroll
        for (int ky = 0; ky < 4; ky++) {
            const float* rp = &ish[(2 * r + ky) * 36 + 2 * cb];
            float4 v0 = *(const float4*)(rp);
            float4 v1 = *(const float4*)(rp + 4);
            float4 v2 = *(const float4*)(rp + 8);
            float4 v3 = *(const float4*)(rp + 12);
            float4 v4 = *(const float4*)(rp + 16);
            float riv[20] = {v0.x, v0.y, v0.z, v0.w, v1.x, v1.y, v1.z, v1.w,
                             v2.x, v2.y, v2.z, v2.w, v3.x, v3.y, v3.z, v3.w,
                             v4.x, v4.y, v4.z, v4.w};
#pragma unroll
            for (int kx = 0; kx < 4; kx++) {
                const int t = ky * 4 + kx;
                float wv[8];
#pragma unroll
                for (int o = 0; o < 8; o++) wv[o] = wsh[(og * 8 + o) * 16 + t];
#pragma unroll
                for (int o = 0; o < 8; o++)
#pragma unroll
                    for (int j = 0; j < 8; j++)
                        acc[o][j] = fmaf(wv[o], riv[kx + 2 * j], acc[o][j]);
            }
        }
        __syncthreads();
    }

    const int oy = ty0 + r;
    const int oxb = tx0 + cb;
#pragma unroll
    for (int o = 0; o < 8; o++) {
        float* op = out + (((size_t)b * Cout + ocb + og * 8 + o) * Hout + oy) * Wout + oxb;
        float tmp[8];
#pragma unroll
        for (int j = 0; j < 8; j++)
            tmp[j] = RELU ? fmaxf(acc[o][j], 0.f) : acc[o][j];
        *(float4*)op       = make_float4(tmp[0], tmp[1], tmp[2], tmp[3]);
        *(float4*)(op + 4) = make_float4(tmp[4], tmp[5], tmp[6], tmp[7]);
    }
}

__global__ __launch_bounds__(128, 4)
void dconv3out(const float* __restrict__ in, const float* __restrict__ wt,
               const float* __restrict__ bias, float* __restrict__ out,
               int tilesX) {
    const int Cin = 128, Hin = 128, Win = 128, Hout = 256, Wout = 256;
    __shared__ float ish[4][18 * 19];
    __shared__ float wsh[4][3 * 16];

    const int tile = blockIdx.x;
    const int ox0 = (tile % tilesX) * 32;
    const int oy0 = (tile / tilesX) * 32;
    const int b   = blockIdx.y;

    const int tid = threadIdx.x;
    const int q   = tid >> 5;
    const int py  = q >> 1, px = q & 1;
    const int sp  = tid & 31;
    const int ry  = sp >> 1;
    const int ch  = (sp & 1) * 8;

    float acc[3][8];
#pragma unroll
    for (int o = 0; o < 3; o++) {
        float bv = bias[o];
#pragma unroll
        for (int j = 0; j < 8; j++) acc[o][j] = bv;
    }

    const int iy0 = oy0 >> 1, ix0 = ox0 >> 1;
    const int kp = 1 - py, kq = 1 - px;

    for (int ic0 = 0; ic0 < Cin; ic0 += 4) {
        for (int idx = tid; idx < 4 * 324; idx += 128) {
            int icc = idx / 324, p = idx - icc * 324;
            int piy = p / 18, pix = p - piy * 18;
            int iy = iy0 - 1 + piy, ix = ix0 - 1 + pix;
            float v = 0.f;
            if ((unsigned)iy < (unsigned)Hin && (unsigned)ix < (unsigned)Win)
                v = in[(((size_t)b * Cin + ic0 + icc) * Hin + iy) * Win + ix];
            ish[icc][piy * 19 + pix] = v;
        }
        for (int idx = tid; idx < 4 * 48; idx += 128) {
            int icc = idx / 48, rmd = idx - icc * 48;
            wsh[icc][rmd] = wt[(ic0 + icc) * 48 + rmd];
        }
        __syncthreads();

#pragma unroll
        for (int icc = 0; icc < 4; icc++) {
#pragma unroll
            for (int a = 0; a < 2; a++) {
                const int ky  = kp + 2 * a;
                const int liy = ry + 1 + py - a;
                float iv[10];
                const int base = liy * 19 + ch + px;
#pragma unroll
                for (int j = 0; j < 10; j++) iv[j] = ish[icc][base + j];
#pragma unroll
                for (int c = 0; c < 2; c++) {
                    const int kx  = kq + 2 * c;
                    const int t   = ky * 4 + kx;
                    const int off = 1 - c;
                    float wv[3];
#pragma unroll
                    for (int o = 0; o < 3; o++) wv[o] = wsh[icc][o * 16 + t];
#pragma unroll
                    for (int o = 0; o < 3; o++)
#pragma unroll
                        for (int j = 0; j < 8; j++)
                            acc[o][j] = fmaf(wv[o], iv[j + off], acc[o][j]);
                }
            }
        }
        __syncthreads();
    }

    const int oy = oy0 + 2 * ry + py;
#pragma unroll
    for (int o = 0; o < 3; o++) {
        float* op = out + (((size_t)b * 3 + o) * Hout + oy) * Wout + ox0 + px + 2 * ch;
#pragma unroll
        for (int j = 0; j < 8; j++) op[2 * j] = acc[o][j];
    }
}

__global__ __launch_bounds__(128, 8)
void vqk(const float* __restrict__ ze, const float* __restrict__ emb,
         float* __restrict__ zq, float* __restrict__ idxf) {
    __shared__ __align__(16) float esh[64 * 64];
    __shared__ float en[64];

    const int row = blockIdx.x * 128 + threadIdx.x;
    float f[64];
    const float4* fp = (const float4*)(ze + (size_t)row * 64);
#pragma unroll
    for (int i = 0; i < 16; i++) {
        float4 v = fp[i];
        f[4 * i] = v.x; f[4 * i + 1] = v.y; f[4 * i + 2] = v.z; f[4 * i + 3] = v.w;
    }
    float fn = 0.f;
#pragma unroll
    for (int d = 0; d < 64; d++) fn = fmaf(f[d], f[d], fn);

    float best = 3.4e38f;
    int bidx = 0;
    for (int cb = 0; cb < 512; cb += 64) {
        __syncthreads();
        const float4* src = (const float4*)(emb + (size_t)cb * 64);
        for (int i = threadIdx.x; i < 1024; i += 128)
            ((float4*)esh)[i] = src[i];
        __syncthreads();
        if (threadIdx.x < 64) {
            float s = 0.f;
            const float* e = esh + threadIdx.x * 64;
#pragma unroll
            for (int d = 0; d < 64; d++) s = fmaf(e[d], e[d], s);
            en[threadIdx.x] = s;
        }
        __syncthreads();
        for (int c = 0; c < 64; c++) {
            const float4* ev = (const float4*)(esh + c * 64);
            float dot = 0.f;
#pragma unroll
            for (int i = 0; i < 16; i++) {
                float4 e = ev[i];
                dot = fmaf(f[4 * i], e.x, dot);
                dot = fmaf(f[4 * i + 1], e.y, dot);
                dot = fmaf(f[4 * i + 2], e.z, dot);
                dot = fmaf(f[4 * i + 3], e.w, dot);
            }
            float sc = fn - 2.f * dot + en[c];
            if (sc < best) { best = sc; bidx = cb + c; }
        }
    }

    idxf[row] = (float)bidx;
    const float4* ep = (const float4*)(emb + (size_t)bidx * 64);
    float4* qp = (float4*)(zq + (size_t)row * 64);
#pragma unroll
    for (int i = 0; i < 16; i++) qp[i] = ep[i];
}

// ---------------------------------------------------------------------------
extern "C" void kernel_launch(void* const* d_in, const int* in_sizes, int n_in,
                              void* d_out, int out_size) {
    (void)in_sizes; (void)n_in;
    const float* x   = (const float*)d_in[0];
    const float* w1  = (const float*)d_in[1];
    const float* b1  = (const float*)d_in[2];
    const float* w2  = (const float*)d_in[3];
    const float* b2  = (const float*)d_in[4];
    const float* w3  = (const float*)d_in[5];
    const float* b3  = (const float*)d_in[6];
    const float* d1w = (const float*)d_in[7];
    const float* d1b = (const float*)d_in[8];
    const float* d2w = (const float*)d_in[9];
    const float* d2b = (const float*)d_in[10];
    const float* d3w = (const float*)d_in[11];
    const float* d3b = (const float*)d_in[12];
    const float* emb = (const float*)d_in[13];

    float *h1, *h2, *g1, *g2, *ze, *zq, *idxf, *wt1;
    float2 *w2s, *w3s, *d2s, *d1s;
    cudaGetSymbolAddress((void**)&h1, g_h1);
    cudaGetSymbolAddress((void**)&h2, g_h2);
    cudaGetSymbolAddress((void**)&g1, g_g1);
    cudaGetSymbolAddress((void**)&g2, g_g2);
    cudaGetSymbolAddress((void**)&ze, g_ze);
    cudaGetSymbolAddress((void**)&zq, g_zq);
    cudaGetSymbolAddress((void**)&idxf, g_if);
    cudaGetSymbolAddress((void**)&wt1, g_wt1);
    cudaGetSymbolAddress((void**)&w2s, g_w2s);
    cudaGetSymbolAddress((void**)&w3s, g_w3s);
    cudaGetSymbolAddress((void**)&d2s, g_d2s);
    cudaGetSymbolAddress((void**)&d1s, g_d1s);

    float* outF = (float*)d_out;
    const int NX = NBATCH * 3 * 256 * 256;
    const int NZ = NBATCH * 64 * 32 * 32;
    const int NI = 16384;
    if (out_size >= NX + 2 * NZ + NI) {
        ze   = outF + NX;
        zq   = outF + NX + NZ;
        idxf = outF + NX + 2 * NZ;
    }

    static bool attr_done = false;
    if (!attr_done) {
        cudaFuncSetAttribute(conv2_mma, cudaFuncAttributeMaxDynamicSharedMemorySize,
                             C2_SMEM);
        cudaFuncSetAttribute(conv3_mma, cudaFuncAttributeMaxDynamicSharedMemorySize,
                             C3_SMEM);
        cudaFuncSetAttribute(dconv_mma<64, 32>, cudaFuncAttributeMaxDynamicSharedMemorySize,
                             DCONV_SMEM(32));
        cudaFuncSetAttribute(dconv_mma<256, 64>, cudaFuncAttributeMaxDynamicSharedMemorySize,
                             DCONV_SMEM(64));
        attr_done = true;
    }

    wsplit2t<<<2048, 256>>>(w2, w2s);
    wtrans<<<(128 * 3 * 16 + 255) / 256, 256>>>(w1, wt1, 128, 3);
    conv4s2<3, true><<<dim3(64, 2, NBATCH), 256>>>(x, wt1, b1, h1, 128, 256, 256, 128, 128, 8);
    conv2_mma<<<dim3(32, 2, NBATCH), 256, C2_SMEM>>>(h1, w2s, b2, h2);
    wsplit3<<<1024, 256>>>(w3, w3s);
    conv3_mma<<<dim3(4, 1, NBATCH * 4), 256, C3_SMEM>>>(h2, w3s, g2);
    addparts<<<NZ / 256, 256>>>(g2, b3, ze);
    vqk<<<128, 128>>>(ze, emb, zq, idxf);
    wsplitD1<<<1024, 256>>>(d1w, d1s);
    dconv_mma<64, 32><<<dim3(16, 4, NBATCH * 2), 256, DCONV_SMEM(32)>>>(zq, d1s, d1b, g1, 256, 2);
    wsplitD2<<<2048, 256>>>(d2w, d2s);
    dconv_mma<256, 64><<<dim3(32, 4, NBATCH), 256, DCONV_SMEM(64)>>>(g1, d2s, d2b, g2, 128, 1);
    dconv3out<<<dim3(64, NBATCH), 128>>>(g2, d3w, d3b, outF, 8);
}